// round 2
// baseline (speedup 1.0000x reference)
#include <cuda_runtime.h>
#include <math.h>

#define BATCH 8
#define CH 2
#define TLEN 88200
#define BCT (BATCH*CH*TLEN)
#define TC 1378
#define KIR 512

// ---------------- scratch (device globals: allocation-free) ----------------
__device__ float g_mh[BCT];
__device__ float g_bands[3*BCT];          // band 0=high, 1=mid, 2=low
__device__ float g_rms[24*TC];
__device__ float g_env[24*TC];
__device__ float g_comb[BCT];
__device__ float g_act0[BATCH*64*TLEN];
__device__ float g_act1[BATCH*64*TLEN];

__device__ __forceinline__ float geluf(float x){
    return 0.5f*x*(1.0f + erff(x*0.70710678118654752f));
}

// f32x2 packed helpers (ptxas never emits FFMA2 from C++ — PTX only)
__device__ __forceinline__ void fma2(unsigned long long& d, unsigned long long a, unsigned long long b){
    asm("fma.rn.f32x2 %0, %1, %2, %0;" : "+l"(d) : "l"(a), "l"(b));
}
__device__ __forceinline__ unsigned long long dup2(float v){
    unsigned long long r; asm("mov.b64 %0, {%1, %2};" : "=l"(r) : "f"(v), "f"(v)); return r;
}
__device__ __forceinline__ void unpk(unsigned long long v, float& lo, float& hi){
    asm("mov.b64 {%0, %1}, %2;" : "=f"(lo), "=f"(hi) : "l"(v));
}

// ---------------- FIR: two 512-tap filters sharing one input pass ----------
// y[t] = sum_k w[k] * x[t - 511 + k]   (w = time-reversed IR, causal, zero history)
__global__ void __launch_bounds__(256) fir_pair(
    const float* __restrict__ xext, int use_ext,
    const float* __restrict__ wA, const float* __restrict__ wB,
    int outA, int outB, float gain)
{
    __shared__ float s_x[1536];
    __shared__ float s_wA[512];
    __shared__ float s_wB[512];
    int row  = blockIdx.y;          // b*2 + c
    int tile0 = blockIdx.x * 1024;
    int tid = threadIdx.x;
    const float* xr = (use_ext ? xext : (const float*)g_mh) + row*TLEN;
    for (int i = tid; i < 1536; i += 256){
        int g = tile0 - (KIR-1) + i;
        float v = (g >= 0 && g < TLEN) ? xr[g] : 0.0f;
        s_x[i] = v * gain;
    }
    for (int i = tid; i < 512; i += 256){ s_wA[i] = wA[i]; s_wB[i] = wB[i]; }
    __syncthreads();

    int base = tid * 4;
    float a0=0,a1=0,a2=0,a3=0,b0=0,b1=0,b2=0,b3=0;
    float x0=s_x[base], x1=s_x[base+1], x2=s_x[base+2], x3=s_x[base+3];
    #pragma unroll 4
    for (int k = 0; k < KIR; k++){
        float wa = s_wA[k], wb = s_wB[k];
        a0 += wa*x0; a1 += wa*x1; a2 += wa*x2; a3 += wa*x3;
        b0 += wb*x0; b1 += wb*x1; b2 += wb*x2; b3 += wb*x3;
        x0 = x1; x1 = x2; x2 = x3; x3 = s_x[base + k + 4];
    }
    float* oA = (outA < 0 ? g_mh : g_bands + (size_t)outA*BCT) + row*TLEN;
    float* oB = (outB < 0 ? g_mh : g_bands + (size_t)outB*BCT) + row*TLEN;
    int o = tile0 + base;
    if (o+0 < TLEN){ oA[o+0]=a0; oB[o+0]=b0; }
    if (o+1 < TLEN){ oA[o+1]=a1; oB[o+1]=b1; }
    if (o+2 < TLEN){ oA[o+2]=a2; oB[o+2]=b2; }
    if (o+3 < TLEN){ oA[o+3]=a3; oB[o+3]=b3; }
}

// ---------------- RMS downsample (DS=64) --------------------------------
__global__ void rms_kernel(){
    int bi = blockIdx.y;                    // b*3 + band
    int tc = blockIdx.x*256 + threadIdx.x;
    if (tc >= TC) return;
    int b = bi / 3, band = bi % 3;
    const float* p0 = g_bands + (size_t)band*BCT + (b*2+0)*TLEN + tc*64;
    const float* p1 = p0 + TLEN;
    float s = 0.0f;
    #pragma unroll
    for (int d = 0; d < 64; d++){ float u = p0[d], v = p1[d]; s += u*u + v*v; }
    g_rms[bi*TC + tc] = sqrtf(s * (1.0f/128.0f) + 1e-7f);
}

// ---------------- envelope recursion (exact cummax-with-decay) -----------
// NOTE: replicates reference's rel index quirk: k depends on (b*3+band)>>3
__global__ void env_kernel(const float* __restrict__ rel){
    int i = threadIdx.x;
    if (i >= 24) return;
    float k = 1.0f - rel[i >> 3];
    const float* x = g_rms + i*TC;
    float* e = g_env + i*TC;
    float acc = 0.0f;
    #pragma unroll 8
    for (int t = 0; t < TC; t++){
        acc = fmaxf(x[t], k*acc);
        e[t] = acc;
    }
}

// ---------------- gain + band combine ------------------------------------
__global__ void gain_kernel(const float* __restrict__ params, const float* __restrict__ kneep){
    int b = blockIdx.y;
    int t = blockIdx.x*256 + threadIdx.x;
    if (t >= TLEN) return;
    float kdb = kneep[0];
    float pos = (float)t * (1377.0f/88199.0f);
    int i0 = (int)floorf(pos);
    i0 = min(max(i0, 0), TC-2);
    float frac = pos - (float)i0;
    float c0 = 0.0f, c1 = 0.0f;
    #pragma unroll
    for (int band = 0; band < 3; band++){
        const float* er = g_env + (b*3 + band)*TC;
        float e = er[i0]*(1.0f - frac) + er[i0+1]*frac;
        float edb = 20.0f * log10f(e + 1e-7f);
        float ta = params[b*7 + (3 - band)];
        float tb = params[b*7 + (6 - band)];
        float slA = (band == 0) ? 1.0f : (1.0f - 1.0f/66.7f);
        const float slB = 1.0f - 1.0f/4.17f;
        float hk = 0.5f * kdb;
        // downward knee
        float d1 = edb - ta, k1;
        if (fabsf(d1) <= hk)      k1 = slA * (d1 + hk)*(d1 + hk) / (2.0f*kdb);
        else if (d1 > hk)         k1 = slA * d1;
        else                      k1 = 0.0f;
        // upward knee
        float d2 = tb - edb, k2;
        if (fabsf(d2) <= hk)      k2 = slB * (d2 + hk)*(d2 + hk) / (2.0f*kdb);
        else if (d2 > hk)         k2 = slB * d2;
        else                      k2 = 0.0f;
        float gdb = -k1 + k2 + ((band == 1) ? 5.7f : 10.3f);
        gdb = fminf(fmaxf(gdb, -80.0f), 40.0f);
        float tg = exp2f(gdb * 0.16609640474436813f);   // 10^(x/20)
        const float* bb = g_bands + (size_t)band*BCT + (b*2)*TLEN + t;
        c0 += bb[0]    * tg;
        c1 += bb[TLEN] * tg;
    }
    g_comb[(b*2)*TLEN + t]   = c0;
    g_comb[(b*2+1)*TLEN + t] = c1;
}

// ---------------- TCN layer 0: 2 -> 64, dil 1, gelu ----------------------
__global__ void __launch_bounds__(256) conv_in(const float* __restrict__ w, const float* __restrict__ bias){
    __shared__ float s_x[2][258];
    __shared__ float s_w[384];
    __shared__ float s_b[64];
    int bb = blockIdx.y;
    int tile0 = blockIdx.x * 256;
    int tid = threadIdx.x;
    for (int i = tid; i < 516; i += 256){
        int c = i / 258, ii = i % 258;
        int g = tile0 - 1 + ii;
        s_x[c][ii] = (g >= 0 && g < TLEN) ? g_comb[(bb*2 + c)*TLEN + g] : 0.0f;
    }
    for (int i = tid; i < 384; i += 256) s_w[i] = w[i];   // FIXED: full 384 loaded
    if (tid < 64)  s_b[tid] = bias[tid];
    __syncthreads();
    int t = tile0 + tid;
    if (t >= TLEN) return;
    float a0 = s_x[0][tid], a1 = s_x[0][tid+1], a2 = s_x[0][tid+2];
    float c0 = s_x[1][tid], c1 = s_x[1][tid+1], c2 = s_x[1][tid+2];
    #pragma unroll 4
    for (int co = 0; co < 64; co++){
        const float* wp = s_w + co*6;
        float acc = s_b[co] + wp[0]*a0 + wp[1]*a1 + wp[2]*a2
                            + wp[3]*c0 + wp[4]*c1 + wp[5]*c2;
        g_act0[((size_t)bb*64 + co)*TLEN + t] = geluf(acc);
    }
}

// ---------------- TCN 64->64 dilated conv, f32x2 packed implicit GEMM ----
template<int DIL>
__global__ void __launch_bounds__(256,1) conv64(int src, const float* __restrict__ w, const float* __restrict__ bias){
    constexpr int SSTR = 256 + 2*DIL;
    extern __shared__ float smem[];
    float* s_in = smem;                                                // 64*SSTR floats
    unsigned long long* s_w2 = (unsigned long long*)(smem + 64*SSTR);  // 12288 ull
    const float* in  = src ? g_act1 : g_act0;
    float*       out = src ? g_act0 : g_act1;
    int bb = blockIdx.y;
    int tile0 = blockIdx.x * 256;
    int tid = threadIdx.x;

    for (int i = tid; i < 12288; i += 256) s_w2[i] = dup2(w[i]);
    const float* inb = in + (size_t)bb*64*TLEN;
    for (int idx = tid; idx < 64*SSTR; idx += 256){
        int ci = idx / SSTR, ii = idx % SSTR;
        int g = tile0 - DIL + ii;
        s_in[idx] = (g >= 0 && g < TLEN) ? inb[(size_t)ci*TLEN + g] : 0.0f;
    }
    __syncthreads();

    int lane = tid & 31, warp = tid >> 5;      // warp owns co = warp*8 .. warp*8+7
    unsigned long long acc[8][4];
    #pragma unroll
    for (int cc = 0; cc < 8; cc++)
        #pragma unroll
        for (int p = 0; p < 4; p++) acc[cc][p] = 0ull;

    const unsigned long long* wbase = s_w2 + warp*8*192;
    #pragma unroll 2
    for (int ci = 0; ci < 64; ci++){
        const float* r = s_in + ci*SSTR + 2*lane;
        unsigned long long xin[3][4];
        #pragma unroll
        for (int j = 0; j < 3; j++)
            #pragma unroll
            for (int p = 0; p < 4; p++)
                xin[j][p] = *(const unsigned long long*)(r + 64*p + j*DIL);
        #pragma unroll
        for (int cc = 0; cc < 8; cc++){
            const unsigned long long* wp = wbase + cc*192 + ci*3;
            unsigned long long w0 = wp[0], w1 = wp[1], w2 = wp[2];
            #pragma unroll
            for (int p = 0; p < 4; p++){
                fma2(acc[cc][p], w0, xin[0][p]);
                fma2(acc[cc][p], w1, xin[1][p]);
                fma2(acc[cc][p], w2, xin[2][p]);
            }
        }
    }

    float* outb = out + (size_t)bb*64*TLEN;
    #pragma unroll
    for (int cc = 0; cc < 8; cc++){
        int co = warp*8 + cc;
        float bv = bias[co];
        #pragma unroll
        for (int p = 0; p < 4; p++){
            float lo, hi; unpk(acc[cc][p], lo, hi);
            int t = tile0 + 2*lane + 64*p;
            if (t < TLEN){
                float2 v; v.x = geluf(bv + lo); v.y = geluf(bv + hi);
                *(float2*)(outb + (size_t)co*TLEN + t) = v;
            }
        }
    }
}

// ---------------- TCN last layer 64->2 + skip + dry/wet mix ---------------
__global__ void __launch_bounds__(256) conv_out(
    const float* __restrict__ w, const float* __restrict__ bias,
    const float* __restrict__ audio, const float* __restrict__ params,
    float* __restrict__ outp)
{
    extern __shared__ float smem[];          // 64*258 floats
    __shared__ float s_w[384];
    __shared__ float s_b2[2];
    int bb = blockIdx.y;
    int tile0 = blockIdx.x * 256;
    int tid = threadIdx.x;
    const float* inb = g_act1 + (size_t)bb*64*TLEN;
    for (int idx = tid; idx < 64*258; idx += 256){
        int ci = idx / 258, ii = idx % 258;
        int g = tile0 - 1 + ii;
        smem[idx] = (g >= 0 && g < TLEN) ? inb[(size_t)ci*TLEN + g] : 0.0f;
    }
    for (int i = tid; i < 384; i += 256) s_w[i] = w[i];   // FIXED: full 384 loaded
    if (tid < 2)   s_b2[tid] = bias[tid];
    __syncthreads();
    int t = tile0 + tid;
    if (t >= TLEN) return;
    float acc0 = s_b2[0], acc1 = s_b2[1];
    #pragma unroll 4
    for (int ci = 0; ci < 64; ci++){
        float x0 = smem[ci*258 + tid], x1 = smem[ci*258 + tid + 1], x2 = smem[ci*258 + tid + 2];
        const float* w0p = s_w + ci*3;
        const float* w1p = s_w + 192 + ci*3;
        acc0 += w0p[0]*x0 + w0p[1]*x1 + w0p[2]*x2;
        acc1 += w1p[0]*x0 + w1p[1]*x1 + w1p[2]*x2;
    }
    float amount = params[bb*7];
    int i0 = (bb*2)*TLEN + t;
    int i1 = i0 + TLEN;
    outp[i0] = (1.0f - amount)*audio[i0] + amount*(g_comb[i0] + acc0);
    outp[i1] = (1.0f - amount)*audio[i1] + amount*(g_comb[i1] + acc1);
}

// ---------------- launch ---------------------------------------------------
extern "C" void kernel_launch(void* const* d_in, const int* in_sizes, int n_in,
                              void* d_out, int out_size)
{
    const float* audio = (const float*)d_in[0];
    const float* params = (const float*)d_in[1];
    const float* rel   = (const float*)d_in[2];
    const float* kneep = (const float*)d_in[3];
    const float* irLL  = (const float*)d_in[4];
    const float* irLH  = (const float*)d_in[5];
    const float* irHL  = (const float*)d_in[6];
    const float* irHH  = (const float*)d_in[7];
    const float* w0 = (const float*)d_in[8];  const float* b0 = (const float*)d_in[9];
    const float* w1 = (const float*)d_in[10]; const float* b1 = (const float*)d_in[11];
    const float* w2 = (const float*)d_in[12]; const float* b2 = (const float*)d_in[13];
    const float* w3 = (const float*)d_in[14]; const float* b3 = (const float*)d_in[15];
    const float* w4 = (const float*)d_in[16]; const float* b4 = (const float*)d_in[17];
    float* out = (float*)d_out;

    // idempotent, non-stream API: safe to call every time (incl. during capture)
    cudaFuncSetAttribute(conv64<2>, cudaFuncAttributeMaxDynamicSharedMemorySize, 64*260*4 + 12288*8);
    cudaFuncSetAttribute(conv64<4>, cudaFuncAttributeMaxDynamicSharedMemorySize, 64*264*4 + 12288*8);
    cudaFuncSetAttribute(conv64<8>, cudaFuncAttributeMaxDynamicSharedMemorySize, 64*272*4 + 12288*8);
    cudaFuncSetAttribute(conv_out,  cudaFuncAttributeMaxDynamicSharedMemorySize, 64*258*4);

    dim3 gfir((TLEN + 1023)/1024, BATCH*CH);
    // pass A: audio*IN_GAIN -> low (band 2), m_h
    fir_pair<<<gfir, 256>>>(audio, 1, irLL, irLH, 2, -1, 1.81970085860998f);
    // pass B: m_h -> mid (band 1), high (band 0)
    fir_pair<<<gfir, 256>>>(nullptr, 0, irHL, irHH, 1, 0, 1.0f);

    rms_kernel<<<dim3((TC + 255)/256, 24), 256>>>();
    env_kernel<<<1, 32>>>(rel);

    dim3 gT((TLEN + 255)/256, BATCH);
    gain_kernel<<<gT, 256>>>(params, kneep);

    conv_in<<<gT, 256>>>(w0, b0);
    conv64<2><<<gT, 256, 64*260*4 + 12288*8>>>(0, w1, b1);
    conv64<4><<<gT, 256, 64*264*4 + 12288*8>>>(1, w2, b2);
    conv64<8><<<gT, 256, 64*272*4 + 12288*8>>>(0, w3, b3);
    conv_out<<<gT, 256, 64*258*4>>>(w4, b4, audio, params, out);
}

// round 3
// speedup vs baseline: 1.2485x; 1.2485x over previous
#include <cuda_runtime.h>
#include <math.h>

#define BATCH 8
#define CH 2
#define TLEN 88200
#define BCT (BATCH*CH*TLEN)
#define TC 1378
#define KIR 512

// ---------------- scratch (device globals: allocation-free) ----------------
__device__ float g_mh[BCT];
__device__ float g_bands[3*BCT];          // band 0=high, 1=mid, 2=low
__device__ float g_rms[24*TC];
__device__ float g_env[24*TC];
__device__ float g_comb[BCT];
__device__ float g_act0[BATCH*64*TLEN];
__device__ float g_act1[BATCH*64*TLEN];

typedef unsigned long long ull;

__device__ __forceinline__ float geluf(float x){
    return 0.5f*x*(1.0f + erff(x*0.70710678118654752f));
}
__device__ __forceinline__ void fma2(ull& d, ull a, ull b){
    asm("fma.rn.f32x2 %0, %1, %2, %0;" : "+l"(d) : "l"(a), "l"(b));
}
__device__ __forceinline__ ull dup2(float v){
    ull r; asm("mov.b64 %0, {%1, %2};" : "=l"(r) : "f"(v), "f"(v)); return r;
}
__device__ __forceinline__ void unpk(ull v, float& lo, float& hi){
    asm("mov.b64 {%0, %1}, %2;" : "=f"(lo), "=f"(hi) : "l"(v));
}

// ---------------- FIR: two 512-tap filters, f32x2 with register rotation ---
// y[t] = sum_k w[k] * x[t - 511 + k]. 8 outputs (4 pairs) per thread.
// Odd taps use a 1-shifted smem copy so pair loads stay 8B-aligned.
__global__ void __launch_bounds__(256) fir_pair(
    const float* __restrict__ xext, int use_ext,
    const float* __restrict__ wA, const float* __restrict__ wB,
    int outA, int outB, float gain)
{
    __shared__ __align__(16) float s_x[2564];
    __shared__ __align__(16) float s_xs[2564];
    __shared__ ull s_wA2[512];
    __shared__ ull s_wB2[512];
    int row  = blockIdx.y;            // b*2 + c
    int tile0 = blockIdx.x * 2048;
    int tid = threadIdx.x;
    const float* xr = (use_ext ? xext : (const float*)g_mh) + row*TLEN;
    for (int i = tid; i < 2564; i += 256){
        int g = tile0 - (KIR-1) + i;
        s_x[i] = (g >= 0 && g < TLEN) ? xr[g] * gain : 0.0f;
    }
    for (int i = tid; i < 512; i += 256){ s_wA2[i] = dup2(wA[i]); s_wB2[i] = dup2(wB[i]); }
    __syncthreads();
    for (int i = tid; i < 2563; i += 256) s_xs[i] = s_x[i+1];
    if (tid == 0) s_xs[2563] = 0.0f;
    __syncthreads();

    int base = tid * 8;
    ull aA[4], aB[4];
    #pragma unroll
    for (int i = 0; i < 4; i++){ aA[i] = 0ull; aB[i] = 0ull; }
    ull E[4], O[4];
    #pragma unroll
    for (int i = 0; i < 4; i++){
        E[i] = *(const ull*)(s_x  + base + 2*i);
        O[i] = *(const ull*)(s_xs + base + 2*i);
    }
    #pragma unroll 4
    for (int k2 = 0; k2 < 256; k2++){
        int k = 2*k2;
        ull wa0 = s_wA2[k], wa1 = s_wA2[k+1];
        ull wb0 = s_wB2[k], wb1 = s_wB2[k+1];
        #pragma unroll
        for (int i = 0; i < 4; i++){
            fma2(aA[i], wa0, E[i]);
            fma2(aB[i], wb0, E[i]);
            fma2(aA[i], wa1, O[i]);
            fma2(aB[i], wb1, O[i]);
        }
        E[0]=E[1]; E[1]=E[2]; E[2]=E[3];
        O[0]=O[1]; O[1]=O[2]; O[2]=O[3];
        E[3] = *(const ull*)(s_x  + base + k + 8);
        O[3] = *(const ull*)(s_xs + base + k + 8);
    }

    float* oA = (outA < 0 ? g_mh : g_bands + (size_t)outA*BCT) + row*TLEN;
    float* oB = (outB < 0 ? g_mh : g_bands + (size_t)outB*BCT) + row*TLEN;
    #pragma unroll
    for (int i = 0; i < 4; i++){
        int o = tile0 + base + 2*i;
        if (o < TLEN){   // TLEN even: a pair never straddles the boundary
            float lo, hi;
            unpk(aA[i], lo, hi); *(float2*)(oA + o) = make_float2(lo, hi);
            unpk(aB[i], lo, hi); *(float2*)(oB + o) = make_float2(lo, hi);
        }
    }
}

// ---------------- RMS downsample (DS=64) --------------------------------
__global__ void rms_kernel(){
    int bi = blockIdx.y;                    // b*3 + band
    int tc = blockIdx.x*256 + threadIdx.x;
    if (tc >= TC) return;
    int b = bi / 3, band = bi % 3;
    const float* p0 = g_bands + (size_t)band*BCT + (b*2+0)*TLEN + tc*64;
    const float* p1 = p0 + TLEN;
    float s = 0.0f;
    #pragma unroll
    for (int d = 0; d < 64; d++){ float u = p0[d], v = p1[d]; s += u*u + v*v; }
    g_rms[bi*TC + tc] = sqrtf(s * (1.0f/128.0f) + 1e-7f);
}

// ---------------- envelope: parallel segmented scan (1 warp / sequence) ---
// y[t] = max(x[t], k*y[t-1]); segment transform f(e)=max(M,p*e) composes
// (M1,p1)o(M2,p2) = (max(M2,p2*M1), p1*p2). Replicates rel quirk (i>>3).
__global__ void env_kernel(const float* __restrict__ rel){
    int seq = blockIdx.x;                  // 24 sequences
    int lane = threadIdx.x;                // 32 lanes
    float k = 1.0f - rel[seq >> 3];
    const float* x = g_rms + seq*TC;
    float* e = g_env + seq*TC;
    const int CL = 44;                     // 32*44 >= 1378
    int start = lane*CL;
    int end = min(start + CL, TC);
    float M = 0.0f, p = 1.0f;
    for (int t = start; t < end; t++){ M = fmaxf(x[t], k*M); p *= k; }
    #pragma unroll
    for (int d = 1; d < 32; d <<= 1){
        float Mo = __shfl_up_sync(0xffffffffu, M, d);
        float po = __shfl_up_sync(0xffffffffu, p, d);
        if (lane >= d){ M = fmaxf(M, p*Mo); p *= po; }
    }
    float ein = __shfl_up_sync(0xffffffffu, M, 1);
    float y = (lane == 0) ? 0.0f : ein;
    for (int t = start; t < end; t++){ y = fmaxf(x[t], k*y); e[t] = y; }
}

// ---------------- gain + band combine ------------------------------------
__global__ void gain_kernel(const float* __restrict__ params, const float* __restrict__ kneep){
    int b = blockIdx.y;
    int t = blockIdx.x*256 + threadIdx.x;
    if (t >= TLEN) return;
    float kdb = kneep[0];
    float pos = (float)t * (1377.0f/88199.0f);
    int i0 = (int)floorf(pos);
    i0 = min(max(i0, 0), TC-2);
    float frac = pos - (float)i0;
    float c0 = 0.0f, c1 = 0.0f;
    #pragma unroll
    for (int band = 0; band < 3; band++){
        const float* er = g_env + (b*3 + band)*TC;
        float e = er[i0]*(1.0f - frac) + er[i0+1]*frac;
        float edb = 20.0f * log10f(e + 1e-7f);
        float ta = params[b*7 + (3 - band)];
        float tb = params[b*7 + (6 - band)];
        float slA = (band == 0) ? 1.0f : (1.0f - 1.0f/66.7f);
        const float slB = 1.0f - 1.0f/4.17f;
        float hk = 0.5f * kdb;
        float d1 = edb - ta, k1;
        if (fabsf(d1) <= hk)      k1 = slA * (d1 + hk)*(d1 + hk) / (2.0f*kdb);
        else if (d1 > hk)         k1 = slA * d1;
        else                      k1 = 0.0f;
        float d2 = tb - edb, k2;
        if (fabsf(d2) <= hk)      k2 = slB * (d2 + hk)*(d2 + hk) / (2.0f*kdb);
        else if (d2 > hk)         k2 = slB * d2;
        else                      k2 = 0.0f;
        float gdb = -k1 + k2 + ((band == 1) ? 5.7f : 10.3f);
        gdb = fminf(fmaxf(gdb, -80.0f), 40.0f);
        float tg = exp2f(gdb * 0.16609640474436813f);   // 10^(x/20)
        const float* bb = g_bands + (size_t)band*BCT + (b*2)*TLEN + t;
        c0 += bb[0]    * tg;
        c1 += bb[TLEN] * tg;
    }
    g_comb[(b*2)*TLEN + t]   = c0;
    g_comb[(b*2+1)*TLEN + t] = c1;
}

// ---------------- TCN layer 0: 2 -> 64, dil 1, gelu ----------------------
__global__ void __launch_bounds__(256) conv_in(const float* __restrict__ w, const float* __restrict__ bias){
    __shared__ float s_x[2][258];
    __shared__ float s_w[384];
    __shared__ float s_b[64];
    int bb = blockIdx.y;
    int tile0 = blockIdx.x * 256;
    int tid = threadIdx.x;
    for (int i = tid; i < 516; i += 256){
        int c = i / 258, ii = i % 258;
        int g = tile0 - 1 + ii;
        s_x[c][ii] = (g >= 0 && g < TLEN) ? g_comb[(bb*2 + c)*TLEN + g] : 0.0f;
    }
    for (int i = tid; i < 384; i += 256) s_w[i] = w[i];
    if (tid < 64)  s_b[tid] = bias[tid];
    __syncthreads();
    int t = tile0 + tid;
    if (t >= TLEN) return;
    float a0 = s_x[0][tid], a1 = s_x[0][tid+1], a2 = s_x[0][tid+2];
    float c0 = s_x[1][tid], c1 = s_x[1][tid+1], c2 = s_x[1][tid+2];
    #pragma unroll 4
    for (int co = 0; co < 64; co++){
        const float* wp = s_w + co*6;
        float acc = s_b[co] + wp[0]*a0 + wp[1]*a1 + wp[2]*a2
                            + wp[3]*c0 + wp[4]*c1 + wp[5]*c2;
        g_act0[((size_t)bb*64 + co)*TLEN + t] = geluf(acc);
    }
}

// ---------------- TCN 64->64 dilated conv, f32x2, 512 threads ------------
// warps 0..15: (warp&7) selects 8 output channels, (warp>>3) selects t-quarter pair
template<int DIL>
__global__ void __launch_bounds__(512,1) conv64(int src, const float* __restrict__ w, const float* __restrict__ bias){
    constexpr int SSTR = 256 + 2*DIL;
    extern __shared__ float smem[];
    float* s_in = smem;                                   // 64*SSTR floats
    ull* s_w2 = (ull*)(smem + 64*SSTR);                   // 12288 ull
    const float* in  = src ? g_act1 : g_act0;
    float*       out = src ? g_act0 : g_act1;
    int bb = blockIdx.y;
    int tile0 = blockIdx.x * 256;
    int tid = threadIdx.x;

    for (int i = tid; i < 12288; i += 512) s_w2[i] = dup2(w[i]);
    const float* inb = in + (size_t)bb*64*TLEN;
    for (int idx = tid; idx < 64*SSTR; idx += 512){
        int ci = idx / SSTR, ii = idx % SSTR;
        int g = tile0 - DIL + ii;
        s_in[idx] = (g >= 0 && g < TLEN) ? inb[(size_t)ci*TLEN + g] : 0.0f;
    }
    __syncthreads();

    int lane = tid & 31, warp = tid >> 5;
    int wco = warp & 7, half = warp >> 3;     // half: 0 -> p 0,1 ; 1 -> p 2,3
    ull acc[8][2];
    #pragma unroll
    for (int cc = 0; cc < 8; cc++){ acc[cc][0] = 0ull; acc[cc][1] = 0ull; }

    const ull* wbase = s_w2 + wco*8*192;
    #pragma unroll 2
    for (int ci = 0; ci < 64; ci++){
        const float* r = s_in + ci*SSTR + 2*lane + 128*half;
        ull xin[3][2];
        #pragma unroll
        for (int j = 0; j < 3; j++){
            xin[j][0] = *(const ull*)(r + j*DIL);
            xin[j][1] = *(const ull*)(r + 64 + j*DIL);
        }
        #pragma unroll
        for (int cc = 0; cc < 8; cc++){
            const ull* wp = wbase + cc*192 + ci*3;
            ull w0 = wp[0], w1 = wp[1], w2 = wp[2];
            #pragma unroll
            for (int p = 0; p < 2; p++){
                fma2(acc[cc][p], w0, xin[0][p]);
                fma2(acc[cc][p], w1, xin[1][p]);
                fma2(acc[cc][p], w2, xin[2][p]);
            }
        }
    }

    float* outb = out + (size_t)bb*64*TLEN;
    #pragma unroll
    for (int cc = 0; cc < 8; cc++){
        int co = wco*8 + cc;
        float bv = bias[co];
        #pragma unroll
        for (int p = 0; p < 2; p++){
            float lo, hi; unpk(acc[cc][p], lo, hi);
            int t = tile0 + 2*lane + 128*half + 64*p;
            if (t < TLEN){
                float2 v; v.x = geluf(bv + lo); v.y = geluf(bv + hi);
                *(float2*)(outb + (size_t)co*TLEN + t) = v;
            }
        }
    }
}

// ---------------- TCN last layer 64->2 + skip + dry/wet mix ---------------
__global__ void __launch_bounds__(256) conv_out(
    const float* __restrict__ w, const float* __restrict__ bias,
    const float* __restrict__ audio, const float* __restrict__ params,
    float* __restrict__ outp)
{
    extern __shared__ float smem[];          // 64*258 floats
    __shared__ float s_w[384];
    __shared__ float s_b2[2];
    int bb = blockIdx.y;
    int tile0 = blockIdx.x * 256;
    int tid = threadIdx.x;
    const float* inb = g_act1 + (size_t)bb*64*TLEN;
    for (int idx = tid; idx < 64*258; idx += 256){
        int ci = idx / 258, ii = idx % 258;
        int g = tile0 - 1 + ii;
        smem[idx] = (g >= 0 && g < TLEN) ? inb[(size_t)ci*TLEN + g] : 0.0f;
    }
    for (int i = tid; i < 384; i += 256) s_w[i] = w[i];
    if (tid < 2)   s_b2[tid] = bias[tid];
    __syncthreads();
    int t = tile0 + tid;
    if (t >= TLEN) return;
    float acc0 = s_b2[0], acc1 = s_b2[1];
    #pragma unroll 4
    for (int ci = 0; ci < 64; ci++){
        float x0 = smem[ci*258 + tid], x1 = smem[ci*258 + tid + 1], x2 = smem[ci*258 + tid + 2];
        const float* w0p = s_w + ci*3;
        const float* w1p = s_w + 192 + ci*3;
        acc0 += w0p[0]*x0 + w0p[1]*x1 + w0p[2]*x2;
        acc1 += w1p[0]*x0 + w1p[1]*x1 + w1p[2]*x2;
    }
    float amount = params[bb*7];
    int i0 = (bb*2)*TLEN + t;
    int i1 = i0 + TLEN;
    outp[i0] = (1.0f - amount)*audio[i0] + amount*(g_comb[i0] + acc0);
    outp[i1] = (1.0f - amount)*audio[i1] + amount*(g_comb[i1] + acc1);
}

// ---------------- launch ---------------------------------------------------
extern "C" void kernel_launch(void* const* d_in, const int* in_sizes, int n_in,
                              void* d_out, int out_size)
{
    const float* audio = (const float*)d_in[0];
    const float* params = (const float*)d_in[1];
    const float* rel   = (const float*)d_in[2];
    const float* kneep = (const float*)d_in[3];
    const float* irLL  = (const float*)d_in[4];
    const float* irLH  = (const float*)d_in[5];
    const float* irHL  = (const float*)d_in[6];
    const float* irHH  = (const float*)d_in[7];
    const float* w0 = (const float*)d_in[8];  const float* b0 = (const float*)d_in[9];
    const float* w1 = (const float*)d_in[10]; const float* b1 = (const float*)d_in[11];
    const float* w2 = (const float*)d_in[12]; const float* b2 = (const float*)d_in[13];
    const float* w3 = (const float*)d_in[14]; const float* b3 = (const float*)d_in[15];
    const float* w4 = (const float*)d_in[16]; const float* b4 = (const float*)d_in[17];
    float* out = (float*)d_out;

    cudaFuncSetAttribute(conv64<2>, cudaFuncAttributeMaxDynamicSharedMemorySize, 64*260*4 + 12288*8);
    cudaFuncSetAttribute(conv64<4>, cudaFuncAttributeMaxDynamicSharedMemorySize, 64*264*4 + 12288*8);
    cudaFuncSetAttribute(conv64<8>, cudaFuncAttributeMaxDynamicSharedMemorySize, 64*272*4 + 12288*8);
    cudaFuncSetAttribute(conv_out,  cudaFuncAttributeMaxDynamicSharedMemorySize, 64*258*4);

    dim3 gfir((TLEN + 2047)/2048, BATCH*CH);
    // pass A: audio*IN_GAIN -> low (band 2), m_h
    fir_pair<<<gfir, 256>>>(audio, 1, irLL, irLH, 2, -1, 1.81970085860998f);
    // pass B: m_h -> mid (band 1), high (band 0)
    fir_pair<<<gfir, 256>>>(nullptr, 0, irHL, irHH, 1, 0, 1.0f);

    rms_kernel<<<dim3((TC + 255)/256, 24), 256>>>();
    env_kernel<<<24, 32>>>(rel);

    dim3 gT((TLEN + 255)/256, BATCH);
    gain_kernel<<<gT, 256>>>(params, kneep);

    conv_in<<<gT, 256>>>(w0, b0);
    conv64<2><<<gT, 512, 64*260*4 + 12288*8>>>(0, w1, b1);
    conv64<4><<<gT, 512, 64*264*4 + 12288*8>>>(1, w2, b2);
    conv64<8><<<gT, 512, 64*272*4 + 12288*8>>>(0, w3, b3);
    conv_out<<<gT, 256, 64*258*4>>>(w4, b4, audio, params, out);
}

// round 9
// speedup vs baseline: 1.9527x; 1.5641x over previous
#include <cuda_runtime.h>
#include <cuda_bf16.h>
#include <math.h>

#define BATCH 8
#define CH 2
#define TLEN 88200
#define BCT (BATCH*CH*TLEN)
#define TC 1378
#define KIR 512

typedef unsigned long long ull;
typedef unsigned int uint;

#if defined(__CUDA_ARCH_FEAT_SM103_ALL) || defined(__CUDA_ARCH_FEAT_SM100_ALL)
#define HAS_TCGEN05 1
#else
#define HAS_TCGEN05 0
#endif

// ---------------- scratch (device globals: allocation-free) ----------------
__device__ float g_mh[BCT];
__device__ float g_bands[3*BCT];          // band 0=high, 1=mid, 2=low
__device__ float g_rms[24*TC];
__device__ float g_env[24*TC];
__device__ float g_comb[BCT];
__device__ __align__(16) unsigned short g_b0[BATCH*64*TLEN];   // bf16 activations
__device__ __align__(16) unsigned short g_b1[BATCH*64*TLEN];
__device__ __align__(16) unsigned short g_wA[3*24576];  // swizzled A-tile images

__device__ __forceinline__ float geluf(float x){
    return 0.5f*x*(1.0f + erff(x*0.70710678118654752f));
}
__device__ __forceinline__ void fma2(ull& d, ull a, ull b){
    asm("fma.rn.f32x2 %0, %1, %2, %0;" : "+l"(d) : "l"(a), "l"(b));
}
__device__ __forceinline__ ull dup2(float v){
    ull r; asm("mov.b64 %0, {%1, %2};" : "=l"(r) : "f"(v), "f"(v)); return r;
}
__device__ __forceinline__ void unpk(ull v, float& lo, float& hi){
    asm("mov.b64 {%0, %1}, %2;" : "=f"(lo), "=f"(hi) : "l"(v));
}
__device__ __forceinline__ float bf2f(unsigned short u){
    return __bfloat162float(*(__nv_bfloat16*)&u);
}
__device__ __forceinline__ unsigned short f2bf(float v){
    __nv_bfloat16 b = __float2bfloat16(v);
    return *(unsigned short*)&b;
}

// ---------------- tcgen05 helpers (only referenced under HAS_TCGEN05) ------
__device__ __forceinline__ uint smem_u32(const void* p){
    uint a; asm("{ .reg .u64 t; cvta.to.shared.u64 t, %1; cvt.u32.u64 %0, t; }" : "=r"(a) : "l"(p)); return a;
}
__device__ __forceinline__ uint elect1(){
    uint p;
    asm volatile("{\n\t.reg .pred P;\n\telect.sync _|P, 0xFFFFFFFF;\n\tselp.b32 %0,1,0,P;\n\t}" : "=r"(p));
    return p;
}
__device__ __forceinline__ void mbar_wait(uint mbar, uint parity){
    asm volatile("{\n\t.reg .pred P;\n\tLW%=:\n\t"
      "mbarrier.try_wait.parity.acquire.cta.shared::cta.b64 P, [%0], %1, 0x989680;\n\t"
      "@P bra LD%=;\n\tbra LW%=;\n\tLD%=:\n\t}" :: "r"(mbar), "r"(parity) : "memory");
}
#if HAS_TCGEN05
__device__ __forceinline__ void mma_f16_ss(uint d, ull a, ull b, uint idesc, uint en){
    asm volatile("{\n\t.reg .pred p;\n\tsetp.ne.u32 p, %5, 0;\n\t"
        "tcgen05.mma.cta_group::1.kind::f16 [%0], %1, %2, %3, {%4,%4,%4,%4}, p;\n\t}"
        :: "r"(d), "l"(a), "l"(b), "r"(idesc), "r"(0u), "r"(en) : "memory");
}
#define TC_LD_X32(r, addr) \
    asm volatile("tcgen05.ld.sync.aligned.32x32b.x32.b32 " \
        "{%0,%1,%2,%3,%4,%5,%6,%7,%8,%9,%10,%11,%12,%13,%14,%15," \
        "%16,%17,%18,%19,%20,%21,%22,%23,%24,%25,%26,%27,%28,%29,%30,%31}, [%32];" \
        : "=r"((r)[0]),"=r"((r)[1]),"=r"((r)[2]),"=r"((r)[3]),"=r"((r)[4]),"=r"((r)[5]),"=r"((r)[6]),"=r"((r)[7]), \
          "=r"((r)[8]),"=r"((r)[9]),"=r"((r)[10]),"=r"((r)[11]),"=r"((r)[12]),"=r"((r)[13]),"=r"((r)[14]),"=r"((r)[15]), \
          "=r"((r)[16]),"=r"((r)[17]),"=r"((r)[18]),"=r"((r)[19]),"=r"((r)[20]),"=r"((r)[21]),"=r"((r)[22]),"=r"((r)[23]), \
          "=r"((r)[24]),"=r"((r)[25]),"=r"((r)[26]),"=r"((r)[27]),"=r"((r)[28]),"=r"((r)[29]),"=r"((r)[30]),"=r"((r)[31]) \
        : "r"(addr))
#endif

// SMEM descriptor bases (Blackwell: version=1, SW128 layout=2)
__device__ __forceinline__ ull desc_kmajor(uint addr){   // LBO=1, SBO=64 (K-major)
    return (2ull<<61) | (1ull<<46) | (64ull<<32) | (1ull<<16) | ((ull)(addr>>4) & 0x3FFF);
}
__device__ __forceinline__ ull desc_mnmajor(uint addr){  // LBO=64, SBO=8 (MN-major)
    return (2ull<<61) | (1ull<<46) | (8ull<<32) | (64ull<<16) | ((ull)(addr>>4) & 0x3FFF);
}
// idesc: F32 accum(1<<4), BF16 a(1<<7), BF16 b(1<<10), TransB(1<<16), N=64(8<<17), M=128(8<<24)
#define MMA_IDESC 0x08110490u

// ---------------- FIR: two 512-tap filters, f32x2 with register rotation ---
__global__ void __launch_bounds__(256) fir_pair(
    const float* __restrict__ xext, int use_ext,
    const float* __restrict__ wA, const float* __restrict__ wB,
    int outA, int outB, float gain)
{
    __shared__ __align__(16) float s_x[2564];
    __shared__ __align__(16) float s_xs[2564];
    __shared__ ull s_wA2[512];
    __shared__ ull s_wB2[512];
    int row  = blockIdx.y;
    int tile0 = blockIdx.x * 2048;
    int tid = threadIdx.x;
    const float* xr = (use_ext ? xext : (const float*)g_mh) + row*TLEN;
    for (int i = tid; i < 2564; i += 256){
        int g = tile0 - (KIR-1) + i;
        s_x[i] = (g >= 0 && g < TLEN) ? xr[g] * gain : 0.0f;
    }
    for (int i = tid; i < 512; i += 256){ s_wA2[i] = dup2(wA[i]); s_wB2[i] = dup2(wB[i]); }
    __syncthreads();
    for (int i = tid; i < 2563; i += 256) s_xs[i] = s_x[i+1];
    if (tid == 0) s_xs[2563] = 0.0f;
    __syncthreads();

    int base = tid * 8;
    ull aA[4], aB[4];
    #pragma unroll
    for (int i = 0; i < 4; i++){ aA[i] = 0ull; aB[i] = 0ull; }
    ull E[4], O[4];
    #pragma unroll
    for (int i = 0; i < 4; i++){
        E[i] = *(const ull*)(s_x  + base + 2*i);
        O[i] = *(const ull*)(s_xs + base + 2*i);
    }
    #pragma unroll 4
    for (int k2 = 0; k2 < 256; k2++){
        int k = 2*k2;
        ull wa0 = s_wA2[k], wa1 = s_wA2[k+1];
        ull wb0 = s_wB2[k], wb1 = s_wB2[k+1];
        #pragma unroll
        for (int i = 0; i < 4; i++){
            fma2(aA[i], wa0, E[i]);
            fma2(aB[i], wb0, E[i]);
            fma2(aA[i], wa1, O[i]);
            fma2(aB[i], wb1, O[i]);
        }
        E[0]=E[1]; E[1]=E[2]; E[2]=E[3];
        O[0]=O[1]; O[1]=O[2]; O[2]=O[3];
        E[3] = *(const ull*)(s_x  + base + k + 8);
        O[3] = *(const ull*)(s_xs + base + k + 8);
    }

    float* oA = (outA < 0 ? g_mh : g_bands + (size_t)outA*BCT) + row*TLEN;
    float* oB = (outB < 0 ? g_mh : g_bands + (size_t)outB*BCT) + row*TLEN;
    #pragma unroll
    for (int i = 0; i < 4; i++){
        int o = tile0 + base + 2*i;
        if (o < TLEN){
            float lo, hi;
            unpk(aA[i], lo, hi); *(float2*)(oA + o) = make_float2(lo, hi);
            unpk(aB[i], lo, hi); *(float2*)(oB + o) = make_float2(lo, hi);
        }
    }
}

// ---------------- RMS downsample (DS=64) -----------------------------------
__global__ void rms_kernel(){
    int bi = blockIdx.y;
    int tc = blockIdx.x*256 + threadIdx.x;
    if (tc >= TC) return;
    int b = bi / 3, band = bi % 3;
    const float* p0 = g_bands + (size_t)band*BCT + (b*2+0)*TLEN + tc*64;
    const float* p1 = p0 + TLEN;
    float s = 0.0f;
    #pragma unroll
    for (int d = 0; d < 64; d++){ float u = p0[d], v = p1[d]; s += u*u + v*v; }
    g_rms[bi*TC + tc] = sqrtf(s * (1.0f/128.0f) + 1e-7f);
}

// ---------------- envelope: parallel segmented scan -------------------------
__global__ void env_kernel(const float* __restrict__ rel){
    int seq = blockIdx.x;
    int lane = threadIdx.x;
    float k = 1.0f - rel[seq >> 3];
    const float* x = g_rms + seq*TC;
    float* e = g_env + seq*TC;
    const int CL = 44;
    int start = lane*CL;
    int end = min(start + CL, TC);
    float M = 0.0f, p = 1.0f;
    for (int t = start; t < end; t++){ M = fmaxf(x[t], k*M); p *= k; }
    #pragma unroll
    for (int d = 1; d < 32; d <<= 1){
        float Mo = __shfl_up_sync(0xffffffffu, M, d);
        float po = __shfl_up_sync(0xffffffffu, p, d);
        if (lane >= d){ M = fmaxf(M, p*Mo); p *= po; }
    }
    float ein = __shfl_up_sync(0xffffffffu, M, 1);
    float y = (lane == 0) ? 0.0f : ein;
    for (int t = start; t < end; t++){ y = fmaxf(x[t], k*y); e[t] = y; }
}

// ---------------- gain + band combine ---------------------------------------
__global__ void gain_kernel(const float* __restrict__ params, const float* __restrict__ kneep){
    int b = blockIdx.y;
    int t = blockIdx.x*256 + threadIdx.x;
    if (t >= TLEN) return;
    float kdb = kneep[0];
    float pos = (float)t * (1377.0f/88199.0f);
    int i0 = (int)floorf(pos);
    i0 = min(max(i0, 0), TC-2);
    float frac = pos - (float)i0;
    float c0 = 0.0f, c1 = 0.0f;
    #pragma unroll
    for (int band = 0; band < 3; band++){
        const float* er = g_env + (b*3 + band)*TC;
        float e = er[i0]*(1.0f - frac) + er[i0+1]*frac;
        float edb = 20.0f * log10f(e + 1e-7f);
        float ta = params[b*7 + (3 - band)];
        float tb = params[b*7 + (6 - band)];
        float slA = (band == 0) ? 1.0f : (1.0f - 1.0f/66.7f);
        const float slB = 1.0f - 1.0f/4.17f;
        float hk = 0.5f * kdb;
        float d1 = edb - ta, k1;
        if (fabsf(d1) <= hk)      k1 = slA * (d1 + hk)*(d1 + hk) / (2.0f*kdb);
        else if (d1 > hk)         k1 = slA * d1;
        else                      k1 = 0.0f;
        float d2 = tb - edb, k2;
        if (fabsf(d2) <= hk)      k2 = slB * (d2 + hk)*(d2 + hk) / (2.0f*kdb);
        else if (d2 > hk)         k2 = slB * d2;
        else                      k2 = 0.0f;
        float gdb = -k1 + k2 + ((band == 1) ? 5.7f : 10.3f);
        gdb = fminf(fmaxf(gdb, -80.0f), 40.0f);
        float tg = exp2f(gdb * 0.16609640474436813f);
        const float* bb = g_bands + (size_t)band*BCT + (b*2)*TLEN + t;
        c0 += bb[0]    * tg;
        c1 += bb[TLEN] * tg;
    }
    g_comb[(b*2)*TLEN + t]   = c0;
    g_comb[(b*2+1)*TLEN + t] = c1;
}

// ---------------- weight-tile prep: swizzled A images -----------------------
// A[128,192] K-major blocked-atom SW128 (atom 8r x 64col, atom_off = mrow + kcol*16).
// m = kh*64+co, k = kblk*64+ci. kh=0 rows carry taps {0,1}; kh=1 rows carry tap 2.
__global__ void prep_wtiles(const float* __restrict__ w1, const float* __restrict__ w2, const float* __restrict__ w3){
    int layer = blockIdx.y;
    const float* w = (layer == 0) ? w1 : (layer == 1) ? w2 : w3;
    int idx = blockIdx.x*256 + threadIdx.x;
    if (idx >= 24576) return;
    int m = idx / 192, k = idx % 192;
    int kblk = k / 64, ci = k % 64;
    int kh = m >> 6, co = m & 63;
    float v = 0.0f;
    if ((kh == 0 && kblk < 2) || (kh == 1 && kblk == 2)) v = w[co*192 + ci*3 + kblk];
    uint byte = (uint)((m>>3) + kblk*16)*1024u + (uint)(m&7)*128u + (uint)(k&63)*2u;
    uint sw = byte ^ ((byte>>3)&0x70);
    g_wA[layer*24576 + (sw>>1)] = f2bf(v);
}

// ---------------- TCN layer 0: 2 -> 64, dil 1, gelu, bf16 out ---------------
__global__ void __launch_bounds__(256) conv_in(const float* __restrict__ w, const float* __restrict__ bias){
    __shared__ float s_x[2][258];
    __shared__ float s_w[384];
    __shared__ float s_b[64];
    int bb = blockIdx.y;
    int tile0 = blockIdx.x * 256;
    int tid = threadIdx.x;
    for (int i = tid; i < 516; i += 256){
        int c = i / 258, ii = i % 258;
        int g = tile0 - 1 + ii;
        s_x[c][ii] = (g >= 0 && g < TLEN) ? g_comb[(bb*2 + c)*TLEN + g] : 0.0f;
    }
    for (int i = tid; i < 384; i += 256) s_w[i] = w[i];
    if (tid < 64)  s_b[tid] = bias[tid];
    __syncthreads();
    int t = tile0 + tid;
    if (t >= TLEN) return;
    float a0 = s_x[0][tid], a1 = s_x[0][tid+1], a2 = s_x[0][tid+2];
    float c0 = s_x[1][tid], c1 = s_x[1][tid+1], c2 = s_x[1][tid+2];
    #pragma unroll 4
    for (int co = 0; co < 64; co++){
        const float* wp = s_w + co*6;
        float acc = s_b[co] + wp[0]*a0 + wp[1]*a1 + wp[2]*a2
                            + wp[3]*c0 + wp[4]*c1 + wp[5]*c2;
        g_b0[((size_t)bb*64 + co)*TLEN + t] = f2bf(geluf(acc));
    }
}

// ---------------- TCN 64->64 dilated conv: tcgen05 or f32x2 fallback --------
#define SM_A       1024
#define SM_B       (SM_A + 49152)           /* 50176 */
#define B_BYTES    24576
#define XCH_STRIDE 16640                    /* 64 rows * 65 f32 * 4B */
#define SM_LIN     (SM_B + 4*B_BYTES)       /* 148480 */
#define SLIN_W     272
#define SM_TOTAL   (SM_LIN + 64*SLIN_W*2)   /* 183296 */

template<int DIL>
__global__ void __launch_bounds__(512,1) conv64_mma(int src, int layer,
    const float* __restrict__ w, const float* __restrict__ bias)
{
    extern __shared__ char smem[];
    const unsigned short* in = src ? g_b1 : g_b0;
    unsigned short* out      = src ? g_b0 : g_b1;
    int bb = blockIdx.y;
    int t0 = blockIdx.x * 256;
    int tid = threadIdx.x;
    int lane = tid & 31, warp = tid >> 5;

#if HAS_TCGEN05
    uint smem_base = smem_u32(smem);
    uint mbar = smem_base + 8;

    if (warp == 0){
        asm volatile("tcgen05.alloc.cta_group::1.sync.aligned.shared::cta.b32 [%0], %1;"
                     :: "r"(smem_base), "r"(256u) : "memory");
        if (elect1()) asm volatile("mbarrier.init.shared.b64 [%0], 1;" :: "r"(mbar) : "memory");
    }

    // A tile: linear copy of the precomputed swizzled image (49152 B)
    {
        const uint4* wsrc = (const uint4*)(g_wA + layer*24576);
        uint4* adst = (uint4*)(smem + SM_A);
        for (int i = tid; i < 3072; i += 512) adst[i] = wsrc[i];
    }
    // staging: 64 rows x 272 bf16, covering t = t0-8 .. t0+263 (index i <-> t0-8+i)
    {
        const unsigned short* inb = in + (size_t)bb*64*TLEN;
        unsigned short* s_lin = (unsigned short*)(smem + SM_LIN);
        for (int idx = tid; idx < 64*68; idx += 512){
            int ci = idx / 68, j = idx % 68;
            int e = t0 - 8 + 4*j;
            ull v = 0ull;
            if (e >= 0 && e + 3 < TLEN) v = *(const ull*)(inb + (size_t)ci*TLEN + e);
            *(ull*)(s_lin + ci*SLIN_W + 4*j) = v;
        }
    }
    __syncthreads();
    // B tiles: 4 chains x [192 rows x 64 t] MN-major 128B rows, SW128 swizzle.
    // row r = kblk*64+ci holds x[ci, t0+64c + n + (kblk-1)*DIL], n=0..63.
    {
        const unsigned short* s_lin = (const unsigned short*)(smem + SM_LIN);
        for (int idx = tid; idx < 4*6144; idx += 512){
            int c  = idx / 6144;
            int p  = idx - c*6144;
            int r  = p >> 5;                 // 0..191
            int pp = p & 31;                 // uint (2-elem) index within row
            int kblk = r >> 6, ci = r & 63;
            int soff = 8 + c*64 + 2*pp + (kblk - 1)*DIL;   // staging elem index (even)
            uint v = *(const uint*)(s_lin + ci*SLIN_W + soff);
            uint boff = ((uint)r << 7) + ((uint)pp << 2);
            uint sw = boff ^ ((boff>>3)&0x70);
            *(uint*)(smem + SM_B + c*B_BYTES + sw) = v;
        }
    }
    __syncthreads();
    asm volatile("fence.proxy.async.shared::cta;" ::: "memory");

    uint tmem_base;
    asm volatile("ld.shared.b32 %0, [%1];" : "=r"(tmem_base) : "r"(smem_base));

    if (warp == 0 && elect1()){
        ull adesc = desc_kmajor(smem_base + SM_A);
        #pragma unroll
        for (int c = 0; c < 4; c++){
            ull bdesc = desc_mnmajor(smem_base + SM_B + c*B_BYTES);
            #pragma unroll
            for (int s = 0; s < 12; s++){
                // A: K-step 16 elems = 32B = 2 units in atom-col; atom-col stride 16384B = 1024 units
                // B: K-step 16 rows = 2048B = 128 units
                mma_f16_ss(tmem_base + 64*c,
                           adesc + (ull)((s>>2)*1024 + (s&3)*2),
                           bdesc + (ull)(s*128),
                           MMA_IDESC, (s > 0) ? 1u : 0u);
            }
        }
        asm volatile("tcgen05.commit.cta_group::1.mbarrier::arrive::one.shared::cluster.b64 [%0];"
                     :: "r"(mbar) : "memory");
    }

    mbar_wait(mbar, 0);
    asm volatile("tcgen05.fence::after_thread_sync;" ::: "memory");

    // epilogue: warpgroup wg handles chain wg; warp j covers TMEM lanes 32j..32j+31
    int wg = warp >> 2;      // chain 0..3
    int j  = warp & 3;       // subpartition
    uint dr[64];
    TC_LD_X32(dr,      tmem_base + 64*wg);
    TC_LD_X32(dr + 32, tmem_base + 64*wg + 32);
    asm volatile("tcgen05.wait::ld.sync.aligned;" ::: "memory");
    asm volatile("tcgen05.fence::before_thread_sync;" ::: "memory");

    float* xch = (float*)(smem + SM_B + wg*XCH_STRIDE);
    if (j >= 2){                              // kh=1 rows (tap-2 partial sums)
        int co = (j - 2)*32 + lane;
        #pragma unroll
        for (int i = 0; i < 64; i++) xch[co*65 + i] = __uint_as_float(dr[i]);
    }
    __syncthreads();
    if (j < 2){                               // kh=0 rows: combine, gelu, store
        int co = j*32 + lane;
        float bv = bias[co];
        int tbase = t0 + wg*64;
        unsigned short* orow = out + ((size_t)bb*64 + co)*TLEN;
        #pragma unroll
        for (int q = 0; q < 16; q++){
            int t = tbase + 4*q;
            if (t < TLEN){
                unsigned short pk[4];
                #pragma unroll
                for (int h = 0; h < 4; h++){
                    int i = 4*q + h;
                    pk[h] = f2bf(geluf(bv + __uint_as_float(dr[i]) + xch[co*65 + i]));
                }
                *(ull*)(orow + t) = *(ull*)pk;
            }
        }
    }
    __syncthreads();
    if (warp == 0){
        asm volatile("tcgen05.relinquish_alloc_permit.cta_group::1.sync.aligned;");
        asm volatile("tcgen05.dealloc.cta_group::1.sync.aligned.b32 %0, %1;" :: "r"(tmem_base), "r"(256u));
    }
#else
    // -------- f32x2 fallback (R3 design, bf16 in/out) ----------------------
    constexpr int SSTR = 256 + 2*DIL;
    float* s_in = (float*)smem;                          // 64*SSTR floats
    ull* s_w2 = (ull*)(smem + ((64*SSTR*4 + 7) & ~7));   // 12288 ull

    for (int i = tid; i < 12288; i += 512) s_w2[i] = dup2(w[i]);
    const unsigned short* inb = in + (size_t)bb*64*TLEN;
    for (int idx = tid; idx < 64*SSTR; idx += 512){
        int ci = idx / SSTR, ii = idx % SSTR;
        int g = t0 - DIL + ii;
        float v = 0.0f;
        if (g >= 0 && g < TLEN) v = bf2f(inb[(size_t)ci*TLEN + g]);
        s_in[idx] = v;
    }
    __syncthreads();

    int wco = warp & 7, half = warp >> 3;
    ull acc[8][2];
    #pragma unroll
    for (int cc = 0; cc < 8; cc++){ acc[cc][0] = 0ull; acc[cc][1] = 0ull; }

    const ull* wbase = s_w2 + wco*8*192;
    #pragma unroll 2
    for (int ci = 0; ci < 64; ci++){
        const float* r = s_in + ci*SSTR + 2*lane + 128*half;
        ull xin[3][2];
        #pragma unroll
        for (int jj = 0; jj < 3; jj++){
            xin[jj][0] = *(const ull*)(r + jj*DIL);
            xin[jj][1] = *(const ull*)(r + 64 + jj*DIL);
        }
        #pragma unroll
        for (int cc = 0; cc < 8; cc++){
            const ull* wp = wbase + cc*192 + ci*3;
            ull w0 = wp[0], w1 = wp[1], w2 = wp[2];
            #pragma unroll
            for (int p = 0; p < 2; p++){
                fma2(acc[cc][p], w0, xin[0][p]);
                fma2(acc[cc][p], w1, xin[1][p]);
                fma2(acc[cc][p], w2, xin[2][p]);
            }
        }
    }

    unsigned short* outb = out + (size_t)bb*64*TLEN;
    #pragma unroll
    for (int cc = 0; cc < 8; cc++){
        int co = wco*8 + cc;
        float bv = bias[co];
        #pragma unroll
        for (int p = 0; p < 2; p++){
            float lo, hi; unpk(acc[cc][p], lo, hi);
            int t = t0 + 2*lane + 128*half + 64*p;
            if (t < TLEN){
                unsigned short pk[2];
                pk[0] = f2bf(geluf(bv + lo));
                pk[1] = f2bf(geluf(bv + hi));
                *(uint*)(outb + (size_t)co*TLEN + t) = *(uint*)pk;
            }
        }
    }
#endif
}

// ---------------- TCN last layer 64->2 + skip + dry/wet mix -----------------
__global__ void __launch_bounds__(256) conv_out(
    const float* __restrict__ w, const float* __restrict__ bias,
    const float* __restrict__ audio, const float* __restrict__ params,
    float* __restrict__ outp)
{
    extern __shared__ float smemf[];          // 64*258 floats
    __shared__ float s_w[384];
    __shared__ float s_b2[2];
    int bb = blockIdx.y;
    int tile0 = blockIdx.x * 256;
    int tid = threadIdx.x;
    const unsigned short* inb = g_b1 + (size_t)bb*64*TLEN;
    for (int idx = tid; idx < 64*258; idx += 256){
        int ci = idx / 258, ii = idx % 258;
        int g = tile0 - 1 + ii;
        float v = 0.0f;
        if (g >= 0 && g < TLEN) v = bf2f(inb[(size_t)ci*TLEN + g]);
        smemf[idx] = v;
    }
    for (int i = tid; i < 384; i += 256) s_w[i] = w[i];
    if (tid < 2)   s_b2[tid] = bias[tid];
    __syncthreads();
    int t = tile0 + tid;
    if (t >= TLEN) return;
    float acc0 = s_b2[0], acc1 = s_b2[1];
    #pragma unroll 4
    for (int ci = 0; ci < 64; ci++){
        float x0 = smemf[ci*258 + tid], x1 = smemf[ci*258 + tid + 1], x2 = smemf[ci*258 + tid + 2];
        const float* w0p = s_w + ci*3;
        const float* w1p = s_w + 192 + ci*3;
        acc0 += w0p[0]*x0 + w0p[1]*x1 + w0p[2]*x2;
        acc1 += w1p[0]*x0 + w1p[1]*x1 + w1p[2]*x2;
    }
    float amount = params[bb*7];
    int i0 = (bb*2)*TLEN + t;
    int i1 = i0 + TLEN;
    outp[i0] = (1.0f - amount)*audio[i0] + amount*(g_comb[i0] + acc0);
    outp[i1] = (1.0f - amount)*audio[i1] + amount*(g_comb[i1] + acc1);
}

// ---------------- launch -----------------------------------------------------
extern "C" void kernel_launch(void* const* d_in, const int* in_sizes, int n_in,
                              void* d_out, int out_size)
{
    const float* audio = (const float*)d_in[0];
    const float* params = (const float*)d_in[1];
    const float* rel   = (const float*)d_in[2];
    const float* kneep = (const float*)d_in[3];
    const float* irLL  = (const float*)d_in[4];
    const float* irLH  = (const float*)d_in[5];
    const float* irHL  = (const float*)d_in[6];
    const float* irHH  = (const float*)d_in[7];
    const float* w0 = (const float*)d_in[8];  const float* b0 = (const float*)d_in[9];
    const float* w1 = (const float*)d_in[10]; const float* b1 = (const float*)d_in[11];
    const float* w2 = (const float*)d_in[12]; const float* b2 = (const float*)d_in[13];
    const float* w3 = (const float*)d_in[14]; const float* b3 = (const float*)d_in[15];
    const float* w4 = (const float*)d_in[16]; const float* b4 = (const float*)d_in[17];
    float* out = (float*)d_out;

    cudaFuncSetAttribute(conv64_mma<2>, cudaFuncAttributeMaxDynamicSharedMemorySize, SM_TOTAL);
    cudaFuncSetAttribute(conv64_mma<4>, cudaFuncAttributeMaxDynamicSharedMemorySize, SM_TOTAL);
    cudaFuncSetAttribute(conv64_mma<8>, cudaFuncAttributeMaxDynamicSharedMemorySize, SM_TOTAL);
    cudaFuncSetAttribute(conv_out,      cudaFuncAttributeMaxDynamicSharedMemorySize, 64*258*4);

    prep_wtiles<<<dim3(96, 3), 256>>>(w1, w2, w3);

    dim3 gfir((TLEN + 2047)/2048, BATCH*CH);
    fir_pair<<<gfir, 256>>>(audio, 1, irLL, irLH, 2, -1, 1.81970085860998f);
    fir_pair<<<gfir, 256>>>(nullptr, 0, irHL, irHH, 1, 0, 1.0f);

    rms_kernel<<<dim3((TC + 255)/256, 24), 256>>>();
    env_kernel<<<24, 32>>>(rel);

    dim3 gT((TLEN + 255)/256, BATCH);
    gain_kernel<<<gT, 256>>>(params, kneep);

    conv_in<<<gT, 256>>>(w0, b0);
    conv64_mma<2><<<gT, 512, SM_TOTAL>>>(0, 0, w1, b1);
    conv64_mma<4><<<gT, 512, SM_TOTAL>>>(1, 1, w2, b2);
    conv64_mma<8><<<gT, 512, SM_TOTAL>>>(0, 2, w3, b3);
    conv_out<<<gT, 256, 64*258*4>>>(w4, b4, audio, params, out);
}

// round 12
// speedup vs baseline: 2.4824x; 1.2713x over previous
#include <cuda_runtime.h>
#include <cuda_bf16.h>
#include <math.h>

#define BATCH 8
#define CH 2
#define TLEN 88200
#define BCT (BATCH*CH*TLEN)
#define TC 1378
#define KIR 512

typedef unsigned long long ull;
typedef unsigned int uint;

#if defined(__CUDA_ARCH_FEAT_SM103_ALL) || defined(__CUDA_ARCH_FEAT_SM100_ALL)
#define HAS_TCGEN05 1
#else
#define HAS_TCGEN05 0
#endif

// ---------------- scratch (device globals: allocation-free) ----------------
__device__ float g_mh[BCT];
__device__ float g_bands[3*BCT];          // band 0=high, 1=mid, 2=low
__device__ float g_rms[24*TC];
__device__ float g_env[24*TC];
__device__ float g_comb[BCT];
__device__ __align__(16) unsigned short g_b0[BATCH*64*TLEN];   // bf16 activations
__device__ __align__(16) unsigned short g_b1[BATCH*64*TLEN];
__device__ __align__(16) unsigned short g_wA[3*24576];  // swizzled A-tile images

__device__ __forceinline__ float geluf(float x){
    return 0.5f*x*(1.0f + erff(x*0.70710678118654752f));
}
__device__ __forceinline__ void fma2(ull& d, ull a, ull b){
    asm("fma.rn.f32x2 %0, %1, %2, %0;" : "+l"(d) : "l"(a), "l"(b));
}
__device__ __forceinline__ ull dup2(float v){
    ull r; asm("mov.b64 %0, {%1, %2};" : "=l"(r) : "f"(v), "f"(v)); return r;
}
__device__ __forceinline__ void unpk(ull v, float& lo, float& hi){
    asm("mov.b64 {%0, %1}, %2;" : "=f"(lo), "=f"(hi) : "l"(v));
}
__device__ __forceinline__ float bf2f(unsigned short u){
    return __bfloat162float(*(__nv_bfloat16*)&u);
}
__device__ __forceinline__ unsigned short f2bf(float v){
    __nv_bfloat16 b = __float2bfloat16(v);
    return *(unsigned short*)&b;
}

// ---------------- tcgen05 helpers ------------------------------------------
__device__ __forceinline__ uint smem_u32(const void* p){
    uint a; asm("{ .reg .u64 t; cvta.to.shared.u64 t, %1; cvt.u32.u64 %0, t; }" : "=r"(a) : "l"(p)); return a;
}
__device__ __forceinline__ uint elect1(){
    uint p;
    asm volatile("{\n\t.reg .pred P;\n\telect.sync _|P, 0xFFFFFFFF;\n\tselp.b32 %0,1,0,P;\n\t}" : "=r"(p));
    return p;
}
__device__ __forceinline__ void mbar_wait(uint mbar, uint parity){
    asm volatile("{\n\t.reg .pred P;\n\tLW%=:\n\t"
      "mbarrier.try_wait.parity.acquire.cta.shared::cta.b64 P, [%0], %1, 0x989680;\n\t"
      "@P bra LD%=;\n\tbra LW%=;\n\tLD%=:\n\t}" :: "r"(mbar), "r"(parity) : "memory");
}
#if HAS_TCGEN05
__device__ __forceinline__ void mma_f16_ss(uint d, ull a, ull b, uint idesc, uint en){
    asm volatile("{\n\t.reg .pred p;\n\tsetp.ne.u32 p, %5, 0;\n\t"
        "tcgen05.mma.cta_group::1.kind::f16 [%0], %1, %2, %3, {%4,%4,%4,%4}, p;\n\t}"
        :: "r"(d), "l"(a), "l"(b), "r"(idesc), "r"(0u), "r"(en) : "memory");
}
#define TC_LD_X32(r, addr) \
    asm volatile("tcgen05.ld.sync.aligned.32x32b.x32.b32 " \
        "{%0,%1,%2,%3,%4,%5,%6,%7,%8,%9,%10,%11,%12,%13,%14,%15," \
        "%16,%17,%18,%19,%20,%21,%22,%23,%24,%25,%26,%27,%28,%29,%30,%31}, [%32];" \
        : "=r"((r)[0]),"=r"((r)[1]),"=r"((r)[2]),"=r"((r)[3]),"=r"((r)[4]),"=r"((r)[5]),"=r"((r)[6]),"=r"((r)[7]), \
          "=r"((r)[8]),"=r"((r)[9]),"=r"((r)[10]),"=r"((r)[11]),"=r"((r)[12]),"=r"((r)[13]),"=r"((r)[14]),"=r"((r)[15]), \
          "=r"((r)[16]),"=r"((r)[17]),"=r"((r)[18]),"=r"((r)[19]),"=r"((r)[20]),"=r"((r)[21]),"=r"((r)[22]),"=r"((r)[23]), \
          "=r"((r)[24]),"=r"((r)[25]),"=r"((r)[26]),"=r"((r)[27]),"=r"((r)[28]),"=r"((r)[29]),"=r"((r)[30]),"=r"((r)[31]) \
        : "r"(addr))
#endif

// SMEM descriptor bases (Blackwell: version=1, SW128 layout=2)
__device__ __forceinline__ ull desc_kmajor(uint addr){   // LBO=1, SBO=64 (K-major)
    return (2ull<<61) | (1ull<<46) | (64ull<<32) | (1ull<<16) | ((ull)(addr>>4) & 0x3FFF);
}
__device__ __forceinline__ ull desc_mnmajor(uint addr){  // LBO=64, SBO=8 (MN-major)
    return (2ull<<61) | (1ull<<46) | (8ull<<32) | (64ull<<16) | ((ull)(addr>>4) & 0x3FFF);
}
// idesc: F32 accum(1<<4), BF16 a(1<<7), BF16 b(1<<10), TransB(1<<16), N=64(8<<17), M=128(8<<24)
#define MMA_IDESC 0x08110490u

// ---------------- FIR: two 512-tap filters, f32x2 with register rotation ---
__global__ void __launch_bounds__(256) fir_pair(
    const float* __restrict__ xext, int use_ext,
    const float* __restrict__ wA, const float* __restrict__ wB,
    int outA, int outB, float gain)
{
    __shared__ __align__(16) float s_x[2564];
    __shared__ __align__(16) float s_xs[2564];
    __shared__ ull s_wA2[512];
    __shared__ ull s_wB2[512];
    int row  = blockIdx.y;
    int tile0 = blockIdx.x * 2048;
    int tid = threadIdx.x;
    const float* xr = (use_ext ? xext : (const float*)g_mh) + row*TLEN;
    for (int i = tid; i < 2564; i += 256){
        int g = tile0 - (KIR-1) + i;
        s_x[i] = (g >= 0 && g < TLEN) ? xr[g] * gain : 0.0f;
    }
    for (int i = tid; i < 512; i += 256){ s_wA2[i] = dup2(wA[i]); s_wB2[i] = dup2(wB[i]); }
    __syncthreads();
    for (int i = tid; i < 2563; i += 256) s_xs[i] = s_x[i+1];
    if (tid == 0) s_xs[2563] = 0.0f;
    __syncthreads();

    int base = tid * 8;
    ull aA[4], aB[4];
    #pragma unroll
    for (int i = 0; i < 4; i++){ aA[i] = 0ull; aB[i] = 0ull; }
    ull E[4], O[4];
    #pragma unroll
    for (int i = 0; i < 4; i++){
        E[i] = *(const ull*)(s_x  + base + 2*i);
        O[i] = *(const ull*)(s_xs + base + 2*i);
    }
    #pragma unroll 4
    for (int k2 = 0; k2 < 256; k2++){
        int k = 2*k2;
        ull wa0 = s_wA2[k], wa1 = s_wA2[k+1];
        ull wb0 = s_wB2[k], wb1 = s_wB2[k+1];
        #pragma unroll
        for (int i = 0; i < 4; i++){
            fma2(aA[i], wa0, E[i]);
            fma2(aB[i], wb0, E[i]);
            fma2(aA[i], wa1, O[i]);
            fma2(aB[i], wb1, O[i]);
        }
        E[0]=E[1]; E[1]=E[2]; E[2]=E[3];
        O[0]=O[1]; O[1]=O[2]; O[2]=O[3];
        E[3] = *(const ull*)(s_x  + base + k + 8);
        O[3] = *(const ull*)(s_xs + base + k + 8);
    }

    float* oA = (outA < 0 ? g_mh : g_bands + (size_t)outA*BCT) + row*TLEN;
    float* oB = (outB < 0 ? g_mh : g_bands + (size_t)outB*BCT) + row*TLEN;
    #pragma unroll
    for (int i = 0; i < 4; i++){
        int o = tile0 + base + 2*i;
        if (o < TLEN){
            float lo, hi;
            unpk(aA[i], lo, hi); *(float2*)(oA + o) = make_float2(lo, hi);
            unpk(aB[i], lo, hi); *(float2*)(oB + o) = make_float2(lo, hi);
        }
    }
}

// ---------------- RMS downsample (DS=64) -----------------------------------
__global__ void rms_kernel(){
    int bi = blockIdx.y;
    int tc = blockIdx.x*256 + threadIdx.x;
    if (tc >= TC) return;
    int b = bi / 3, band = bi % 3;
    const float* p0 = g_bands + (size_t)band*BCT + (b*2+0)*TLEN + tc*64;
    const float* p1 = p0 + TLEN;
    float s = 0.0f;
    #pragma unroll
    for (int d = 0; d < 64; d++){ float u = p0[d], v = p1[d]; s += u*u + v*v; }
    g_rms[bi*TC + tc] = sqrtf(s * (1.0f/128.0f) + 1e-7f);
}

// ---------------- envelope: parallel segmented scan -------------------------
__global__ void env_kernel(const float* __restrict__ rel){
    int seq = blockIdx.x;
    int lane = threadIdx.x;
    float k = 1.0f - rel[seq >> 3];
    const float* x = g_rms + seq*TC;
    float* e = g_env + seq*TC;
    const int CL = 44;
    int start = lane*CL;
    int end = min(start + CL, TC);
    float M = 0.0f, p = 1.0f;
    for (int t = start; t < end; t++){ M = fmaxf(x[t], k*M); p *= k; }
    #pragma unroll
    for (int d = 1; d < 32; d <<= 1){
        float Mo = __shfl_up_sync(0xffffffffu, M, d);
        float po = __shfl_up_sync(0xffffffffu, p, d);
        if (lane >= d){ M = fmaxf(M, p*Mo); p *= po; }
    }
    float ein = __shfl_up_sync(0xffffffffu, M, 1);
    float y = (lane == 0) ? 0.0f : ein;
    for (int t = start; t < end; t++){ y = fmaxf(x[t], k*y); e[t] = y; }
}

// ---------------- gain + band combine ---------------------------------------
__global__ void gain_kernel(const float* __restrict__ params, const float* __restrict__ kneep){
    int b = blockIdx.y;
    int t = blockIdx.x*256 + threadIdx.x;
    if (t >= TLEN) return;
    float kdb = kneep[0];
    float pos = (float)t * (1377.0f/88199.0f);
    int i0 = (int)floorf(pos);
    i0 = min(max(i0, 0), TC-2);
    float frac = pos - (float)i0;
    float c0 = 0.0f, c1 = 0.0f;
    #pragma unroll
    for (int band = 0; band < 3; band++){
        const float* er = g_env + (b*3 + band)*TC;
        float e = er[i0]*(1.0f - frac) + er[i0+1]*frac;
        float edb = 20.0f * log10f(e + 1e-7f);
        float ta = params[b*7 + (3 - band)];
        float tb = params[b*7 + (6 - band)];
        float slA = (band == 0) ? 1.0f : (1.0f - 1.0f/66.7f);
        const float slB = 1.0f - 1.0f/4.17f;
        float hk = 0.5f * kdb;
        float d1 = edb - ta, k1;
        if (fabsf(d1) <= hk)      k1 = slA * (d1 + hk)*(d1 + hk) / (2.0f*kdb);
        else if (d1 > hk)         k1 = slA * d1;
        else                      k1 = 0.0f;
        float d2 = tb - edb, k2;
        if (fabsf(d2) <= hk)      k2 = slB * (d2 + hk)*(d2 + hk) / (2.0f*kdb);
        else if (d2 > hk)         k2 = slB * d2;
        else                      k2 = 0.0f;
        float gdb = -k1 + k2 + ((band == 1) ? 5.7f : 10.3f);
        gdb = fminf(fmaxf(gdb, -80.0f), 40.0f);
        float tg = exp2f(gdb * 0.16609640474436813f);
        const float* bb = g_bands + (size_t)band*BCT + (b*2)*TLEN + t;
        c0 += bb[0]    * tg;
        c1 += bb[TLEN] * tg;
    }
    g_comb[(b*2)*TLEN + t]   = c0;
    g_comb[(b*2+1)*TLEN + t] = c1;
}

// ---------------- weight-tile prep: swizzled A images -----------------------
// A[128,192] K-major blocked-atom SW128 (atom 8r x 64col, atom_off = mrow + kcol*16).
// m = kh*64+co, k = kblk*64+ci. kh=0 rows carry taps {0,1}; kh=1 rows carry tap 2.
__global__ void prep_wtiles(const float* __restrict__ w1, const float* __restrict__ w2, const float* __restrict__ w3){
    int layer = blockIdx.y;
    const float* w = (layer == 0) ? w1 : (layer == 1) ? w2 : w3;
    int idx = blockIdx.x*256 + threadIdx.x;
    if (idx >= 24576) return;
    int m = idx / 192, k = idx % 192;
    int kblk = k / 64, ci = k % 64;
    int kh = m >> 6, co = m & 63;
    float v = 0.0f;
    if ((kh == 0 && kblk < 2) || (kh == 1 && kblk == 2)) v = w[co*192 + ci*3 + kblk];
    uint byte = (uint)((m>>3) + kblk*16)*1024u + (uint)(m&7)*128u + (uint)(k&63)*2u;
    uint sw = byte ^ ((byte>>3)&0x70);
    g_wA[layer*24576 + (sw>>1)] = f2bf(v);
}

// ---------------- TCN layer 0: 2 -> 64, dil 1, gelu, bf16 out ---------------
__global__ void __launch_bounds__(256) conv_in(const float* __restrict__ w, const float* __restrict__ bias){
    __shared__ float s_x[2][258];
    __shared__ float s_w[384];
    __shared__ float s_b[64];
    int bb = blockIdx.y;
    int tile0 = blockIdx.x * 256;
    int tid = threadIdx.x;
    for (int i = tid; i < 516; i += 256){
        int c = i / 258, ii = i % 258;
        int g = tile0 - 1 + ii;
        s_x[c][ii] = (g >= 0 && g < TLEN) ? g_comb[(bb*2 + c)*TLEN + g] : 0.0f;
    }
    for (int i = tid; i < 384; i += 256) s_w[i] = w[i];
    if (tid < 64)  s_b[tid] = bias[tid];
    __syncthreads();
    int t = tile0 + tid;
    if (t >= TLEN) return;
    float a0 = s_x[0][tid], a1 = s_x[0][tid+1], a2 = s_x[0][tid+2];
    float c0 = s_x[1][tid], c1 = s_x[1][tid+1], c2 = s_x[1][tid+2];
    #pragma unroll 4
    for (int co = 0; co < 64; co++){
        const float* wp = s_w + co*6;
        float acc = s_b[co] + wp[0]*a0 + wp[1]*a1 + wp[2]*a2
                            + wp[3]*c0 + wp[4]*c1 + wp[5]*c2;
        g_b0[((size_t)bb*64 + co)*TLEN + t] = f2bf(geluf(acc));
    }
}

// ---------------- TCN 64->64 dilated conv: tcgen05, occ=2 -------------------
// Per block: 128 t = 2 chains of D[128,64] = A[128,192] @ B[192,64] (TransB).
// smem: [0..1K ctrl][A 48K][B 2x24K] = 99328 B -> 2 CTAs/SM.
#define SM_A       1024
#define C64_BBYTES 24576
#define SM_B2      (SM_A + 49152)            /* 50176 */
#define XCH_STRIDE 16640                     /* 64 rows * 65 f32 * 4B */
#define C64_TOTAL  (SM_B2 + 2*C64_BBYTES)    /* 99328 */

template<int DIL>
__global__ void __launch_bounds__(256,2) conv64_mma(int src, int layer,
    const float* __restrict__ w, const float* __restrict__ bias)
{
    extern __shared__ char smem[];
    const unsigned short* in = src ? g_b1 : g_b0;
    unsigned short* out      = src ? g_b0 : g_b1;
    int bb = blockIdx.y;
    int t0 = blockIdx.x * 128;
    int tid = threadIdx.x;
    int lane = tid & 31, warp = tid >> 5;

#if HAS_TCGEN05
    uint smem_base = smem_u32(smem);
    uint mbar = smem_base + 8;

    if (warp == 0){
        asm volatile("tcgen05.alloc.cta_group::1.sync.aligned.shared::cta.b32 [%0], %1;"
                     :: "r"(smem_base), "r"(128u) : "memory");
        if (elect1()) asm volatile("mbarrier.init.shared.b64 [%0], 1;" :: "r"(mbar) : "memory");
    }

    // A tile: linear copy of the precomputed swizzled image (49152 B)
    {
        const uint4* wsrc = (const uint4*)(g_wA + layer*24576);
        uint4* adst = (uint4*)(smem + SM_A);
        #pragma unroll
        for (int i = 0; i < 12; i++) adst[tid + 256*i] = wsrc[tid + 256*i];
    }
    // B tiles built DIRECTLY from gmem: 2 chains x [192 rows x 64 t] MN-major
    // 128B rows, SW128. Row r = kblk*64+ci holds x[ci, t0+64c + n + (kblk-1)*DIL].
    {
        const unsigned short* inb = in + (size_t)bb*64*TLEN;
        #pragma unroll
        for (int ii = 0; ii < 48; ii++){
            int idx = tid + 256*ii;                  // < 12288
            int c  = idx >> 12;                      // /4096... careful: 2*6144=12288
            int p  = idx & 6143;                     // valid since 6144 = 0x1800 not pow2!
            // (replaced below with exact div)
            c = idx / 6144;
            p = idx - c*6144;
            int r  = p >> 5;                         // 0..191
            int pp = p & 31;
            int kblk = r >> 6, ci = r & 63;
            int t = t0 + 64*c + 2*pp + (kblk - 1)*DIL;   // even
            uint v = 0u;
            if (t >= 0 && t < TLEN) v = *(const uint*)(inb + (size_t)ci*TLEN + t);
            uint boff = ((uint)r << 7) + ((uint)pp << 2);
            uint sw = boff ^ ((boff>>3)&0x70);
            *(uint*)(smem + SM_B2 + c*C64_BBYTES + sw) = v;
        }
    }
    __syncthreads();
    asm volatile("fence.proxy.async.shared::cta;" ::: "memory");

    uint tmem_base;
    asm volatile("ld.shared.b32 %0, [%1];" : "=r"(tmem_base) : "r"(smem_base));

    if (warp == 0 && elect1()){
        ull adesc = desc_kmajor(smem_base + SM_A);
        #pragma unroll
        for (int c = 0; c < 2; c++){
            ull bdesc = desc_mnmajor(smem_base + SM_B2 + c*C64_BBYTES);
            #pragma unroll
            for (int s = 0; s < 12; s++){
                // A: K-step 16 elems = 2 desc units in atom-col; atom-col stride 1024 units
                // B: K-step 16 rows = 2048B = 128 units
                mma_f16_ss(tmem_base + 64*c,
                           adesc + (ull)((s>>2)*1024 + (s&3)*2),
                           bdesc + (ull)(s*128),
                           MMA_IDESC, (s > 0) ? 1u : 0u);
            }
        }
        asm volatile("tcgen05.commit.cta_group::1.mbarrier::arrive::one.shared::cluster.b64 [%0];"
                     :: "r"(mbar) : "memory");
    }

    mbar_wait(mbar, 0);
    asm volatile("tcgen05.fence::after_thread_sync;" ::: "memory");

    // epilogue: warpgroup wg (0,1) handles chain wg; warp j covers TMEM lanes 32j
    int wg = warp >> 2;      // chain 0..1 (8 warps = 2 warpgroups)
    int j  = warp & 3;
    uint dr[64];
    TC_LD_X32(dr,      tmem_base + 64*wg);
    TC_LD_X32(dr + 32, tmem_base + 64*wg + 32);
    asm volatile("tcgen05.wait::ld.sync.aligned;" ::: "memory");
    asm volatile("tcgen05.fence::before_thread_sync;" ::: "memory");

    float* xch = (float*)(smem + SM_B2 + wg*XCH_STRIDE);   // aliases B (done with it)
    if (j >= 2){                              // kh=1 rows (tap-2 partial sums)
        int co = (j - 2)*32 + lane;
        #pragma unroll
        for (int i = 0; i < 64; i++) xch[co*65 + i] = __uint_as_float(dr[i]);
    }
    __syncthreads();
    if (j < 2){                               // kh=0 rows: combine, gelu, store
        int co = j*32 + lane;
        float bv = bias[co];
        int tbase = t0 + wg*64;
        unsigned short* orow = out + ((size_t)bb*64 + co)*TLEN;
        #pragma unroll
        for (int q = 0; q < 16; q++){
            int t = tbase + 4*q;
            if (t < TLEN){
                unsigned short pk[4];
                #pragma unroll
                for (int h = 0; h < 4; h++){
                    int i = 4*q + h;
                    pk[h] = f2bf(geluf(bv + __uint_as_float(dr[i]) + xch[co*65 + i]));
                }
                *(ull*)(orow + t) = *(ull*)pk;
            }
        }
    }
    __syncthreads();
    if (warp == 0){
        asm volatile("tcgen05.relinquish_alloc_permit.cta_group::1.sync.aligned;");
        asm volatile("tcgen05.dealloc.cta_group::1.sync.aligned.b32 %0, %1;" :: "r"(tmem_base), "r"(128u));
    }
#else
    // -------- f32x2 fallback (compiled for non-'a' virtual arch) -----------
    constexpr int SSTR = 128 + 2*DIL;
    float* s_in = (float*)smem;                          // 64*SSTR floats
    float* s_w  = (float*)(smem + 64*SSTR*4);            // 12288 floats (48KB)

    for (int i = tid; i < 12288; i += 256) s_w[i] = w[i];
    const unsigned short* inb = in + (size_t)bb*64*TLEN;
    for (int idx = tid; idx < 64*SSTR; idx += 256){
        int ci = idx / SSTR, ii = idx % SSTR;
        int g = t0 - DIL + ii;
        float v = 0.0f;
        if (g >= 0 && g < TLEN) v = bf2f(inb[(size_t)ci*TLEN + g]);
        s_in[idx] = v;
    }
    __syncthreads();

    int wco = warp;                      // 8 warps x 8 co
    ull acc[8][2];
    #pragma unroll
    for (int cc = 0; cc < 8; cc++){ acc[cc][0] = 0ull; acc[cc][1] = 0ull; }

    for (int ci = 0; ci < 64; ci++){
        const float* r = s_in + ci*SSTR + 2*lane;
        ull xin[3][2];
        #pragma unroll
        for (int jj = 0; jj < 3; jj++){
            xin[jj][0] = *(const ull*)(r + jj*DIL);
            xin[jj][1] = *(const ull*)(r + 64 + jj*DIL);
        }
        #pragma unroll
        for (int cc = 0; cc < 8; cc++){
            const float* wp = s_w + (wco*8 + cc)*192 + ci*3;
            ull w0 = dup2(wp[0]), w1 = dup2(wp[1]), w2 = dup2(wp[2]);
            #pragma unroll
            for (int p = 0; p < 2; p++){
                fma2(acc[cc][p], w0, xin[0][p]);
                fma2(acc[cc][p], w1, xin[1][p]);
                fma2(acc[cc][p], w2, xin[2][p]);
            }
        }
    }

    unsigned short* outb = out + (size_t)bb*64*TLEN;
    #pragma unroll
    for (int cc = 0; cc < 8; cc++){
        int co = wco*8 + cc;
        float bv = bias[co];
        #pragma unroll
        for (int p = 0; p < 2; p++){
            float lo, hi; unpk(acc[cc][p], lo, hi);
            int t = t0 + 2*lane + 64*p;
            if (t < TLEN){
                unsigned short pk[2];
                pk[0] = f2bf(geluf(bv + lo));
                pk[1] = f2bf(geluf(bv + hi));
                *(uint*)(outb + (size_t)co*TLEN + t) = *(uint*)pk;
            }
        }
    }
#endif
}

// ---------------- TCN last layer 64->2 + skip + dry/wet mix -----------------
#define COUT_W 264
__global__ void __launch_bounds__(256) conv_out(
    const float* __restrict__ w, const float* __restrict__ bias,
    const float* __restrict__ audio, const float* __restrict__ params,
    float* __restrict__ outp)
{
    extern __shared__ float smemf[];          // 64*COUT_W floats
    __shared__ float s_w[384];
    __shared__ float s_b2[2];
    int bb = blockIdx.y;
    int tile0 = blockIdx.x * 256;
    int tid = threadIdx.x;
    const unsigned short* inb = g_b1 + (size_t)bb*64*TLEN;
    // vectorized fill: 66 ull (4 bf16 each) per ci, covering t0-4 .. t0+259
    for (int idx = tid; idx < 64*66; idx += 256){
        int ci = idx / 66, j = idx % 66;
        int e = tile0 - 4 + 4*j;
        float v0=0,v1=0,v2=0,v3=0;
        if (e >= 0 && e + 3 < TLEN){
            ull u = *(const ull*)(inb + (size_t)ci*TLEN + e);
            unsigned short* s = (unsigned short*)&u;
            v0 = bf2f(s[0]); v1 = bf2f(s[1]); v2 = bf2f(s[2]); v3 = bf2f(s[3]);
        } else {
            #pragma unroll
            for (int h = 0; h < 4; h++){
                int g = e + h;
                float vv = (g >= 0 && g < TLEN) ? bf2f(inb[(size_t)ci*TLEN + g]) : 0.0f;
                if (h==0) v0=vv; else if (h==1) v1=vv; else if (h==2) v2=vv; else v3=vv;
            }
        }
        float* d = smemf + ci*COUT_W + 4*j;
        d[0]=v0; d[1]=v1; d[2]=v2; d[3]=v3;
    }
    for (int i = tid; i < 384; i += 256) s_w[i] = w[i];
    if (tid < 2)   s_b2[tid] = bias[tid];
    __syncthreads();
    int t = tile0 + tid;
    if (t >= TLEN) return;
    float acc0 = s_b2[0], acc1 = s_b2[1];
    #pragma unroll 4
    for (int ci = 0; ci < 64; ci++){
        const float* xr = smemf + ci*COUT_W + tid + 3;   // index of t-1
        float x0 = xr[0], x1 = xr[1], x2 = xr[2];
        const float* w0p = s_w + ci*3;
        const float* w1p = s_w + 192 + ci*3;
        acc0 += w0p[0]*x0 + w0p[1]*x1 + w0p[2]*x2;
        acc1 += w1p[0]*x0 + w1p[1]*x1 + w1p[2]*x2;
    }
    float amount = params[bb*7];
    int i0 = (bb*2)*TLEN + t;
    int i1 = i0 + TLEN;
    outp[i0] = (1.0f - amount)*audio[i0] + amount*(g_comb[i0] + acc0);
    outp[i1] = (1.0f - amount)*audio[i1] + amount*(g_comb[i1] + acc1);
}

// ---------------- launch -----------------------------------------------------
extern "C" void kernel_launch(void* const* d_in, const int* in_sizes, int n_in,
                              void* d_out, int out_size)
{
    const float* audio = (const float*)d_in[0];
    const float* params = (const float*)d_in[1];
    const float* rel   = (const float*)d_in[2];
    const float* kneep = (const float*)d_in[3];
    const float* irLL  = (const float*)d_in[4];
    const float* irLH  = (const float*)d_in[5];
    const float* irHL  = (const float*)d_in[6];
    const float* irHH  = (const float*)d_in[7];
    const float* w0 = (const float*)d_in[8];  const float* b0 = (const float*)d_in[9];
    const float* w1 = (const float*)d_in[10]; const float* b1 = (const float*)d_in[11];
    const float* w2 = (const float*)d_in[12]; const float* b2 = (const float*)d_in[13];
    const float* w3 = (const float*)d_in[14]; const float* b3 = (const float*)d_in[15];
    const float* w4 = (const float*)d_in[16]; const float* b4 = (const float*)d_in[17];
    float* out = (float*)d_out;

    cudaFuncSetAttribute(conv64_mma<2>, cudaFuncAttributeMaxDynamicSharedMemorySize, C64_TOTAL);
    cudaFuncSetAttribute(conv64_mma<4>, cudaFuncAttributeMaxDynamicSharedMemorySize, C64_TOTAL);
    cudaFuncSetAttribute(conv64_mma<8>, cudaFuncAttributeMaxDynamicSharedMemorySize, C64_TOTAL);
    cudaFuncSetAttribute(conv_out,      cudaFuncAttributeMaxDynamicSharedMemorySize, 64*COUT_W*4);

    prep_wtiles<<<dim3(96, 3), 256>>>(w1, w2, w3);

    dim3 gfir((TLEN + 2047)/2048, BATCH*CH);
    fir_pair<<<gfir, 256>>>(audio, 1, irLL, irLH, 2, -1, 1.81970085860998f);
    fir_pair<<<gfir, 256>>>(nullptr, 0, irHL, irHH, 1, 0, 1.0f);

    rms_kernel<<<dim3((TC + 255)/256, 24), 256>>>();
    env_kernel<<<24, 32>>>(rel);

    dim3 gT((TLEN + 255)/256, BATCH);
    gain_kernel<<<gT, 256>>>(params, kneep);

    conv_in<<<gT, 256>>>(w0, b0);
    dim3 gC((TLEN + 127)/128, BATCH);
    conv64_mma<2><<<gC, 256, C64_TOTAL>>>(0, 0, w1, b1);
    conv64_mma<4><<<gC, 256, C64_TOTAL>>>(1, 1, w2, b2);
    conv64_mma<8><<<gC, 256, C64_TOTAL>>>(0, 2, w3, b3);
    conv_out<<<gT, 256, 64*COUT_W*4>>>(w4, b4, audio, params, out);
}

// round 13
// speedup vs baseline: 2.6662x; 1.0740x over previous
#include <cuda_runtime.h>
#include <cuda_bf16.h>
#include <math.h>

#define BATCH 8
#define CH 2
#define TLEN 88200
#define BCT (BATCH*CH*TLEN)
#define TC 1378
#define KIR 512
#define NT 690                 /* ceil(TLEN/128) tiles per batch row */
#define NWORK (NT*BATCH)
#define PGRID 296              /* persistent grid: 2 CTAs x 148 SMs */

typedef unsigned long long ull;
typedef unsigned int uint;

#if defined(__CUDA_ARCH_FEAT_SM103_ALL) || defined(__CUDA_ARCH_FEAT_SM100_ALL)
#define HAS_TCGEN05 1
#else
#define HAS_TCGEN05 0
#endif

// ---------------- scratch (device globals: allocation-free) ----------------
__device__ float g_mh[BCT];
__device__ float g_bands[3*BCT];          // band 0=high, 1=mid, 2=low
__device__ float g_rms[24*TC];
__device__ float g_env[24*TC];
__device__ float g_comb[BCT];
__device__ __align__(16) unsigned short g_b0[BATCH*64*TLEN];   // bf16 activations
__device__ __align__(16) unsigned short g_b1[BATCH*64*TLEN];
__device__ __align__(16) unsigned short g_wA[3*24576];  // swizzled A-tile images

__device__ __forceinline__ float geluf(float x){
    return 0.5f*x*(1.0f + erff(x*0.70710678118654752f));
}
__device__ __forceinline__ void fma2(ull& d, ull a, ull b){
    asm("fma.rn.f32x2 %0, %1, %2, %0;" : "+l"(d) : "l"(a), "l"(b));
}
__device__ __forceinline__ ull dup2(float v){
    ull r; asm("mov.b64 %0, {%1, %2};" : "=l"(r) : "f"(v), "f"(v)); return r;
}
__device__ __forceinline__ void unpk(ull v, float& lo, float& hi){
    asm("mov.b64 {%0, %1}, %2;" : "=f"(lo), "=f"(hi) : "l"(v));
}
__device__ __forceinline__ float bf2f(unsigned short u){
    return __bfloat162float(*(__nv_bfloat16*)&u);
}
__device__ __forceinline__ unsigned short f2bf(float v){
    __nv_bfloat16 b = __float2bfloat16(v);
    return *(unsigned short*)&b;
}

// ---------------- tcgen05 helpers ------------------------------------------
__device__ __forceinline__ uint smem_u32(const void* p){
    uint a; asm("{ .reg .u64 t; cvta.to.shared.u64 t, %1; cvt.u32.u64 %0, t; }" : "=r"(a) : "l"(p)); return a;
}
__device__ __forceinline__ uint elect1(){
    uint p;
    asm volatile("{\n\t.reg .pred P;\n\telect.sync _|P, 0xFFFFFFFF;\n\tselp.b32 %0,1,0,P;\n\t}" : "=r"(p));
    return p;
}
__device__ __forceinline__ void mbar_wait(uint mbar, uint parity){
    asm volatile("{\n\t.reg .pred P;\n\tLW%=:\n\t"
      "mbarrier.try_wait.parity.acquire.cta.shared::cta.b64 P, [%0], %1, 0x989680;\n\t"
      "@P bra LD%=;\n\tbra LW%=;\n\tLD%=:\n\t}" :: "r"(mbar), "r"(parity) : "memory");
}
#if HAS_TCGEN05
__device__ __forceinline__ void mma_f16_ss(uint d, ull a, ull b, uint idesc, uint en){
    asm volatile("{\n\t.reg .pred p;\n\tsetp.ne.u32 p, %5, 0;\n\t"
        "tcgen05.mma.cta_group::1.kind::f16 [%0], %1, %2, %3, {%4,%4,%4,%4}, p;\n\t}"
        :: "r"(d), "l"(a), "l"(b), "r"(idesc), "r"(0u), "r"(en) : "memory");
}
#define TC_LD_X32(r, addr) \
    asm volatile("tcgen05.ld.sync.aligned.32x32b.x32.b32 " \
        "{%0,%1,%2,%3,%4,%5,%6,%7,%8,%9,%10,%11,%12,%13,%14,%15," \
        "%16,%17,%18,%19,%20,%21,%22,%23,%24,%25,%26,%27,%28,%29,%30,%31}, [%32];" \
        : "=r"((r)[0]),"=r"((r)[1]),"=r"((r)[2]),"=r"((r)[3]),"=r"((r)[4]),"=r"((r)[5]),"=r"((r)[6]),"=r"((r)[7]), \
          "=r"((r)[8]),"=r"((r)[9]),"=r"((r)[10]),"=r"((r)[11]),"=r"((r)[12]),"=r"((r)[13]),"=r"((r)[14]),"=r"((r)[15]), \
          "=r"((r)[16]),"=r"((r)[17]),"=r"((r)[18]),"=r"((r)[19]),"=r"((r)[20]),"=r"((r)[21]),"=r"((r)[22]),"=r"((r)[23]), \
          "=r"((r)[24]),"=r"((r)[25]),"=r"((r)[26]),"=r"((r)[27]),"=r"((r)[28]),"=r"((r)[29]),"=r"((r)[30]),"=r"((r)[31]) \
        : "r"(addr))
#endif

// SMEM descriptor bases (Blackwell: version=1, SW128 layout=2)
__device__ __forceinline__ ull desc_kmajor(uint addr){   // LBO=1, SBO=64 (K-major)
    return (2ull<<61) | (1ull<<46) | (64ull<<32) | (1ull<<16) | ((ull)(addr>>4) & 0x3FFF);
}
__device__ __forceinline__ ull desc_mnmajor(uint addr){  // LBO=64, SBO=8 (MN-major)
    return (2ull<<61) | (1ull<<46) | (8ull<<32) | (64ull<<16) | ((ull)(addr>>4) & 0x3FFF);
}
// idesc: F32 accum(1<<4), BF16 a(1<<7), BF16 b(1<<10), TransB(1<<16), N=64(8<<17), M=128(8<<24)
#define MMA_IDESC 0x08110490u

// ---------------- FIR: two 512-tap filters, f32x2 with register rotation ---
__global__ void __launch_bounds__(256) fir_pair(
    const float* __restrict__ xext, int use_ext,
    const float* __restrict__ wA, const float* __restrict__ wB,
    int outA, int outB, float gain)
{
    __shared__ __align__(16) float s_x[2564];
    __shared__ __align__(16) float s_xs[2564];
    __shared__ ull s_wA2[512];
    __shared__ ull s_wB2[512];
    int row  = blockIdx.y;
    int tile0 = blockIdx.x * 2048;
    int tid = threadIdx.x;
    const float* xr = (use_ext ? xext : (const float*)g_mh) + row*TLEN;
    for (int i = tid; i < 2564; i += 256){
        int g = tile0 - (KIR-1) + i;
        s_x[i] = (g >= 0 && g < TLEN) ? xr[g] * gain : 0.0f;
    }
    for (int i = tid; i < 512; i += 256){ s_wA2[i] = dup2(wA[i]); s_wB2[i] = dup2(wB[i]); }
    __syncthreads();
    for (int i = tid; i < 2563; i += 256) s_xs[i] = s_x[i+1];
    if (tid == 0) s_xs[2563] = 0.0f;
    __syncthreads();

    int base = tid * 8;
    ull aA[4], aB[4];
    #pragma unroll
    for (int i = 0; i < 4; i++){ aA[i] = 0ull; aB[i] = 0ull; }
    ull E[4], O[4];
    #pragma unroll
    for (int i = 0; i < 4; i++){
        E[i] = *(const ull*)(s_x  + base + 2*i);
        O[i] = *(const ull*)(s_xs + base + 2*i);
    }
    #pragma unroll 4
    for (int k2 = 0; k2 < 256; k2++){
        int k = 2*k2;
        ull wa0 = s_wA2[k], wa1 = s_wA2[k+1];
        ull wb0 = s_wB2[k], wb1 = s_wB2[k+1];
        #pragma unroll
        for (int i = 0; i < 4; i++){
            fma2(aA[i], wa0, E[i]);
            fma2(aB[i], wb0, E[i]);
            fma2(aA[i], wa1, O[i]);
            fma2(aB[i], wb1, O[i]);
        }
        E[0]=E[1]; E[1]=E[2]; E[2]=E[3];
        O[0]=O[1]; O[1]=O[2]; O[2]=O[3];
        E[3] = *(const ull*)(s_x  + base + k + 8);
        O[3] = *(const ull*)(s_xs + base + k + 8);
    }

    float* oA = (outA < 0 ? g_mh : g_bands + (size_t)outA*BCT) + row*TLEN;
    float* oB = (outB < 0 ? g_mh : g_bands + (size_t)outB*BCT) + row*TLEN;
    #pragma unroll
    for (int i = 0; i < 4; i++){
        int o = tile0 + base + 2*i;
        if (o < TLEN){
            float lo, hi;
            unpk(aA[i], lo, hi); *(float2*)(oA + o) = make_float2(lo, hi);
            unpk(aB[i], lo, hi); *(float2*)(oB + o) = make_float2(lo, hi);
        }
    }
}

// ---------------- RMS downsample (DS=64) -----------------------------------
__global__ void rms_kernel(){
    int bi = blockIdx.y;
    int tc = blockIdx.x*256 + threadIdx.x;
    if (tc >= TC) return;
    int b = bi / 3, band = bi % 3;
    const float* p0 = g_bands + (size_t)band*BCT + (b*2+0)*TLEN + tc*64;
    const float* p1 = p0 + TLEN;
    float s = 0.0f;
    #pragma unroll
    for (int d = 0; d < 64; d++){ float u = p0[d], v = p1[d]; s += u*u + v*v; }
    g_rms[bi*TC + tc] = sqrtf(s * (1.0f/128.0f) + 1e-7f);
}

// ---------------- envelope: parallel segmented scan -------------------------
__global__ void env_kernel(const float* __restrict__ rel){
    int seq = blockIdx.x;
    int lane = threadIdx.x;
    float k = 1.0f - rel[seq >> 3];
    const float* x = g_rms + seq*TC;
    float* e = g_env + seq*TC;
    const int CL = 44;
    int start = lane*CL;
    int end = min(start + CL, TC);
    float M = 0.0f, p = 1.0f;
    for (int t = start; t < end; t++){ M = fmaxf(x[t], k*M); p *= k; }
    #pragma unroll
    for (int d = 1; d < 32; d <<= 1){
        float Mo = __shfl_up_sync(0xffffffffu, M, d);
        float po = __shfl_up_sync(0xffffffffu, p, d);
        if (lane >= d){ M = fmaxf(M, p*Mo); p *= po; }
    }
    float ein = __shfl_up_sync(0xffffffffu, M, 1);
    float y = (lane == 0) ? 0.0f : ein;
    for (int t = start; t < end; t++){ y = fmaxf(x[t], k*y); e[t] = y; }
}

// ---------------- gain + band combine ---------------------------------------
__global__ void gain_kernel(const float* __restrict__ params, const float* __restrict__ kneep){
    int b = blockIdx.y;
    int t = blockIdx.x*256 + threadIdx.x;
    if (t >= TLEN) return;
    float kdb = kneep[0];
    float pos = (float)t * (1377.0f/88199.0f);
    int i0 = (int)floorf(pos);
    i0 = min(max(i0, 0), TC-2);
    float frac = pos - (float)i0;
    float c0 = 0.0f, c1 = 0.0f;
    #pragma unroll
    for (int band = 0; band < 3; band++){
        const float* er = g_env + (b*3 + band)*TC;
        float e = er[i0]*(1.0f - frac) + er[i0+1]*frac;
        float edb = 20.0f * log10f(e + 1e-7f);
        float ta = params[b*7 + (3 - band)];
        float tb = params[b*7 + (6 - band)];
        float slA = (band == 0) ? 1.0f : (1.0f - 1.0f/66.7f);
        const float slB = 1.0f - 1.0f/4.17f;
        float hk = 0.5f * kdb;
        float d1 = edb - ta, k1;
        if (fabsf(d1) <= hk)      k1 = slA * (d1 + hk)*(d1 + hk) / (2.0f*kdb);
        else if (d1 > hk)         k1 = slA * d1;
        else                      k1 = 0.0f;
        float d2 = tb - edb, k2;
        if (fabsf(d2) <= hk)      k2 = slB * (d2 + hk)*(d2 + hk) / (2.0f*kdb);
        else if (d2 > hk)         k2 = slB * d2;
        else                      k2 = 0.0f;
        float gdb = -k1 + k2 + ((band == 1) ? 5.7f : 10.3f);
        gdb = fminf(fmaxf(gdb, -80.0f), 40.0f);
        float tg = exp2f(gdb * 0.16609640474436813f);
        const float* bb = g_bands + (size_t)band*BCT + (b*2)*TLEN + t;
        c0 += bb[0]    * tg;
        c1 += bb[TLEN] * tg;
    }
    g_comb[(b*2)*TLEN + t]   = c0;
    g_comb[(b*2+1)*TLEN + t] = c1;
}

// ---------------- weight-tile prep: swizzled A images -----------------------
__global__ void prep_wtiles(const float* __restrict__ w1, const float* __restrict__ w2, const float* __restrict__ w3){
    int layer = blockIdx.y;
    const float* w = (layer == 0) ? w1 : (layer == 1) ? w2 : w3;
    int idx = blockIdx.x*256 + threadIdx.x;
    if (idx >= 24576) return;
    int m = idx / 192, k = idx % 192;
    int kblk = k / 64, ci = k % 64;
    int kh = m >> 6, co = m & 63;
    float v = 0.0f;
    if ((kh == 0 && kblk < 2) || (kh == 1 && kblk == 2)) v = w[co*192 + ci*3 + kblk];
    uint byte = (uint)((m>>3) + kblk*16)*1024u + (uint)(m&7)*128u + (uint)(k&63)*2u;
    uint sw = byte ^ ((byte>>3)&0x70);
    g_wA[layer*24576 + (sw>>1)] = f2bf(v);
}

// ---------------- TCN layer 0: 2 -> 64, dil 1, gelu, bf16 out ---------------
__global__ void __launch_bounds__(256) conv_in(const float* __restrict__ w, const float* __restrict__ bias){
    __shared__ float s_x[2][258];
    __shared__ float s_w[384];
    __shared__ float s_b[64];
    int bb = blockIdx.y;
    int tile0 = blockIdx.x * 256;
    int tid = threadIdx.x;
    for (int i = tid; i < 516; i += 256){
        int c = i / 258, ii = i % 258;
        int g = tile0 - 1 + ii;
        s_x[c][ii] = (g >= 0 && g < TLEN) ? g_comb[(bb*2 + c)*TLEN + g] : 0.0f;
    }
    for (int i = tid; i < 384; i += 256) s_w[i] = w[i];
    if (tid < 64)  s_b[tid] = bias[tid];
    __syncthreads();
    int t = tile0 + tid;
    if (t >= TLEN) return;
    float a0 = s_x[0][tid], a1 = s_x[0][tid+1], a2 = s_x[0][tid+2];
    float c0 = s_x[1][tid], c1 = s_x[1][tid+1], c2 = s_x[1][tid+2];
    #pragma unroll 4
    for (int co = 0; co < 64; co++){
        const float* wp = s_w + co*6;
        float acc = s_b[co] + wp[0]*a0 + wp[1]*a1 + wp[2]*a2
                            + wp[3]*c0 + wp[4]*c1 + wp[5]*c2;
        g_b0[((size_t)bb*64 + co)*TLEN + t] = f2bf(geluf(acc));
    }
}

// ---------------- TCN 64->64 dilated conv: persistent tcgen05, occ=2 --------
// Persistent CTA: A + TMEM alloc once; loop over (bb, tile) work items.
// Per tile: 128 t = 2 chains of D[128,64] = A[128,192] @ B[192,64] (TransB).
#define SM_A       1024
#define C64_BBYTES 24576
#define SM_B2      (SM_A + 49152)            /* 50176 */
#define XCH_STRIDE 16640                     /* 64 rows * 65 f32 * 4B */
#define C64_TOTAL  (SM_B2 + 2*C64_BBYTES)    /* 99328 */

template<int DIL>
__global__ void __launch_bounds__(256,2) conv64_mma(int src, int layer,
    const float* __restrict__ w, const float* __restrict__ bias)
{
    extern __shared__ char smem[];
    const unsigned short* in = src ? g_b1 : g_b0;
    unsigned short* out      = src ? g_b0 : g_b1;
    int tid = threadIdx.x;
    int lane = tid & 31, warp = tid >> 5;

#if HAS_TCGEN05
    uint smem_base = smem_u32(smem);
    uint mbar = smem_base + 8;

    if (warp == 0){
        asm volatile("tcgen05.alloc.cta_group::1.sync.aligned.shared::cta.b32 [%0], %1;"
                     :: "r"(smem_base), "r"(128u) : "memory");
        if (elect1()) asm volatile("mbarrier.init.shared.b64 [%0], 1;" :: "r"(mbar) : "memory");
    }
    // A tile: loaded ONCE per persistent CTA (49152 B)
    {
        const uint4* wsrc = (const uint4*)(g_wA + layer*24576);
        uint4* adst = (uint4*)(smem + SM_A);
        #pragma unroll
        for (int i = 0; i < 12; i++) adst[tid + 256*i] = wsrc[tid + 256*i];
    }
    __syncthreads();

    uint tmem_base;
    asm volatile("ld.shared.b32 %0, [%1];" : "=r"(tmem_base) : "r"(smem_base));
    ull adesc = desc_kmajor(smem_base + SM_A);
    float bv01[2];
    // biases for this thread's two epilogue roles (loaded once)
    {
        int j = warp & 3;
        int co = (j < 2) ? (j*32 + lane) : ((j-2)*32 + lane);
        bv01[0] = bias[co];
        bv01[1] = 0.0f;
    }

    int it = 0;
    for (int work = blockIdx.x; work < NWORK; work += PGRID, it++){
        int bb = work / NT;
        int t0 = (work - bb*NT) * 128;
        int par = it & 1;

        // B tiles from gmem: 2 chains x [192 rows x 64 t] MN-major, SW128.
        {
            const unsigned short* inb = in + (size_t)bb*64*TLEN;
            #pragma unroll
            for (int ii = 0; ii < 48; ii++){
                int idx = tid + 256*ii;              // < 12288
                int c = idx / 6144;
                int p = idx - c*6144;
                int r  = p >> 5;                     // 0..191
                int pp = p & 31;
                int kblk = r >> 6, ci = r & 63;
                int t = t0 + 64*c + 2*pp + (kblk - 1)*DIL;   // even
                uint v = 0u;
                if (t >= 0 && t < TLEN) v = *(const uint*)(inb + (size_t)ci*TLEN + t);
                uint boff = ((uint)r << 7) + ((uint)pp << 2);
                uint sw = boff ^ ((boff>>3)&0x70);
                *(uint*)(smem + SM_B2 + c*C64_BBYTES + sw) = v;
            }
        }
        __syncthreads();
        asm volatile("fence.proxy.async.shared::cta;" ::: "memory");

        if (warp == 0 && elect1()){
            #pragma unroll
            for (int c = 0; c < 2; c++){
                ull bdesc = desc_mnmajor(smem_base + SM_B2 + c*C64_BBYTES);
                #pragma unroll
                for (int s = 0; s < 12; s++){
                    mma_f16_ss(tmem_base + 64*c,
                               adesc + (ull)((s>>2)*1024 + (s&3)*2),
                               bdesc + (ull)(s*128),
                               MMA_IDESC, (s > 0) ? 1u : 0u);
                }
            }
            asm volatile("tcgen05.commit.cta_group::1.mbarrier::arrive::one.shared::cluster.b64 [%0];"
                         :: "r"(mbar) : "memory");
        }

        mbar_wait(mbar, par);
        asm volatile("tcgen05.fence::after_thread_sync;" ::: "memory");

        int wg = warp >> 2;      // chain 0..1
        int j  = warp & 3;
        uint dr[64];
        TC_LD_X32(dr,      tmem_base + 64*wg);
        TC_LD_X32(dr + 32, tmem_base + 64*wg + 32);
        asm volatile("tcgen05.wait::ld.sync.aligned;" ::: "memory");
        asm volatile("tcgen05.fence::before_thread_sync;" ::: "memory");

        float* xch = (float*)(smem + SM_B2 + wg*XCH_STRIDE);   // aliases B (dead)
        if (j >= 2){                              // kh=1 rows (tap-2 partials)
            int co = (j - 2)*32 + lane;
            #pragma unroll
            for (int i = 0; i < 64; i++) xch[co*65 + i] = __uint_as_float(dr[i]);
        }
        __syncthreads();
        if (j < 2){                               // kh=0 rows: combine+gelu+store
            int co = j*32 + lane;
            float bv = bv01[0];
            int tbase = t0 + wg*64;
            unsigned short* orow = out + ((size_t)bb*64 + co)*TLEN;
            #pragma unroll
            for (int q = 0; q < 16; q++){
                int t = tbase + 4*q;
                if (t < TLEN){
                    unsigned short pk[4];
                    #pragma unroll
                    for (int h = 0; h < 4; h++){
                        int i = 4*q + h;
                        pk[h] = f2bf(geluf(bv + __uint_as_float(dr[i]) + xch[co*65 + i]));
                    }
                    *(ull*)(orow + t) = *(ull*)pk;
                }
            }
        }
        __syncthreads();
    }
    if (warp == 0){
        asm volatile("tcgen05.relinquish_alloc_permit.cta_group::1.sync.aligned;");
        asm volatile("tcgen05.dealloc.cta_group::1.sync.aligned.b32 %0, %1;" :: "r"(tmem_base), "r"(128u));
    }
#else
    // -------- f32x2 fallback (non-'a' virtual arch), persistent loop -------
    constexpr int SSTR = 128 + 2*DIL;
    float* s_in = (float*)smem;                          // 64*SSTR floats
    float* s_w  = (float*)(smem + 64*SSTR*4);            // 12288 floats

    for (int i = tid; i < 12288; i += 256) s_w[i] = w[i];
    __syncthreads();

    for (int work = blockIdx.x; work < NWORK; work += PGRID){
        int bb = work / NT;
        int t0 = (work - bb*NT) * 128;
        const unsigned short* inb = in + (size_t)bb*64*TLEN;
        for (int idx = tid; idx < 64*SSTR; idx += 256){
            int ci = idx / SSTR, ii = idx % SSTR;
            int g = t0 - DIL + ii;
            float v = 0.0f;
            if (g >= 0 && g < TLEN) v = bf2f(inb[(size_t)ci*TLEN + g]);
            s_in[idx] = v;
        }
        __syncthreads();

        int wco = warp;
        ull acc[8][2];
        #pragma unroll
        for (int cc = 0; cc < 8; cc++){ acc[cc][0] = 0ull; acc[cc][1] = 0ull; }
        for (int ci = 0; ci < 64; ci++){
            const float* r = s_in + ci*SSTR + 2*lane;
            ull xin[3][2];
            #pragma unroll
            for (int jj = 0; jj < 3; jj++){
                xin[jj][0] = *(const ull*)(r + jj*DIL);
                xin[jj][1] = *(const ull*)(r + 64 + jj*DIL);
            }
            #pragma unroll
            for (int cc = 0; cc < 8; cc++){
                const float* wp = s_w + (wco*8 + cc)*192 + ci*3;
                ull w0 = dup2(wp[0]), w1 = dup2(wp[1]), w2 = dup2(wp[2]);
                #pragma unroll
                for (int p = 0; p < 2; p++){
                    fma2(acc[cc][p], w0, xin[0][p]);
                    fma2(acc[cc][p], w1, xin[1][p]);
                    fma2(acc[cc][p], w2, xin[2][p]);
                }
            }
        }

        unsigned short* outb = out + (size_t)bb*64*TLEN;
        #pragma unroll
        for (int cc = 0; cc < 8; cc++){
            int co = wco*8 + cc;
            float bv = bias[co];
            #pragma unroll
            for (int p = 0; p < 2; p++){
                float lo, hi; unpk(acc[cc][p], lo, hi);
                int t = t0 + 2*lane + 64*p;
                if (t < TLEN){
                    unsigned short pk[2];
                    pk[0] = f2bf(geluf(bv + lo));
                    pk[1] = f2bf(geluf(bv + hi));
                    *(uint*)(outb + (size_t)co*TLEN + t) = *(uint*)pk;
                }
            }
        }
        __syncthreads();
    }
#endif
}

// ---------------- TCN last layer 64->2 + skip + dry/wet mix -----------------
#define COUT_W 264
__global__ void __launch_bounds__(256) conv_out(
    const float* __restrict__ w, const float* __restrict__ bias,
    const float* __restrict__ audio, const float* __restrict__ params,
    float* __restrict__ outp)
{
    extern __shared__ float smemf[];          // 64*COUT_W floats
    __shared__ float s_w[384];
    __shared__ float s_b2[2];
    int bb = blockIdx.y;
    int tile0 = blockIdx.x * 256;
    int tid = threadIdx.x;
    const unsigned short* inb = g_b1 + (size_t)bb*64*TLEN;
    for (int idx = tid; idx < 64*66; idx += 256){
        int ci = idx / 66, j = idx % 66;
        int e = tile0 - 4 + 4*j;
        float v0=0,v1=0,v2=0,v3=0;
        if (e >= 0 && e + 3 < TLEN){
            ull u = *(const ull*)(inb + (size_t)ci*TLEN + e);
            unsigned short* s = (unsigned short*)&u;
            v0 = bf2f(s[0]); v1 = bf2f(s[1]); v2 = bf2f(s[2]); v3 = bf2f(s[3]);
        } else {
            #pragma unroll
            for (int h = 0; h < 4; h++){
                int g = e + h;
                float vv = (g >= 0 && g < TLEN) ? bf2f(inb[(size_t)ci*TLEN + g]) : 0.0f;
                if (h==0) v0=vv; else if (h==1) v1=vv; else if (h==2) v2=vv; else v3=vv;
            }
        }
        float* d = smemf + ci*COUT_W + 4*j;
        d[0]=v0; d[1]=v1; d[2]=v2; d[3]=v3;
    }
    for (int i = tid; i < 384; i += 256) s_w[i] = w[i];
    if (tid < 2)   s_b2[tid] = bias[tid];
    __syncthreads();
    int t = tile0 + tid;
    if (t >= TLEN) return;
    float acc0 = s_b2[0], acc1 = s_b2[1];
    #pragma unroll 4
    for (int ci = 0; ci < 64; ci++){
        const float* xr = smemf + ci*COUT_W + tid + 3;   // index of t-1
        float x0 = xr[0], x1 = xr[1], x2 = xr[2];
        const float* w0p = s_w + ci*3;
        const float* w1p = s_w + 192 + ci*3;
        acc0 += w0p[0]*x0 + w0p[1]*x1 + w0p[2]*x2;
        acc1 += w1p[0]*x0 + w1p[1]*x1 + w1p[2]*x2;
    }
    float amount = params[bb*7];
    int i0 = (bb*2)*TLEN + t;
    int i1 = i0 + TLEN;
    outp[i0] = (1.0f - amount)*audio[i0] + amount*(g_comb[i0] + acc0);
    outp[i1] = (1.0f - amount)*audio[i1] + amount*(g_comb[i1] + acc1);
}

// ---------------- launch -----------------------------------------------------
extern "C" void kernel_launch(void* const* d_in, const int* in_sizes, int n_in,
                              void* d_out, int out_size)
{
    const float* audio = (const float*)d_in[0];
    const float* params = (const float*)d_in[1];
    const float* rel   = (const float*)d_in[2];
    const float* kneep = (const float*)d_in[3];
    const float* irLL  = (const float*)d_in[4];
    const float* irLH  = (const float*)d_in[5];
    const float* irHL  = (const float*)d_in[6];
    const float* irHH  = (const float*)d_in[7];
    const float* w0 = (const float*)d_in[8];  const float* b0 = (const float*)d_in[9];
    const float* w1 = (const float*)d_in[10]; const float* b1 = (const float*)d_in[11];
    const float* w2 = (const float*)d_in[12]; const float* b2 = (const float*)d_in[13];
    const float* w3 = (const float*)d_in[14]; const float* b3 = (const float*)d_in[15];
    const float* w4 = (const float*)d_in[16]; const float* b4 = (const float*)d_in[17];
    float* out = (float*)d_out;

    cudaFuncSetAttribute(conv64_mma<2>, cudaFuncAttributeMaxDynamicSharedMemorySize, C64_TOTAL);
    cudaFuncSetAttribute(conv64_mma<4>, cudaFuncAttributeMaxDynamicSharedMemorySize, C64_TOTAL);
    cudaFuncSetAttribute(conv64_mma<8>, cudaFuncAttributeMaxDynamicSharedMemorySize, C64_TOTAL);
    cudaFuncSetAttribute(conv_out,      cudaFuncAttributeMaxDynamicSharedMemorySize, 64*COUT_W*4);

    prep_wtiles<<<dim3(96, 3), 256>>>(w1, w2, w3);

    dim3 gfir((TLEN + 2047)/2048, BATCH*CH);
    fir_pair<<<gfir, 256>>>(audio, 1, irLL, irLH, 2, -1, 1.81970085860998f);
    fir_pair<<<gfir, 256>>>(nullptr, 0, irHL, irHH, 1, 0, 1.0f);

    rms_kernel<<<dim3((TC + 255)/256, 24), 256>>>();
    env_kernel<<<24, 32>>>(rel);

    dim3 gT((TLEN + 255)/256, BATCH);
    gain_kernel<<<gT, 256>>>(params, kneep);

    conv_in<<<gT, 256>>>(w0, b0);
    conv64_mma<2><<<PGRID, 256, C64_TOTAL>>>(0, 0, w1, b1);
    conv64_mma<4><<<PGRID, 256, C64_TOTAL>>>(1, 1, w2, b2);
    conv64_mma<8><<<PGRID, 256, C64_TOTAL>>>(0, 2, w3, b3);
    conv_out<<<gT, 256, 64*COUT_W*4>>>(w4, b4, audio, params, out);
}

// round 14
// speedup vs baseline: 2.9248x; 1.0970x over previous
#include <cuda_runtime.h>
#include <cuda_bf16.h>
#include <math.h>

#define BATCH 8
#define CH 2
#define TLEN 88200
#define BCT (BATCH*CH*TLEN)
#define TC 1378
#define KIR 512
#define NT 690                 /* ceil(TLEN/128) tiles per batch row */
#define NWORK (NT*BATCH)
#define PGRID 296              /* persistent grid: 2 CTAs x 148 SMs */

typedef unsigned long long ull;
typedef unsigned int uint;

#if defined(__CUDA_ARCH_FEAT_SM103_ALL) || defined(__CUDA_ARCH_FEAT_SM100_ALL)
#define HAS_TCGEN05 1
#else
#define HAS_TCGEN05 0
#endif

// ---------------- scratch (device globals: allocation-free) ----------------
__device__ float g_mh[BCT];
__device__ float g_bands[3*BCT];          // band 0=high, 1=mid, 2=low
__device__ float g_rms[24*TC];
__device__ float g_env[24*TC];
__device__ float g_comb[BCT];
__device__ __align__(16) unsigned short g_b0[BATCH*64*TLEN];   // bf16 activations
__device__ __align__(16) unsigned short g_b1[BATCH*64*TLEN];
__device__ __align__(16) unsigned short g_wA[3*24576];  // swizzled A-tile images

// tanh-form gelu approximation (hidden path only; res is w4(x0.01)-scaled,
// so ~3e-4 abs hidden error -> ~3e-6 output rel err). 2 MUFU + ~6 FMA.
__device__ __forceinline__ float geluf(float x){
    float x2 = x*x;
    float t = x*(0.7978845608f + 0.0356774081f*x2);
    float e; asm("ex2.approx.f32 %0, %1;" : "=f"(e) : "f"(2.885390082f*t));
    float r; asm("rcp.approx.f32 %0, %1;" : "=f"(r) : "f"(e + 1.0f));
    float th = 1.0f - 2.0f*r;                  // tanh(t)
    return 0.5f*x*(1.0f + th);
}
__device__ __forceinline__ void fma2(ull& d, ull a, ull b){
    asm("fma.rn.f32x2 %0, %1, %2, %0;" : "+l"(d) : "l"(a), "l"(b));
}
__device__ __forceinline__ ull dup2(float v){
    ull r; asm("mov.b64 %0, {%1, %2};" : "=l"(r) : "f"(v), "f"(v)); return r;
}
__device__ __forceinline__ void unpk(ull v, float& lo, float& hi){
    asm("mov.b64 {%0, %1}, %2;" : "=f"(lo), "=f"(hi) : "l"(v));
}
__device__ __forceinline__ float bf2f(unsigned short u){
    return __bfloat162float(*(__nv_bfloat16*)&u);
}
__device__ __forceinline__ unsigned short f2bf(float v){
    __nv_bfloat16 b = __float2bfloat16(v);
    return *(unsigned short*)&b;
}

// ---------------- tcgen05 helpers ------------------------------------------
__device__ __forceinline__ uint smem_u32(const void* p){
    uint a; asm("{ .reg .u64 t; cvta.to.shared.u64 t, %1; cvt.u32.u64 %0, t; }" : "=r"(a) : "l"(p)); return a;
}
__device__ __forceinline__ uint elect1(){
    uint p;
    asm volatile("{\n\t.reg .pred P;\n\telect.sync _|P, 0xFFFFFFFF;\n\tselp.b32 %0,1,0,P;\n\t}" : "=r"(p));
    return p;
}
__device__ __forceinline__ void mbar_wait(uint mbar, uint parity){
    asm volatile("{\n\t.reg .pred P;\n\tLW%=:\n\t"
      "mbarrier.try_wait.parity.acquire.cta.shared::cta.b64 P, [%0], %1, 0x989680;\n\t"
      "@P bra LD%=;\n\tbra LW%=;\n\tLD%=:\n\t}" :: "r"(mbar), "r"(parity) : "memory");
}
#if HAS_TCGEN05
__device__ __forceinline__ void mma_f16_ss(uint d, ull a, ull b, uint idesc, uint en){
    asm volatile("{\n\t.reg .pred p;\n\tsetp.ne.u32 p, %5, 0;\n\t"
        "tcgen05.mma.cta_group::1.kind::f16 [%0], %1, %2, %3, {%4,%4,%4,%4}, p;\n\t}"
        :: "r"(d), "l"(a), "l"(b), "r"(idesc), "r"(0u), "r"(en) : "memory");
}
#define TC_LD_X32(r, addr) \
    asm volatile("tcgen05.ld.sync.aligned.32x32b.x32.b32 " \
        "{%0,%1,%2,%3,%4,%5,%6,%7,%8,%9,%10,%11,%12,%13,%14,%15," \
        "%16,%17,%18,%19,%20,%21,%22,%23,%24,%25,%26,%27,%28,%29,%30,%31}, [%32];" \
        : "=r"((r)[0]),"=r"((r)[1]),"=r"((r)[2]),"=r"((r)[3]),"=r"((r)[4]),"=r"((r)[5]),"=r"((r)[6]),"=r"((r)[7]), \
          "=r"((r)[8]),"=r"((r)[9]),"=r"((r)[10]),"=r"((r)[11]),"=r"((r)[12]),"=r"((r)[13]),"=r"((r)[14]),"=r"((r)[15]), \
          "=r"((r)[16]),"=r"((r)[17]),"=r"((r)[18]),"=r"((r)[19]),"=r"((r)[20]),"=r"((r)[21]),"=r"((r)[22]),"=r"((r)[23]), \
          "=r"((r)[24]),"=r"((r)[25]),"=r"((r)[26]),"=r"((r)[27]),"=r"((r)[28]),"=r"((r)[29]),"=r"((r)[30]),"=r"((r)[31]) \
        : "r"(addr))
#endif

// SMEM descriptor bases (Blackwell: version=1, SW128 layout=2)
__device__ __forceinline__ ull desc_kmajor(uint addr){   // LBO=1, SBO=64 (K-major)
    return (2ull<<61) | (1ull<<46) | (64ull<<32) | (1ull<<16) | ((ull)(addr>>4) & 0x3FFF);
}
__device__ __forceinline__ ull desc_mnmajor(uint addr){  // LBO=64, SBO=8 (MN-major)
    return (2ull<<61) | (1ull<<46) | (8ull<<32) | (64ull<<16) | ((ull)(addr>>4) & 0x3FFF);
}
// idesc: F32 accum(1<<4), BF16 a(1<<7), BF16 b(1<<10), TransB(1<<16), N=64(8<<17), M=128(8<<24)
#define MMA_IDESC 0x08110490u

// ---------------- FIR: two 512-tap filters, f32x2 with register rotation ---
__global__ void __launch_bounds__(256) fir_pair(
    const float* __restrict__ xext, int use_ext,
    const float* __restrict__ wA, const float* __restrict__ wB,
    int outA, int outB, float gain)
{
    __shared__ __align__(16) float s_x[2564];
    __shared__ __align__(16) float s_xs[2564];
    __shared__ ull s_wA2[512];
    __shared__ ull s_wB2[512];
    int row  = blockIdx.y;
    int tile0 = blockIdx.x * 2048;
    int tid = threadIdx.x;
    const float* xr = (use_ext ? xext : (const float*)g_mh) + row*TLEN;
    for (int i = tid; i < 2564; i += 256){
        int g = tile0 - (KIR-1) + i;
        s_x[i] = (g >= 0 && g < TLEN) ? xr[g] * gain : 0.0f;
    }
    for (int i = tid; i < 512; i += 256){ s_wA2[i] = dup2(wA[i]); s_wB2[i] = dup2(wB[i]); }
    __syncthreads();
    for (int i = tid; i < 2563; i += 256) s_xs[i] = s_x[i+1];
    if (tid == 0) s_xs[2563] = 0.0f;
    __syncthreads();

    int base = tid * 8;
    ull aA[4], aB[4];
    #pragma unroll
    for (int i = 0; i < 4; i++){ aA[i] = 0ull; aB[i] = 0ull; }
    ull E[4], O[4];
    #pragma unroll
    for (int i = 0; i < 4; i++){
        E[i] = *(const ull*)(s_x  + base + 2*i);
        O[i] = *(const ull*)(s_xs + base + 2*i);
    }
    #pragma unroll 4
    for (int k2 = 0; k2 < 256; k2++){
        int k = 2*k2;
        ull wa0 = s_wA2[k], wa1 = s_wA2[k+1];
        ull wb0 = s_wB2[k], wb1 = s_wB2[k+1];
        #pragma unroll
        for (int i = 0; i < 4; i++){
            fma2(aA[i], wa0, E[i]);
            fma2(aB[i], wb0, E[i]);
            fma2(aA[i], wa1, O[i]);
            fma2(aB[i], wb1, O[i]);
        }
        E[0]=E[1]; E[1]=E[2]; E[2]=E[3];
        O[0]=O[1]; O[1]=O[2]; O[2]=O[3];
        E[3] = *(const ull*)(s_x  + base + k + 8);
        O[3] = *(const ull*)(s_xs + base + k + 8);
    }

    float* oA = (outA < 0 ? g_mh : g_bands + (size_t)outA*BCT) + row*TLEN;
    float* oB = (outB < 0 ? g_mh : g_bands + (size_t)outB*BCT) + row*TLEN;
    #pragma unroll
    for (int i = 0; i < 4; i++){
        int o = tile0 + base + 2*i;
        if (o < TLEN){
            float lo, hi;
            unpk(aA[i], lo, hi); *(float2*)(oA + o) = make_float2(lo, hi);
            unpk(aB[i], lo, hi); *(float2*)(oB + o) = make_float2(lo, hi);
        }
    }
}

// ---------------- RMS downsample (DS=64), float4 loads ----------------------
__global__ void rms_kernel(){
    int bi = blockIdx.y;
    int tc = blockIdx.x*256 + threadIdx.x;
    if (tc >= TC) return;
    int b = bi / 3, band = bi % 3;
    const float4* p0 = (const float4*)(g_bands + (size_t)band*BCT + (b*2+0)*TLEN + tc*64);
    const float4* p1 = (const float4*)(g_bands + (size_t)band*BCT + (b*2+1)*TLEN + tc*64);
    float s = 0.0f;
    #pragma unroll
    for (int d = 0; d < 16; d++){
        float4 u = p0[d], v = p1[d];
        s += u.x*u.x + u.y*u.y + u.z*u.z + u.w*u.w;
        s += v.x*v.x + v.y*v.y + v.z*v.z + v.w*v.w;
    }
    g_rms[bi*TC + tc] = sqrtf(s * (1.0f/128.0f) + 1e-7f);
}

// ---------------- envelope: parallel segmented scan -------------------------
__global__ void env_kernel(const float* __restrict__ rel){
    int seq = blockIdx.x;
    int lane = threadIdx.x;
    float k = 1.0f - rel[seq >> 3];
    const float* x = g_rms + seq*TC;
    float* e = g_env + seq*TC;
    const int CL = 44;
    int start = lane*CL;
    int end = min(start + CL, TC);
    float M = 0.0f, p = 1.0f;
    for (int t = start; t < end; t++){ M = fmaxf(x[t], k*M); p *= k; }
    #pragma unroll
    for (int d = 1; d < 32; d <<= 1){
        float Mo = __shfl_up_sync(0xffffffffu, M, d);
        float po = __shfl_up_sync(0xffffffffu, p, d);
        if (lane >= d){ M = fmaxf(M, p*Mo); p *= po; }
    }
    float ein = __shfl_up_sync(0xffffffffu, M, 1);
    float y = (lane == 0) ? 0.0f : ein;
    for (int t = start; t < end; t++){ y = fmaxf(x[t], k*y); e[t] = y; }
}

// ---------------- weight-tile prep: swizzled A images -----------------------
__global__ void prep_wtiles(const float* __restrict__ w1, const float* __restrict__ w2, const float* __restrict__ w3){
    int layer = blockIdx.y;
    const float* w = (layer == 0) ? w1 : (layer == 1) ? w2 : w3;
    int idx = blockIdx.x*256 + threadIdx.x;
    if (idx >= 24576) return;
    int m = idx / 192, k = idx % 192;
    int kblk = k / 64, ci = k % 64;
    int kh = m >> 6, co = m & 63;
    float v = 0.0f;
    if ((kh == 0 && kblk < 2) || (kh == 1 && kblk == 2)) v = w[co*192 + ci*3 + kblk];
    uint byte = (uint)((m>>3) + kblk*16)*1024u + (uint)(m&7)*128u + (uint)(k&63)*2u;
    uint sw = byte ^ ((byte>>3)&0x70);
    g_wA[layer*24576 + (sw>>1)] = f2bf(v);
}

// ---------------- FUSED: gain + band combine + conv_in (2->64) --------------
// Computes combined (incl. 1-elem halo) per tile, writes g_comb for the skip
// path, then immediately runs the 2->64 conv + gelu into g_b0 (bf16).
__global__ void __launch_bounds__(256) gain_conv_in(
    const float* __restrict__ params, const float* __restrict__ kneep,
    const float* __restrict__ w, const float* __restrict__ bias)
{
    __shared__ float s_c[2][258];
    __shared__ float s_w[384];
    __shared__ float s_b[64];
    int bb = blockIdx.y;
    int tile0 = blockIdx.x * 256;
    int tid = threadIdx.x;
    float kdb = kneep[0];

    for (int idx = tid; idx < 258; idx += 256){
        int t = tile0 - 1 + idx;
        float c0 = 0.0f, c1 = 0.0f;
        if (t >= 0 && t < TLEN){
            float pos = (float)t * (1377.0f/88199.0f);
            int i0 = (int)floorf(pos);
            i0 = min(max(i0, 0), TC-2);
            float frac = pos - (float)i0;
            #pragma unroll
            for (int band = 0; band < 3; band++){
                const float* er = g_env + (bb*3 + band)*TC;
                float e = er[i0]*(1.0f - frac) + er[i0+1]*frac;
                float edb = 20.0f * log10f(e + 1e-7f);
                float ta = params[bb*7 + (3 - band)];
                float tb = params[bb*7 + (6 - band)];
                float slA = (band == 0) ? 1.0f : (1.0f - 1.0f/66.7f);
                const float slB = 1.0f - 1.0f/4.17f;
                float hk = 0.5f * kdb;
                float d1 = edb - ta, k1;
                if (fabsf(d1) <= hk)      k1 = slA * (d1 + hk)*(d1 + hk) / (2.0f*kdb);
                else if (d1 > hk)         k1 = slA * d1;
                else                      k1 = 0.0f;
                float d2 = tb - edb, k2;
                if (fabsf(d2) <= hk)      k2 = slB * (d2 + hk)*(d2 + hk) / (2.0f*kdb);
                else if (d2 > hk)         k2 = slB * d2;
                else                      k2 = 0.0f;
                float gdb = -k1 + k2 + ((band == 1) ? 5.7f : 10.3f);
                gdb = fminf(fmaxf(gdb, -80.0f), 40.0f);
                float tg = exp2f(gdb * 0.16609640474436813f);
                const float* bptr = g_bands + (size_t)band*BCT + (bb*2)*TLEN + t;
                c0 += bptr[0]    * tg;
                c1 += bptr[TLEN] * tg;
            }
        }
        s_c[0][idx] = c0;
        s_c[1][idx] = c1;
        if (idx >= 1 && idx <= 256 && t < TLEN){
            g_comb[(bb*2)*TLEN + t]   = c0;
            g_comb[(bb*2+1)*TLEN + t] = c1;
        }
    }
    for (int i = tid; i < 384; i += 256) s_w[i] = w[i];
    if (tid < 64)  s_b[tid] = bias[tid];
    __syncthreads();

    int t = tile0 + tid;
    if (t >= TLEN) return;
    float a0 = s_c[0][tid], a1 = s_c[0][tid+1], a2 = s_c[0][tid+2];
    float c0 = s_c[1][tid], c1 = s_c[1][tid+1], c2 = s_c[1][tid+2];
    #pragma unroll 4
    for (int co = 0; co < 64; co++){
        const float* wp = s_w + co*6;
        float acc = s_b[co] + wp[0]*a0 + wp[1]*a1 + wp[2]*a2
                            + wp[3]*c0 + wp[4]*c1 + wp[5]*c2;
        g_b0[((size_t)bb*64 + co)*TLEN + t] = f2bf(geluf(acc));
    }
}

// ---------------- TCN 64->64 dilated conv: persistent tcgen05, occ=2 --------
#define SM_A       1024
#define C64_BBYTES 24576
#define SM_B2      (SM_A + 49152)            /* 50176 */
#define XCH_STRIDE 16640                     /* 64 rows * 65 f32 * 4B */
#define C64_TOTAL  (SM_B2 + 2*C64_BBYTES)    /* 99328 */

template<int DIL>
__global__ void __launch_bounds__(256,2) conv64_mma(int src, int layer,
    const float* __restrict__ w, const float* __restrict__ bias)
{
    extern __shared__ char smem[];
    const unsigned short* in = src ? g_b1 : g_b0;
    unsigned short* out      = src ? g_b0 : g_b1;
    int tid = threadIdx.x;
    int lane = tid & 31, warp = tid >> 5;

#if HAS_TCGEN05
    uint smem_base = smem_u32(smem);
    uint mbar = smem_base + 8;

    if (warp == 0){
        asm volatile("tcgen05.alloc.cta_group::1.sync.aligned.shared::cta.b32 [%0], %1;"
                     :: "r"(smem_base), "r"(128u) : "memory");
        if (elect1()) asm volatile("mbarrier.init.shared.b64 [%0], 1;" :: "r"(mbar) : "memory");
    }
    // A tile: loaded ONCE per persistent CTA (49152 B)
    {
        const uint4* wsrc = (const uint4*)(g_wA + layer*24576);
        uint4* adst = (uint4*)(smem + SM_A);
        #pragma unroll
        for (int i = 0; i < 12; i++) adst[tid + 256*i] = wsrc[tid + 256*i];
    }
    __syncthreads();

    uint tmem_base;
    asm volatile("ld.shared.b32 %0, [%1];" : "=r"(tmem_base) : "r"(smem_base));
    ull adesc = desc_kmajor(smem_base + SM_A);
    float bv0;
    {
        int j = warp & 3;
        int co = (j < 2) ? (j*32 + lane) : ((j-2)*32 + lane);
        bv0 = bias[co];
    }

    int it = 0;
    for (int work = blockIdx.x; work < NWORK; work += PGRID, it++){
        int bb = work / NT;
        int t0 = (work - bb*NT) * 128;
        int par = it & 1;

        // B tiles from gmem: 2 chains x [192 rows x 64 t] MN-major, SW128.
        {
            const unsigned short* inb = in + (size_t)bb*64*TLEN;
            #pragma unroll
            for (int ii = 0; ii < 48; ii++){
                int idx = tid + 256*ii;              // < 12288
                int c = idx / 6144;
                int p = idx - c*6144;
                int r  = p >> 5;                     // 0..191
                int pp = p & 31;
                int kblk = r >> 6, ci = r & 63;
                int t = t0 + 64*c + 2*pp + (kblk - 1)*DIL;   // even
                uint v = 0u;
                if (t >= 0 && t < TLEN) v = *(const uint*)(inb + (size_t)ci*TLEN + t);
                uint boff = ((uint)r << 7) + ((uint)pp << 2);
                uint sw = boff ^ ((boff>>3)&0x70);
                *(uint*)(smem + SM_B2 + c*C64_BBYTES + sw) = v;
            }
        }
        __syncthreads();
        asm volatile("fence.proxy.async.shared::cta;" ::: "memory");

        if (warp == 0 && elect1()){
            #pragma unroll
            for (int c = 0; c < 2; c++){
                ull bdesc = desc_mnmajor(smem_base + SM_B2 + c*C64_BBYTES);
                #pragma unroll
                for (int s = 0; s < 12; s++){
                    mma_f16_ss(tmem_base + 64*c,
                               adesc + (ull)((s>>2)*1024 + (s&3)*2),
                               bdesc + (ull)(s*128),
                               MMA_IDESC, (s > 0) ? 1u : 0u);
                }
            }
            asm volatile("tcgen05.commit.cta_group::1.mbarrier::arrive::one.shared::cluster.b64 [%0];"
                         :: "r"(mbar) : "memory");
        }

        mbar_wait(mbar, par);
        asm volatile("tcgen05.fence::after_thread_sync;" ::: "memory");

        int wg = warp >> 2;      // chain 0..1
        int j  = warp & 3;
        uint dr[64];
        TC_LD_X32(dr,      tmem_base + 64*wg);
        TC_LD_X32(dr + 32, tmem_base + 64*wg + 32);
        asm volatile("tcgen05.wait::ld.sync.aligned;" ::: "memory");
        asm volatile("tcgen05.fence::before_thread_sync;" ::: "memory");

        float* xch = (float*)(smem + SM_B2 + wg*XCH_STRIDE);   // aliases B (dead)
        if (j >= 2){                              // kh=1 rows (tap-2 partials)
            int co = (j - 2)*32 + lane;
            #pragma unroll
            for (int i = 0; i < 64; i++) xch[co*65 + i] = __uint_as_float(dr[i]);
        }
        __syncthreads();
        if (j < 2){                               // kh=0 rows: combine+gelu+store
            int co = j*32 + lane;
            int tbase = t0 + wg*64;
            unsigned short* orow = out + ((size_t)bb*64 + co)*TLEN;
            #pragma unroll
            for (int q = 0; q < 16; q++){
                int t = tbase + 4*q;
                if (t < TLEN){
                    unsigned short pk[4];
                    #pragma unroll
                    for (int h = 0; h < 4; h++){
                        int i = 4*q + h;
                        pk[h] = f2bf(geluf(bv0 + __uint_as_float(dr[i]) + xch[co*65 + i]));
                    }
                    *(ull*)(orow + t) = *(ull*)pk;
                }
            }
        }
        __syncthreads();
    }
    if (warp == 0){
        asm volatile("tcgen05.relinquish_alloc_permit.cta_group::1.sync.aligned;");
        asm volatile("tcgen05.dealloc.cta_group::1.sync.aligned.b32 %0, %1;" :: "r"(tmem_base), "r"(128u));
    }
#else
    // -------- f32x2 fallback (non-'a' virtual arch), persistent loop -------
    constexpr int SSTR = 128 + 2*DIL;
    float* s_in = (float*)smem;                          // 64*SSTR floats
    float* s_w  = (float*)(smem + 64*SSTR*4);            // 12288 floats

    for (int i = tid; i < 12288; i += 256) s_w[i] = w[i];
    __syncthreads();

    for (int work = blockIdx.x; work < NWORK; work += PGRID){
        int bb = work / NT;
        int t0 = (work - bb*NT) * 128;
        const unsigned short* inb = in + (size_t)bb*64*TLEN;
        for (int idx = tid; idx < 64*SSTR; idx += 256){
            int ci = idx / SSTR, ii = idx % SSTR;
            int g = t0 - DIL + ii;
            float v = 0.0f;
            if (g >= 0 && g < TLEN) v = bf2f(inb[(size_t)ci*TLEN + g]);
            s_in[idx] = v;
        }
        __syncthreads();

        int wco = warp;
        ull acc[8][2];
        #pragma unroll
        for (int cc = 0; cc < 8; cc++){ acc[cc][0] = 0ull; acc[cc][1] = 0ull; }
        for (int ci = 0; ci < 64; ci++){
            const float* r = s_in + ci*SSTR + 2*lane;
            ull xin[3][2];
            #pragma unroll
            for (int jj = 0; jj < 3; jj++){
                xin[jj][0] = *(const ull*)(r + jj*DIL);
                xin[jj][1] = *(const ull*)(r + 64 + jj*DIL);
            }
            #pragma unroll
            for (int cc = 0; cc < 8; cc++){
                const float* wp = s_w + (wco*8 + cc)*192 + ci*3;
                ull w0 = dup2(wp[0]), w1 = dup2(wp[1]), w2 = dup2(wp[2]);
                #pragma unroll
                for (int p = 0; p < 2; p++){
                    fma2(acc[cc][p], w0, xin[0][p]);
                    fma2(acc[cc][p], w1, xin[1][p]);
                    fma2(acc[cc][p], w2, xin[2][p]);
                }
            }
        }

        unsigned short* outb = out + (size_t)bb*64*TLEN;
        #pragma unroll
        for (int cc = 0; cc < 8; cc++){
            int co = wco*8 + cc;
            float bv = bias[co];
            #pragma unroll
            for (int p = 0; p < 2; p++){
                float lo, hi; unpk(acc[cc][p], lo, hi);
                int t = t0 + 2*lane + 64*p;
                if (t < TLEN){
                    unsigned short pk[2];
                    pk[0] = f2bf(geluf(bv + lo));
                    pk[1] = f2bf(geluf(bv + hi));
                    *(uint*)(outb + (size_t)co*TLEN + t) = *(uint*)pk;
                }
            }
        }
        __syncthreads();
    }
#endif
}

// ---------------- TCN last layer 64->2 + skip + dry/wet mix -----------------
#define COUT_W 264
__global__ void __launch_bounds__(256) conv_out(
    const float* __restrict__ w, const float* __restrict__ bias,
    const float* __restrict__ audio, const float* __restrict__ params,
    float* __restrict__ outp)
{
    extern __shared__ float smemf[];          // 64*COUT_W floats
    __shared__ float s_w[384];
    __shared__ float s_b2[2];
    int bb = blockIdx.y;
    int tile0 = blockIdx.x * 256;
    int tid = threadIdx.x;
    const unsigned short* inb = g_b1 + (size_t)bb*64*TLEN;
    for (int idx = tid; idx < 64*66; idx += 256){
        int ci = idx / 66, j = idx % 66;
        int e = tile0 - 4 + 4*j;
        float v0=0,v1=0,v2=0,v3=0;
        if (e >= 0 && e + 3 < TLEN){
            ull u = *(const ull*)(inb + (size_t)ci*TLEN + e);
            unsigned short* s = (unsigned short*)&u;
            v0 = bf2f(s[0]); v1 = bf2f(s[1]); v2 = bf2f(s[2]); v3 = bf2f(s[3]);
        } else {
            #pragma unroll
            for (int h = 0; h < 4; h++){
                int g = e + h;
                float vv = (g >= 0 && g < TLEN) ? bf2f(inb[(size_t)ci*TLEN + g]) : 0.0f;
                if (h==0) v0=vv; else if (h==1) v1=vv; else if (h==2) v2=vv; else v3=vv;
            }
        }
        float* d = smemf + ci*COUT_W + 4*j;
        d[0]=v0; d[1]=v1; d[2]=v2; d[3]=v3;
    }
    for (int i = tid; i < 384; i += 256) s_w[i] = w[i];
    if (tid < 2)   s_b2[tid] = bias[tid];
    __syncthreads();
    int t = tile0 + tid;
    if (t >= TLEN) return;
    float acc0 = s_b2[0], acc1 = s_b2[1];
    #pragma unroll 4
    for (int ci = 0; ci < 64; ci++){
        const float* xr = smemf + ci*COUT_W + tid + 3;   // index of t-1
        float x0 = xr[0], x1 = xr[1], x2 = xr[2];
        const float* w0p = s_w + ci*3;
        const float* w1p = s_w + 192 + ci*3;
        acc0 += w0p[0]*x0 + w0p[1]*x1 + w0p[2]*x2;
        acc1 += w1p[0]*x0 + w1p[1]*x1 + w1p[2]*x2;
    }
    float amount = params[bb*7];
    int i0 = (bb*2)*TLEN + t;
    int i1 = i0 + TLEN;
    outp[i0] = (1.0f - amount)*audio[i0] + amount*(g_comb[i0] + acc0);
    outp[i1] = (1.0f - amount)*audio[i1] + amount*(g_comb[i1] + acc1);
}

// ---------------- launch -----------------------------------------------------
extern "C" void kernel_launch(void* const* d_in, const int* in_sizes, int n_in,
                              void* d_out, int out_size)
{
    const float* audio = (const float*)d_in[0];
    const float* params = (const float*)d_in[1];
    const float* rel   = (const float*)d_in[2];
    const float* kneep = (const float*)d_in[3];
    const float* irLL  = (const float*)d_in[4];
    const float* irLH  = (const float*)d_in[5];
    const float* irHL  = (const float*)d_in[6];
    const float* irHH  = (const float*)d_in[7];
    const float* w0 = (const float*)d_in[8];  const float* b0 = (const float*)d_in[9];
    const float* w1 = (const float*)d_in[10]; const float* b1 = (const float*)d_in[11];
    const float* w2 = (const float*)d_in[12]; const float* b2 = (const float*)d_in[13];
    const float* w3 = (const float*)d_in[14]; const float* b3 = (const float*)d_in[15];
    const float* w4 = (const float*)d_in[16]; const float* b4 = (const float*)d_in[17];
    float* out = (float*)d_out;

    cudaFuncSetAttribute(conv64_mma<2>, cudaFuncAttributeMaxDynamicSharedMemorySize, C64_TOTAL);
    cudaFuncSetAttribute(conv64_mma<4>, cudaFuncAttributeMaxDynamicSharedMemorySize, C64_TOTAL);
    cudaFuncSetAttribute(conv64_mma<8>, cudaFuncAttributeMaxDynamicSharedMemorySize, C64_TOTAL);
    cudaFuncSetAttribute(conv_out,      cudaFuncAttributeMaxDynamicSharedMemorySize, 64*COUT_W*4);

    prep_wtiles<<<dim3(96, 3), 256>>>(w1, w2, w3);

    dim3 gfir((TLEN + 2047)/2048, BATCH*CH);
    fir_pair<<<gfir, 256>>>(audio, 1, irLL, irLH, 2, -1, 1.81970085860998f);
    fir_pair<<<gfir, 256>>>(nullptr, 0, irHL, irHH, 1, 0, 1.0f);

    rms_kernel<<<dim3((TC + 255)/256, 24), 256>>>();
    env_kernel<<<24, 32>>>(rel);

    dim3 gT((TLEN + 255)/256, BATCH);
    gain_conv_in<<<gT, 256>>>(params, kneep, w0, b0);
    conv64_mma<2><<<PGRID, 256, C64_TOTAL>>>(0, 0, w1, b1);
    conv64_mma<4><<<PGRID, 256, C64_TOTAL>>>(1, 1, w2, b2);
    conv64_mma<8><<<PGRID, 256, C64_TOTAL>>>(0, 2, w3, b3);
    conv_out<<<gT, 256, 64*COUT_W*4>>>(w4, b4, audio, params, out);
}

// round 15
// speedup vs baseline: 2.9647x; 1.0137x over previous
#include <cuda_runtime.h>
#include <cuda_bf16.h>
#include <math.h>

#define BATCH 8
#define CH 2
#define TLEN 88200
#define BCT (BATCH*CH*TLEN)
#define TC 1378
#define KIR 512
#define NT 690                 /* ceil(TLEN/128) tiles per batch row */
#define NWORK (NT*BATCH)
#define PGRID 296              /* persistent grid: 2 CTAs x 148 SMs */

typedef unsigned long long ull;
typedef unsigned int uint;

#if defined(__CUDA_ARCH_FEAT_SM103_ALL) || defined(__CUDA_ARCH_FEAT_SM100_ALL)
#define HAS_TCGEN05 1
#else
#define HAS_TCGEN05 0
#endif

// ---------------- scratch (device globals: allocation-free) ----------------
__device__ float g_mh[BCT];
__device__ float g_bands[3*BCT];          // band 0=high, 1=mid, 2=low
__device__ float g_rms[24*TC];
__device__ float g_env[24*TC];
__device__ float g_comb[BCT];
__device__ __align__(16) unsigned short g_b0[BATCH*64*TLEN];   // bf16 activations
__device__ __align__(16) unsigned short g_b1[BATCH*64*TLEN];
__device__ __align__(16) unsigned short g_wA[3*24576];  // swizzled A-tile images

// tanh-form gelu approximation (hidden path only; res is w4(x0.01)-scaled).
__device__ __forceinline__ float geluf(float x){
    float x2 = x*x;
    float t = x*(0.7978845608f + 0.0356774081f*x2);
    float e; asm("ex2.approx.f32 %0, %1;" : "=f"(e) : "f"(2.885390082f*t));
    float r; asm("rcp.approx.f32 %0, %1;" : "=f"(r) : "f"(e + 1.0f));
    float th = 1.0f - 2.0f*r;                  // tanh(t)
    return 0.5f*x*(1.0f + th);
}
__device__ __forceinline__ void fma2(ull& d, ull a, ull b){
    asm("fma.rn.f32x2 %0, %1, %2, %0;" : "+l"(d) : "l"(a), "l"(b));
}
__device__ __forceinline__ ull dup2(float v){
    ull r; asm("mov.b64 %0, {%1, %2};" : "=l"(r) : "f"(v), "f"(v)); return r;
}
__device__ __forceinline__ void unpk(ull v, float& lo, float& hi){
    asm("mov.b64 {%0, %1}, %2;" : "=f"(lo), "=f"(hi) : "l"(v));
}
__device__ __forceinline__ float bf2f(unsigned short u){
    return __bfloat162float(*(__nv_bfloat16*)&u);
}
__device__ __forceinline__ unsigned short f2bf(float v){
    __nv_bfloat16 b = __float2bfloat16(v);
    return *(unsigned short*)&b;
}

// ---------------- tcgen05 helpers ------------------------------------------
__device__ __forceinline__ uint smem_u32(const void* p){
    uint a; asm("{ .reg .u64 t; cvta.to.shared.u64 t, %1; cvt.u32.u64 %0, t; }" : "=r"(a) : "l"(p)); return a;
}
__device__ __forceinline__ uint elect1(){
    uint p;
    asm volatile("{\n\t.reg .pred P;\n\telect.sync _|P, 0xFFFFFFFF;\n\tselp.b32 %0,1,0,P;\n\t}" : "=r"(p));
    return p;
}
__device__ __forceinline__ void mbar_wait(uint mbar, uint parity){
    asm volatile("{\n\t.reg .pred P;\n\tLW%=:\n\t"
      "mbarrier.try_wait.parity.acquire.cta.shared::cta.b64 P, [%0], %1, 0x989680;\n\t"
      "@P bra LD%=;\n\tbra LW%=;\n\tLD%=:\n\t}" :: "r"(mbar), "r"(parity) : "memory");
}
#if HAS_TCGEN05
__device__ __forceinline__ void mma_f16_ss(uint d, ull a, ull b, uint idesc, uint en){
    asm volatile("{\n\t.reg .pred p;\n\tsetp.ne.u32 p, %5, 0;\n\t"
        "tcgen05.mma.cta_group::1.kind::f16 [%0], %1, %2, %3, {%4,%4,%4,%4}, p;\n\t}"
        :: "r"(d), "l"(a), "l"(b), "r"(idesc), "r"(0u), "r"(en) : "memory");
}
#define TC_LD_X32(r, addr) \
    asm volatile("tcgen05.ld.sync.aligned.32x32b.x32.b32 " \
        "{%0,%1,%2,%3,%4,%5,%6,%7,%8,%9,%10,%11,%12,%13,%14,%15," \
        "%16,%17,%18,%19,%20,%21,%22,%23,%24,%25,%26,%27,%28,%29,%30,%31}, [%32];" \
        : "=r"((r)[0]),"=r"((r)[1]),"=r"((r)[2]),"=r"((r)[3]),"=r"((r)[4]),"=r"((r)[5]),"=r"((r)[6]),"=r"((r)[7]), \
          "=r"((r)[8]),"=r"((r)[9]),"=r"((r)[10]),"=r"((r)[11]),"=r"((r)[12]),"=r"((r)[13]),"=r"((r)[14]),"=r"((r)[15]), \
          "=r"((r)[16]),"=r"((r)[17]),"=r"((r)[18]),"=r"((r)[19]),"=r"((r)[20]),"=r"((r)[21]),"=r"((r)[22]),"=r"((r)[23]), \
          "=r"((r)[24]),"=r"((r)[25]),"=r"((r)[26]),"=r"((r)[27]),"=r"((r)[28]),"=r"((r)[29]),"=r"((r)[30]),"=r"((r)[31]) \
        : "r"(addr))
#endif

// SMEM descriptor bases (Blackwell: version=1, SW128 layout=2)
__device__ __forceinline__ ull desc_kmajor(uint addr){   // LBO=1, SBO=64 (K-major)
    return (2ull<<61) | (1ull<<46) | (64ull<<32) | (1ull<<16) | ((ull)(addr>>4) & 0x3FFF);
}
__device__ __forceinline__ ull desc_mnmajor(uint addr){  // LBO=64, SBO=8 (MN-major)
    return (2ull<<61) | (1ull<<46) | (8ull<<32) | (64ull<<16) | ((ull)(addr>>4) & 0x3FFF);
}
// idesc: F32 accum(1<<4), BF16 a(1<<7), BF16 b(1<<10), TransB(1<<16), N=64(8<<17), M=128(8<<24)
#define MMA_IDESC 0x08110490u

// ---------------- FIR: two 512-tap filters, f32x2 with register rotation ---
__global__ void __launch_bounds__(256) fir_pair(
    const float* __restrict__ xext, int use_ext,
    const float* __restrict__ wA, const float* __restrict__ wB,
    int outA, int outB, float gain)
{
    __shared__ __align__(16) float s_x[2564];
    __shared__ __align__(16) float s_xs[2564];
    __shared__ ull s_wA2[512];
    __shared__ ull s_wB2[512];
    int row  = blockIdx.y;
    int tile0 = blockIdx.x * 2048;
    int tid = threadIdx.x;
    const float* xr = (use_ext ? xext : (const float*)g_mh) + row*TLEN;
    // fused fill: s_x and its 1-shifted copy in one pass (2nd load L1-hits)
    for (int i = tid; i < 2564; i += 256){
        int g = tile0 - (KIR-1) + i;
        s_x[i]  = (g >= 0 && g < TLEN) ? xr[g] * gain : 0.0f;
        int g2 = g + 1;
        s_xs[i] = (g2 >= 0 && g2 < TLEN) ? xr[g2] * gain : 0.0f;
    }
    for (int i = tid; i < 512; i += 256){ s_wA2[i] = dup2(wA[i]); s_wB2[i] = dup2(wB[i]); }
    __syncthreads();

    int base = tid * 8;
    ull aA[4], aB[4];
    #pragma unroll
    for (int i = 0; i < 4; i++){ aA[i] = 0ull; aB[i] = 0ull; }
    ull E[4], O[4];
    #pragma unroll
    for (int i = 0; i < 4; i++){
        E[i] = *(const ull*)(s_x  + base + 2*i);
        O[i] = *(const ull*)(s_xs + base + 2*i);
    }
    #pragma unroll 4
    for (int k2 = 0; k2 < 256; k2++){
        int k = 2*k2;
        ull wa0 = s_wA2[k], wa1 = s_wA2[k+1];
        ull wb0 = s_wB2[k], wb1 = s_wB2[k+1];
        #pragma unroll
        for (int i = 0; i < 4; i++){
            fma2(aA[i], wa0, E[i]);
            fma2(aB[i], wb0, E[i]);
            fma2(aA[i], wa1, O[i]);
            fma2(aB[i], wb1, O[i]);
        }
        E[0]=E[1]; E[1]=E[2]; E[2]=E[3];
        O[0]=O[1]; O[1]=O[2]; O[2]=O[3];
        E[3] = *(const ull*)(s_x  + base + k + 8);
        O[3] = *(const ull*)(s_xs + base + k + 8);
    }

    float* oA = (outA < 0 ? g_mh : g_bands + (size_t)outA*BCT) + row*TLEN;
    float* oB = (outB < 0 ? g_mh : g_bands + (size_t)outB*BCT) + row*TLEN;
    #pragma unroll
    for (int i = 0; i < 4; i++){
        int o = tile0 + base + 2*i;
        if (o < TLEN){
            float lo, hi;
            unpk(aA[i], lo, hi); *(float2*)(oA + o) = make_float2(lo, hi);
            unpk(aB[i], lo, hi); *(float2*)(oB + o) = make_float2(lo, hi);
        }
    }
}

// ---------------- RMS downsample (DS=64), float4 loads ----------------------
__global__ void rms_kernel(){
    int bi = blockIdx.y;
    int tc = blockIdx.x*256 + threadIdx.x;
    if (tc >= TC) return;
    int b = bi / 3, band = bi % 3;
    const float4* p0 = (const float4*)(g_bands + (size_t)band*BCT + (b*2+0)*TLEN + tc*64);
    const float4* p1 = (const float4*)(g_bands + (size_t)band*BCT + (b*2+1)*TLEN + tc*64);
    float s = 0.0f;
    #pragma unroll
    for (int d = 0; d < 16; d++){
        float4 u = p0[d], v = p1[d];
        s += u.x*u.x + u.y*u.y + u.z*u.z + u.w*u.w;
        s += v.x*v.x + v.y*v.y + v.z*v.z + v.w*v.w;
    }
    g_rms[bi*TC + tc] = sqrtf(s * (1.0f/128.0f) + 1e-7f);
}

// ---------------- envelope: parallel segmented scan -------------------------
__global__ void env_kernel(const float* __restrict__ rel){
    int seq = blockIdx.x;
    int lane = threadIdx.x;
    float k = 1.0f - rel[seq >> 3];
    const float* x = g_rms + seq*TC;
    float* e = g_env + seq*TC;
    const int CL = 44;
    int start = lane*CL;
    int end = min(start + CL, TC);
    float M = 0.0f, p = 1.0f;
    for (int t = start; t < end; t++){ M = fmaxf(x[t], k*M); p *= k; }
    #pragma unroll
    for (int d = 1; d < 32; d <<= 1){
        float Mo = __shfl_up_sync(0xffffffffu, M, d);
        float po = __shfl_up_sync(0xffffffffu, p, d);
        if (lane >= d){ M = fmaxf(M, p*Mo); p *= po; }
    }
    float ein = __shfl_up_sync(0xffffffffu, M, 1);
    float y = (lane == 0) ? 0.0f : ein;
    for (int t = start; t < end; t++){ y = fmaxf(x[t], k*y); e[t] = y; }
}

// ---------------- weight-tile prep: swizzled A images -----------------------
__global__ void prep_wtiles(const float* __restrict__ w1, const float* __restrict__ w2, const float* __restrict__ w3){
    int layer = blockIdx.y;
    const float* w = (layer == 0) ? w1 : (layer == 1) ? w2 : w3;
    int idx = blockIdx.x*256 + threadIdx.x;
    if (idx >= 24576) return;
    int m = idx / 192, k = idx % 192;
    int kblk = k / 64, ci = k % 64;
    int kh = m >> 6, co = m & 63;
    float v = 0.0f;
    if ((kh == 0 && kblk < 2) || (kh == 1 && kblk == 2)) v = w[co*192 + ci*3 + kblk];
    uint byte = (uint)((m>>3) + kblk*16)*1024u + (uint)(m&7)*128u + (uint)(k&63)*2u;
    uint sw = byte ^ ((byte>>3)&0x70);
    g_wA[layer*24576 + (sw>>1)] = f2bf(v);
}

// ---------------- FUSED: gain + band combine + conv_in (2->64) --------------
// Gain path uses lg2/ex2 approx (error ~1e-6 rel in gain). Conv part:
// warp owns 8 co (weights in regs), lane owns 8 consecutive t, ull bf16 stores.
__global__ void __launch_bounds__(256) gain_conv_in(
    const float* __restrict__ params, const float* __restrict__ kneep,
    const float* __restrict__ w, const float* __restrict__ bias)
{
    __shared__ float s_c[2][258];
    __shared__ float s_w[384];
    __shared__ float s_b[64];
    int bb = blockIdx.y;
    int tile0 = blockIdx.x * 256;
    int tid = threadIdx.x;
    float kdb = kneep[0];

    for (int idx = tid; idx < 258; idx += 256){
        int t = tile0 - 1 + idx;
        float c0 = 0.0f, c1 = 0.0f;
        if (t >= 0 && t < TLEN){
            float pos = (float)t * (1377.0f/88199.0f);
            int i0 = (int)floorf(pos);
            i0 = min(max(i0, 0), TC-2);
            float frac = pos - (float)i0;
            #pragma unroll
            for (int band = 0; band < 3; band++){
                const float* er = g_env + (bb*3 + band)*TC;
                float e = er[i0]*(1.0f - frac) + er[i0+1]*frac;
                float l2; asm("lg2.approx.f32 %0, %1;" : "=f"(l2) : "f"(e + 1e-7f));
                float edb = 6.02059991328f * l2;       // 20*log10
                float ta = params[bb*7 + (3 - band)];
                float tb = params[bb*7 + (6 - band)];
                float slA = (band == 0) ? 1.0f : (1.0f - 1.0f/66.7f);
                const float slB = 1.0f - 1.0f/4.17f;
                float hk = 0.5f * kdb;
                float d1 = edb - ta, k1;
                if (fabsf(d1) <= hk)      k1 = slA * (d1 + hk)*(d1 + hk) / (2.0f*kdb);
                else if (d1 > hk)         k1 = slA * d1;
                else                      k1 = 0.0f;
                float d2 = tb - edb, k2;
                if (fabsf(d2) <= hk)      k2 = slB * (d2 + hk)*(d2 + hk) / (2.0f*kdb);
                else if (d2 > hk)         k2 = slB * d2;
                else                      k2 = 0.0f;
                float gdb = -k1 + k2 + ((band == 1) ? 5.7f : 10.3f);
                gdb = fminf(fmaxf(gdb, -80.0f), 40.0f);
                float tg; asm("ex2.approx.f32 %0, %1;" : "=f"(tg) : "f"(gdb * 0.16609640474436813f));
                const float* bptr = g_bands + (size_t)band*BCT + (bb*2)*TLEN + t;
                c0 += bptr[0]    * tg;
                c1 += bptr[TLEN] * tg;
            }
        }
        s_c[0][idx] = c0;
        s_c[1][idx] = c1;
        if (idx >= 1 && idx <= 256 && t < TLEN){
            g_comb[(bb*2)*TLEN + t]   = c0;
            g_comb[(bb*2+1)*TLEN + t] = c1;
        }
    }
    for (int i = tid; i < 384; i += 256) s_w[i] = w[i];
    if (tid < 64)  s_b[tid] = bias[tid];
    __syncthreads();

    int wp = tid >> 5, lane = tid & 31;
    float wr[8][6], bvr[8];
    #pragma unroll
    for (int cc = 0; cc < 8; cc++){
        int co = wp*8 + cc;
        #pragma unroll
        for (int j = 0; j < 6; j++) wr[cc][j] = s_w[co*6 + j];
        bvr[cc] = s_b[co];
    }
    int tl0 = lane * 8;
    int tbase = tile0 + tl0;
    if (tbase < TLEN){                 // tail is 8-divisible -> all-or-nothing per lane
        float xa[10], xc[10];
        #pragma unroll
        for (int q = 0; q < 10; q++){ xa[q] = s_c[0][tl0 + q]; xc[q] = s_c[1][tl0 + q]; }
        #pragma unroll
        for (int cc = 0; cc < 8; cc++){
            int co = wp*8 + cc;
            unsigned short pk[8];
            #pragma unroll
            for (int tt = 0; tt < 8; tt++){
                float acc = bvr[cc] + wr[cc][0]*xa[tt] + wr[cc][1]*xa[tt+1] + wr[cc][2]*xa[tt+2]
                                    + wr[cc][3]*xc[tt] + wr[cc][4]*xc[tt+1] + wr[cc][5]*xc[tt+2];
                pk[tt] = f2bf(geluf(acc));
            }
            ull* dst = (ull*)(g_b0 + ((size_t)bb*64 + co)*TLEN + tbase);
            dst[0] = *(ull*)pk;
            dst[1] = *(ull*)(pk + 4);
        }
    }
}

// ---------------- TCN 64->64 dilated conv: persistent tcgen05, occ=2 --------
#define SM_A       1024
#define C64_BBYTES 24576
#define SM_B2      (SM_A + 49152)            /* 50176 */
#define XCH_STRIDE 16640                     /* 64 rows * 65 f32 * 4B */
#define C64_TOTAL  (SM_B2 + 2*C64_BBYTES)    /* 99328 */

template<int DIL>
__global__ void __launch_bounds__(256,2) conv64_mma(int src, int layer,
    const float* __restrict__ w, const float* __restrict__ bias)
{
    extern __shared__ char smem[];
    const unsigned short* in = src ? g_b1 : g_b0;
    unsigned short* out      = src ? g_b0 : g_b1;
    int tid = threadIdx.x;
    int lane = tid & 31, warp = tid >> 5;

#if HAS_TCGEN05
    uint smem_base = smem_u32(smem);
    uint mbar = smem_base + 8;

    if (warp == 0){
        asm volatile("tcgen05.alloc.cta_group::1.sync.aligned.shared::cta.b32 [%0], %1;"
                     :: "r"(smem_base), "r"(128u) : "memory");
        if (elect1()) asm volatile("mbarrier.init.shared.b64 [%0], 1;" :: "r"(mbar) : "memory");
    }
    // A tile: loaded ONCE per persistent CTA (49152 B)
    {
        const uint4* wsrc = (const uint4*)(g_wA + layer*24576);
        uint4* adst = (uint4*)(smem + SM_A);
        #pragma unroll
        for (int i = 0; i < 12; i++) adst[tid + 256*i] = wsrc[tid + 256*i];
    }
    __syncthreads();

    uint tmem_base;
    asm volatile("ld.shared.b32 %0, [%1];" : "=r"(tmem_base) : "r"(smem_base));
    ull adesc = desc_kmajor(smem_base + SM_A);
    float bv0;
    {
        int j = warp & 3;
        int co = (j < 2) ? (j*32 + lane) : ((j-2)*32 + lane);
        bv0 = bias[co];
    }

    int it = 0;
    for (int work = blockIdx.x; work < NWORK; work += PGRID, it++){
        int bb = work / NT;
        int t0 = (work - bb*NT) * 128;
        int par = it & 1;

        // B tiles from gmem: 2 chains x [192 rows x 64 t] MN-major, SW128.
        {
            const unsigned short* inb = in + (size_t)bb*64*TLEN;
            #pragma unroll
            for (int ii = 0; ii < 48; ii++){
                int idx = tid + 256*ii;              // < 12288
                int c = idx / 6144;
                int p = idx - c*6144;
                int r  = p >> 5;                     // 0..191
                int pp = p & 31;
                int kblk = r >> 6, ci = r & 63;
                int t = t0 + 64*c + 2*pp + (kblk - 1)*DIL;   // even
                uint v = 0u;
                if (t >= 0 && t < TLEN) v = *(const uint*)(inb + (size_t)ci*TLEN + t);
                uint boff = ((uint)r << 7) + ((uint)pp << 2);
                uint sw = boff ^ ((boff>>3)&0x70);
                *(uint*)(smem + SM_B2 + c*C64_BBYTES + sw) = v;
            }
        }
        __syncthreads();
        asm volatile("fence.proxy.async.shared::cta;" ::: "memory");

        if (warp == 0 && elect1()){
            #pragma unroll
            for (int c = 0; c < 2; c++){
                ull bdesc = desc_mnmajor(smem_base + SM_B2 + c*C64_BBYTES);
                #pragma unroll
                for (int s = 0; s < 12; s++){
                    mma_f16_ss(tmem_base + 64*c,
                               adesc + (ull)((s>>2)*1024 + (s&3)*2),
                               bdesc + (ull)(s*128),
                               MMA_IDESC, (s > 0) ? 1u : 0u);
                }
            }
            asm volatile("tcgen05.commit.cta_group::1.mbarrier::arrive::one.shared::cluster.b64 [%0];"
                         :: "r"(mbar) : "memory");
        }

        mbar_wait(mbar, par);
        asm volatile("tcgen05.fence::after_thread_sync;" ::: "memory");

        int wg = warp >> 2;      // chain 0..1
        int j  = warp & 3;
        uint dr[64];
        TC_LD_X32(dr,      tmem_base + 64*wg);
        TC_LD_X32(dr + 32, tmem_base + 64*wg + 32);
        asm volatile("tcgen05.wait::ld.sync.aligned;" ::: "memory");
        asm volatile("tcgen05.fence::before_thread_sync;" ::: "memory");

        float* xch = (float*)(smem + SM_B2 + wg*XCH_STRIDE);   // aliases B (dead)
        if (j >= 2){                              // kh=1 rows (tap-2 partials)
            int co = (j - 2)*32 + lane;
            #pragma unroll
            for (int i = 0; i < 64; i++) xch[co*65 + i] = __uint_as_float(dr[i]);
        }
        __syncthreads();
        if (j < 2){                               // kh=0 rows: combine+gelu+store
            int co = j*32 + lane;
            int tbase = t0 + wg*64;
            unsigned short* orow = out + ((size_t)bb*64 + co)*TLEN;
            #pragma unroll
            for (int q = 0; q < 16; q++){
                int t = tbase + 4*q;
                if (t < TLEN){
                    unsigned short pk[4];
                    #pragma unroll
                    for (int h = 0; h < 4; h++){
                        int i = 4*q + h;
                        pk[h] = f2bf(geluf(bv0 + __uint_as_float(dr[i]) + xch[co*65 + i]));
                    }
                    *(ull*)(orow + t) = *(ull*)pk;
                }
            }
        }
        __syncthreads();
    }
    if (warp == 0){
        asm volatile("tcgen05.relinquish_alloc_permit.cta_group::1.sync.aligned;");
        asm volatile("tcgen05.dealloc.cta_group::1.sync.aligned.b32 %0, %1;" :: "r"(tmem_base), "r"(128u));
    }
#else
    // -------- f32x2 fallback (non-'a' virtual arch), persistent loop -------
    constexpr int SSTR = 128 + 2*DIL;
    float* s_in = (float*)smem;                          // 64*SSTR floats
    float* s_w  = (float*)(smem + 64*SSTR*4);            // 12288 floats

    for (int i = tid; i < 12288; i += 256) s_w[i] = w[i];
    __syncthreads();

    for (int work = blockIdx.x; work < NWORK; work += PGRID){
        int bb = work / NT;
        int t0 = (work - bb*NT) * 128;
        const unsigned short* inb = in + (size_t)bb*64*TLEN;
        for (int idx = tid; idx < 64*SSTR; idx += 256){
            int ci = idx / SSTR, ii = idx % SSTR;
            int g = t0 - DIL + ii;
            float v = 0.0f;
            if (g >= 0 && g < TLEN) v = bf2f(inb[(size_t)ci*TLEN + g]);
            s_in[idx] = v;
        }
        __syncthreads();

        int wco = warp;
        ull acc[8][2];
        #pragma unroll
        for (int cc = 0; cc < 8; cc++){ acc[cc][0] = 0ull; acc[cc][1] = 0ull; }
        for (int ci = 0; ci < 64; ci++){
            const float* r = s_in + ci*SSTR + 2*lane;
            ull xin[3][2];
            #pragma unroll
            for (int jj = 0; jj < 3; jj++){
                xin[jj][0] = *(const ull*)(r + jj*DIL);
                xin[jj][1] = *(const ull*)(r + 64 + jj*DIL);
            }
            #pragma unroll
            for (int cc = 0; cc < 8; cc++){
                const float* wpt = s_w + (wco*8 + cc)*192 + ci*3;
                ull w0 = dup2(wpt[0]), w1 = dup2(wpt[1]), w2 = dup2(wpt[2]);
                #pragma unroll
                for (int p = 0; p < 2; p++){
                    fma2(acc[cc][p], w0, xin[0][p]);
                    fma2(acc[cc][p], w1, xin[1][p]);
                    fma2(acc[cc][p], w2, xin[2][p]);
                }
            }
        }

        unsigned short* outb = out + (size_t)bb*64*TLEN;
        #pragma unroll
        for (int cc = 0; cc < 8; cc++){
            int co = wco*8 + cc;
            float bv = bias[co];
            #pragma unroll
            for (int p = 0; p < 2; p++){
                float lo, hi; unpk(acc[cc][p], lo, hi);
                int t = t0 + 2*lane + 64*p;
                if (t < TLEN){
                    unsigned short pk[2];
                    pk[0] = f2bf(geluf(bv + lo));
                    pk[1] = f2bf(geluf(bv + hi));
                    *(uint*)(outb + (size_t)co*TLEN + t) = *(uint*)pk;
                }
            }
        }
        __syncthreads();
    }
#endif
}

// ---------------- TCN last layer 64->2 + skip + dry/wet mix -----------------
// Warp owns 8 ci (weights in regs), lane owns 8 consecutive t; partial sums
// reduced via padded smem [256][17]. smem tile kept in bf16.
#define COUT_W 264
#define COUT_SMEM (64*COUT_W*2 + 256*17*4)   /* 33792 + 17408 = 51200 */
__global__ void __launch_bounds__(256) conv_out(
    const float* __restrict__ w, const float* __restrict__ bias,
    const float* __restrict__ audio, const float* __restrict__ params,
    float* __restrict__ outp)
{
    extern __shared__ char smemc[];
    unsigned short* s_xb = (unsigned short*)smemc;            // 64 x COUT_W bf16
    float* s_part = (float*)(smemc + 64*COUT_W*2);            // [256][17]
    __shared__ float s_w[384];
    __shared__ float s_b2[2];
    int bb = blockIdx.y;
    int tile0 = blockIdx.x * 256;
    int tid = threadIdx.x;
    const unsigned short* inb = g_b1 + (size_t)bb*64*TLEN;
    // fill: rows cover t = tile0-4 .. tile0+259 (pure bf16 copy)
    for (int idx = tid; idx < 64*66; idx += 256){
        int ci = idx / 66, j = idx % 66;
        int e = tile0 - 4 + 4*j;
        ull v = 0ull;
        if (e >= 0 && e + 3 < TLEN) v = *(const ull*)(inb + (size_t)ci*TLEN + e);
        else {
            unsigned short tmp[4];
            #pragma unroll
            for (int h = 0; h < 4; h++){
                int g = e + h;
                tmp[h] = (g >= 0 && g < TLEN) ? inb[(size_t)ci*TLEN + g] : 0;
            }
            v = *(ull*)tmp;
        }
        *(ull*)(s_xb + ci*COUT_W + 4*j) = v;
    }
    for (int i = tid; i < 384; i += 256) s_w[i] = w[i];
    if (tid < 2) s_b2[tid] = bias[tid];
    __syncthreads();

    int wp = tid >> 5, lane = tid & 31;
    float wr0[8][3], wr1[8][3];
    #pragma unroll
    for (int cc = 0; cc < 8; cc++){
        int ci = wp*8 + cc;
        #pragma unroll
        for (int j = 0; j < 3; j++){
            wr0[cc][j] = s_w[ci*3 + j];
            wr1[cc][j] = s_w[192 + ci*3 + j];
        }
    }
    int tl0 = lane * 8;
    float acc0[8], acc1[8];
    #pragma unroll
    for (int tt = 0; tt < 8; tt++){ acc0[tt] = 0.0f; acc1[tt] = 0.0f; }
    #pragma unroll
    for (int cc = 0; cc < 8; cc++){
        int ci = wp*8 + cc;
        // x[t-1+d] for t=tile0+tl0+tt -> s_xb element at pos tl0+tt+3+d-? : pos = tl0+tt+3 (+d)
        // load 6 uints covering positions [tl0+2 .. tl0+13]
        const uint* up = (const uint*)(s_xb + ci*COUT_W + tl0 + 2);
        float ev[12];
        #pragma unroll
        for (int q = 0; q < 6; q++){
            uint u = up[q];
            ev[2*q]   = __uint_as_float(u << 16);
            ev[2*q+1] = __uint_as_float(u & 0xffff0000u);
        }
        // position tl0+2+i -> ev[i]; x[t-1] = pos tl0+tt+3 = ev[tt+1]
        #pragma unroll
        for (int tt = 0; tt < 8; tt++){
            float x0 = ev[tt+1], x1 = ev[tt+2], x2 = ev[tt+3];
            acc0[tt] += wr0[cc][0]*x0 + wr0[cc][1]*x1 + wr0[cc][2]*x2;
            acc1[tt] += wr1[cc][0]*x0 + wr1[cc][1]*x1 + wr1[cc][2]*x2;
        }
    }
    #pragma unroll
    for (int tt = 0; tt < 8; tt++){
        s_part[(tl0 + tt)*17 + 2*wp]     = acc0[tt];
        s_part[(tl0 + tt)*17 + 2*wp + 1] = acc1[tt];
    }
    __syncthreads();

    int t = tile0 + tid;
    if (t >= TLEN) return;
    float a0 = s_b2[0], a1 = s_b2[1];
    const float* pp = s_part + tid*17;
    #pragma unroll
    for (int k = 0; k < 8; k++){ a0 += pp[2*k]; a1 += pp[2*k+1]; }
    float amount = params[bb*7];
    int i0 = (bb*2)*TLEN + t;
    int i1 = i0 + TLEN;
    outp[i0] = (1.0f - amount)*audio[i0] + amount*(g_comb[i0] + a0);
    outp[i1] = (1.0f - amount)*audio[i1] + amount*(g_comb[i1] + a1);
}

// ---------------- launch -----------------------------------------------------
extern "C" void kernel_launch(void* const* d_in, const int* in_sizes, int n_in,
                              void* d_out, int out_size)
{
    const float* audio = (const float*)d_in[0];
    const float* params = (const float*)d_in[1];
    const float* rel   = (const float*)d_in[2];
    const float* kneep = (const float*)d_in[3];
    const float* irLL  = (const float*)d_in[4];
    const float* irLH  = (const float*)d_in[5];
    const float* irHL  = (const float*)d_in[6];
    const float* irHH  = (const float*)d_in[7];
    const float* w0 = (const float*)d_in[8];  const float* b0 = (const float*)d_in[9];
    const float* w1 = (const float*)d_in[10]; const float* b1 = (const float*)d_in[11];
    const float* w2 = (const float*)d_in[12]; const float* b2 = (const float*)d_in[13];
    const float* w3 = (const float*)d_in[14]; const float* b3 = (const float*)d_in[15];
    const float* w4 = (const float*)d_in[16]; const float* b4 = (const float*)d_in[17];
    float* out = (float*)d_out;

    cudaFuncSetAttribute(conv64_mma<2>, cudaFuncAttributeMaxDynamicSharedMemorySize, C64_TOTAL);
    cudaFuncSetAttribute(conv64_mma<4>, cudaFuncAttributeMaxDynamicSharedMemorySize, C64_TOTAL);
    cudaFuncSetAttribute(conv64_mma<8>, cudaFuncAttributeMaxDynamicSharedMemorySize, C64_TOTAL);
    cudaFuncSetAttribute(conv_out,      cudaFuncAttributeMaxDynamicSharedMemorySize, COUT_SMEM);

    prep_wtiles<<<dim3(96, 3), 256>>>(w1, w2, w3);

    dim3 gfir((TLEN + 2047)/2048, BATCH*CH);
    fir_pair<<<gfir, 256>>>(audio, 1, irLL, irLH, 2, -1, 1.81970085860998f);
    fir_pair<<<gfir, 256>>>(nullptr, 0, irHL, irHH, 1, 0, 1.0f);

    rms_kernel<<<dim3((TC + 255)/256, 24), 256>>>();
    env_kernel<<<24, 32>>>(rel);

    dim3 gT((TLEN + 255)/256, BATCH);
    gain_conv_in<<<gT, 256>>>(params, kneep, w0, b0);
    conv64_mma<2><<<PGRID, 256, C64_TOTAL>>>(0, 0, w1, b1);
    conv64_mma<4><<<PGRID, 256, C64_TOTAL>>>(1, 1, w2, b2);
    conv64_mma<8><<<PGRID, 256, C64_TOTAL>>>(0, 2, w3, b3);
    conv_out<<<gT, 256, COUT_SMEM>>>(w4, b4, audio, params, out);
}

// round 17
// speedup vs baseline: 3.5539x; 1.1987x over previous
#include <cuda_runtime.h>
#include <cuda_bf16.h>
#include <math.h>

#define BATCH 8
#define CH 2
#define TLEN 88200
#define BCT (BATCH*CH*TLEN)
#define TC 1378
#define KIR 512
#define NT 690                 /* ceil(TLEN/128) tiles per batch row */
#define NWORK (NT*BATCH)
#define PGRID 296              /* persistent grid: 2 CTAs x 148 SMs */

typedef unsigned long long ull;
typedef unsigned int uint;

#if defined(__CUDA_ARCH_FEAT_SM103_ALL) || defined(__CUDA_ARCH_FEAT_SM100_ALL)
#define HAS_TCGEN05 1
#else
#define HAS_TCGEN05 0
#endif

// ---------------- scratch (device globals: allocation-free) ----------------
__device__ float g_mh[BCT];
__device__ float g_bands[3*BCT];          // band 0=high, 1=mid, 2=low
__device__ float g_rms[24*TC];
__device__ float g_env[24*TC];
__device__ float g_comb[BCT];
__device__ __align__(16) unsigned short g_b0[BATCH*64*TLEN];   // bf16 activations
__device__ __align__(16) unsigned short g_b1[BATCH*64*TLEN];
__device__ __align__(16) unsigned short g_wA[3*24576];  // swizzled A-tile images

// tanh-form gelu approximation (hidden path only; res is w4(x0.01)-scaled).
__device__ __forceinline__ float geluf(float x){
    float x2 = x*x;
    float t = x*(0.7978845608f + 0.0356774081f*x2);
    float e; asm("ex2.approx.f32 %0, %1;" : "=f"(e) : "f"(2.885390082f*t));
    float r; asm("rcp.approx.f32 %0, %1;" : "=f"(r) : "f"(e + 1.0f));
    float th = 1.0f - 2.0f*r;                  // tanh(t)
    return 0.5f*x*(1.0f + th);
}
__device__ __forceinline__ void fma2(ull& d, ull a, ull b){
    asm("fma.rn.f32x2 %0, %1, %2, %0;" : "+l"(d) : "l"(a), "l"(b));
}
__device__ __forceinline__ ull dup2(float v){
    ull r; asm("mov.b64 %0, {%1, %2};" : "=l"(r) : "f"(v), "f"(v)); return r;
}
__device__ __forceinline__ void unpk(ull v, float& lo, float& hi){
    asm("mov.b64 {%0, %1}, %2;" : "=f"(lo), "=f"(hi) : "l"(v));
}
__device__ __forceinline__ float bf2f(unsigned short u){
    return __bfloat162float(*(__nv_bfloat16*)&u);
}
__device__ __forceinline__ unsigned short f2bf(float v){
    __nv_bfloat16 b = __float2bfloat16(v);
    return *(unsigned short*)&b;
}
// pack two fp32 into bf16x2 (round-to-nearest)
__device__ __forceinline__ uint pack_bf16x2(float lo, float hi){
    uint r; asm("cvt.rn.bf16x2.f32 %0, %1, %2;" : "=r"(r) : "f"(hi), "f"(lo));
    return r;
}

// ---------------- tcgen05 helpers ------------------------------------------
__device__ __forceinline__ uint smem_u32(const void* p){
    uint a; asm("{ .reg .u64 t; cvta.to.shared.u64 t, %1; cvt.u32.u64 %0, t; }" : "=r"(a) : "l"(p)); return a;
}
__device__ __forceinline__ uint elect1(){
    uint p;
    asm volatile("{\n\t.reg .pred P;\n\telect.sync _|P, 0xFFFFFFFF;\n\tselp.b32 %0,1,0,P;\n\t}" : "=r"(p));
    return p;
}
__device__ __forceinline__ void mbar_wait(uint mbar, uint parity){
    asm volatile("{\n\t.reg .pred P;\n\tLW%=:\n\t"
      "mbarrier.try_wait.parity.acquire.cta.shared::cta.b64 P, [%0], %1, 0x989680;\n\t"
      "@P bra LD%=;\n\tbra LW%=;\n\tLD%=:\n\t}" :: "r"(mbar), "r"(parity) : "memory");
}
#if HAS_TCGEN05
__device__ __forceinline__ void mma_f16_ss(uint d, ull a, ull b, uint idesc, uint en){
    asm volatile("{\n\t.reg .pred p;\n\tsetp.ne.u32 p, %5, 0;\n\t"
        "tcgen05.mma.cta_group::1.kind::f16 [%0], %1, %2, %3, {%4,%4,%4,%4}, p;\n\t}"
        :: "r"(d), "l"(a), "l"(b), "r"(idesc), "r"(0u), "r"(en) : "memory");
}
#define TC_LD_X32(r, addr) \
    asm volatile("tcgen05.ld.sync.aligned.32x32b.x32.b32 " \
        "{%0,%1,%2,%3,%4,%5,%6,%7,%8,%9,%10,%11,%12,%13,%14,%15," \
        "%16,%17,%18,%19,%20,%21,%22,%23,%24,%25,%26,%27,%28,%29,%30,%31}, [%32];" \
        : "=r"((r)[0]),"=r"((r)[1]),"=r"((r)[2]),"=r"((r)[3]),"=r"((r)[4]),"=r"((r)[5]),"=r"((r)[6]),"=r"((r)[7]), \
          "=r"((r)[8]),"=r"((r)[9]),"=r"((r)[10]),"=r"((r)[11]),"=r"((r)[12]),"=r"((r)[13]),"=r"((r)[14]),"=r"((r)[15]), \
          "=r"((r)[16]),"=r"((r)[17]),"=r"((r)[18]),"=r"((r)[19]),"=r"((r)[20]),"=r"((r)[21]),"=r"((r)[22]),"=r"((r)[23]), \
          "=r"((r)[24]),"=r"((r)[25]),"=r"((r)[26]),"=r"((r)[27]),"=r"((r)[28]),"=r"((r)[29]),"=r"((r)[30]),"=r"((r)[31]) \
        : "r"(addr))
#endif

// SMEM descriptor bases (Blackwell: version=1, SW128 layout=2)
__device__ __forceinline__ ull desc_kmajor(uint addr){   // LBO=1, SBO=64 (K-major)
    return (2ull<<61) | (1ull<<46) | (64ull<<32) | (1ull<<16) | ((ull)(addr>>4) & 0x3FFF);
}
__device__ __forceinline__ ull desc_mnmajor(uint addr){  // LBO=64, SBO=8 (MN-major)
    return (2ull<<61) | (1ull<<46) | (8ull<<32) | (64ull<<16) | ((ull)(addr>>4) & 0x3FFF);
}
// idesc: F32 accum(1<<4), BF16 a(1<<7), BF16 b(1<<10), TransB(1<<16), N=64(8<<17), M=128(8<<24)
#define MMA_IDESC 0x08110490u

// ---------------- FIR: two 512-tap filters, f32x2 with register rotation ---
__global__ void __launch_bounds__(256) fir_pair(
    const float* __restrict__ xext, int use_ext,
    const float* __restrict__ wA, const float* __restrict__ wB,
    int outA, int outB, float gain)
{
    __shared__ __align__(16) float s_x[2564];
    __shared__ __align__(16) float s_xs[2564];
    __shared__ ull s_wA2[512];
    __shared__ ull s_wB2[512];
    int row  = blockIdx.y;
    int tile0 = blockIdx.x * 2048;
    int tid = threadIdx.x;
    const float* xr = (use_ext ? xext : (const float*)g_mh) + row*TLEN;
    for (int i = tid; i < 2564; i += 256){
        int g = tile0 - (KIR-1) + i;
        s_x[i]  = (g >= 0 && g < TLEN) ? xr[g] * gain : 0.0f;
        int g2 = g + 1;
        s_xs[i] = (g2 >= 0 && g2 < TLEN) ? xr[g2] * gain : 0.0f;
    }
    for (int i = tid; i < 512; i += 256){ s_wA2[i] = dup2(wA[i]); s_wB2[i] = dup2(wB[i]); }
    __syncthreads();

    int base = tid * 8;
    ull aA[4], aB[4];
    #pragma unroll
    for (int i = 0; i < 4; i++){ aA[i] = 0ull; aB[i] = 0ull; }
    ull E[4], O[4];
    #pragma unroll
    for (int i = 0; i < 4; i++){
        E[i] = *(const ull*)(s_x  + base + 2*i);
        O[i] = *(const ull*)(s_xs + base + 2*i);
    }
    #pragma unroll 4
    for (int k2 = 0; k2 < 256; k2++){
        int k = 2*k2;
        ull wa0 = s_wA2[k], wa1 = s_wA2[k+1];
        ull wb0 = s_wB2[k], wb1 = s_wB2[k+1];
        #pragma unroll
        for (int i = 0; i < 4; i++){
            fma2(aA[i], wa0, E[i]);
            fma2(aB[i], wb0, E[i]);
            fma2(aA[i], wa1, O[i]);
            fma2(aB[i], wb1, O[i]);
        }
        E[0]=E[1]; E[1]=E[2]; E[2]=E[3];
        O[0]=O[1]; O[1]=O[2]; O[2]=O[3];
        E[3] = *(const ull*)(s_x  + base + k + 8);
        O[3] = *(const ull*)(s_xs + base + k + 8);
    }

    float* oA = (outA < 0 ? g_mh : g_bands + (size_t)outA*BCT) + row*TLEN;
    float* oB = (outB < 0 ? g_mh : g_bands + (size_t)outB*BCT) + row*TLEN;
    #pragma unroll
    for (int i = 0; i < 4; i++){
        int o = tile0 + base + 2*i;
        if (o < TLEN){
            float lo, hi;
            unpk(aA[i], lo, hi); *(float2*)(oA + o) = make_float2(lo, hi);
            unpk(aB[i], lo, hi); *(float2*)(oB + o) = make_float2(lo, hi);
        }
    }
}

// ---------------- RMS downsample (DS=64), float4 loads ----------------------
__global__ void rms_kernel(){
    int bi = blockIdx.y;
    int tc = blockIdx.x*256 + threadIdx.x;
    if (tc >= TC) return;
    int b = bi / 3, band = bi % 3;
    const float4* p0 = (const float4*)(g_bands + (size_t)band*BCT + (b*2+0)*TLEN + tc*64);
    const float4* p1 = (const float4*)(g_bands + (size_t)band*BCT + (b*2+1)*TLEN + tc*64);
    float s = 0.0f;
    #pragma unroll
    for (int d = 0; d < 16; d++){
        float4 u = p0[d], v = p1[d];
        s += u.x*u.x + u.y*u.y + u.z*u.z + u.w*u.w;
        s += v.x*v.x + v.y*v.y + v.z*v.z + v.w*v.w;
    }
    g_rms[bi*TC + tc] = sqrtf(s * (1.0f/128.0f) + 1e-7f);
}

// ---------------- envelope: parallel segmented scan -------------------------
__global__ void env_kernel(const float* __restrict__ rel){
    int seq = blockIdx.x;
    int lane = threadIdx.x;
    float k = 1.0f - rel[seq >> 3];
    const float* x = g_rms + seq*TC;
    float* e = g_env + seq*TC;
    const int CL = 44;
    int start = lane*CL;
    int end = min(start + CL, TC);
    float M = 0.0f, p = 1.0f;
    for (int t = start; t < end; t++){ M = fmaxf(x[t], k*M); p *= k; }
    #pragma unroll
    for (int d = 1; d < 32; d <<= 1){
        float Mo = __shfl_up_sync(0xffffffffu, M, d);
        float po = __shfl_up_sync(0xffffffffu, p, d);
        if (lane >= d){ M = fmaxf(M, p*Mo); p *= po; }
    }
    float ein = __shfl_up_sync(0xffffffffu, M, 1);
    float y = (lane == 0) ? 0.0f : ein;
    for (int t = start; t < end; t++){ y = fmaxf(x[t], k*y); e[t] = y; }
}

// ---------------- weight-tile prep: swizzled A images -----------------------
__global__ void prep_wtiles(const float* __restrict__ w1, const float* __restrict__ w2, const float* __restrict__ w3){
    int layer = blockIdx.y;
    const float* w = (layer == 0) ? w1 : (layer == 1) ? w2 : w3;
    int idx = blockIdx.x*256 + threadIdx.x;
    if (idx >= 24576) return;
    int m = idx / 192, k = idx % 192;
    int kblk = k / 64, ci = k % 64;
    int kh = m >> 6, co = m & 63;
    float v = 0.0f;
    if ((kh == 0 && kblk < 2) || (kh == 1 && kblk == 2)) v = w[co*192 + ci*3 + kblk];
    uint byte = (uint)((m>>3) + kblk*16)*1024u + (uint)(m&7)*128u + (uint)(k&63)*2u;
    uint sw = byte ^ ((byte>>3)&0x70);
    g_wA[layer*24576 + (sw>>1)] = f2bf(v);
}

// ---------------- FUSED: gain + band combine + conv_in (2->64) --------------
__global__ void __launch_bounds__(256) gain_conv_in(
    const float* __restrict__ params, const float* __restrict__ kneep,
    const float* __restrict__ w, const float* __restrict__ bias)
{
    __shared__ float s_c[2][258];
    __shared__ float s_w[384];
    __shared__ float s_b[64];
    int bb = blockIdx.y;
    int tile0 = blockIdx.x * 256;
    int tid = threadIdx.x;
    float kdb = kneep[0];

    for (int idx = tid; idx < 258; idx += 256){
        int t = tile0 - 1 + idx;
        float c0 = 0.0f, c1 = 0.0f;
        if (t >= 0 && t < TLEN){
            float pos = (float)t * (1377.0f/88199.0f);
            int i0 = (int)floorf(pos);
            i0 = min(max(i0, 0), TC-2);
            float frac = pos - (float)i0;
            #pragma unroll
            for (int band = 0; band < 3; band++){
                const float* er = g_env + (bb*3 + band)*TC;
                float e = er[i0]*(1.0f - frac) + er[i0+1]*frac;
                float l2; asm("lg2.approx.f32 %0, %1;" : "=f"(l2) : "f"(e + 1e-7f));
                float edb = 6.02059991328f * l2;       // 20*log10
                float ta = params[bb*7 + (3 - band)];
                float tb = params[bb*7 + (6 - band)];
                float slA = (band == 0) ? 1.0f : (1.0f - 1.0f/66.7f);
                const float slB = 1.0f - 1.0f/4.17f;
                float hk = 0.5f * kdb;
                float d1 = edb - ta, k1;
                if (fabsf(d1) <= hk)      k1 = slA * (d1 + hk)*(d1 + hk) / (2.0f*kdb);
                else if (d1 > hk)         k1 = slA * d1;
                else                      k1 = 0.0f;
                float d2 = tb - edb, k2;
                if (fabsf(d2) <= hk)      k2 = slB * (d2 + hk)*(d2 + hk) / (2.0f*kdb);
                else if (d2 > hk)         k2 = slB * d2;
                else                      k2 = 0.0f;
                float gdb = -k1 + k2 + ((band == 1) ? 5.7f : 10.3f);
                gdb = fminf(fmaxf(gdb, -80.0f), 40.0f);
                float tg; asm("ex2.approx.f32 %0, %1;" : "=f"(tg) : "f"(gdb * 0.16609640474436813f));
                const float* bptr = g_bands + (size_t)band*BCT + (bb*2)*TLEN + t;
                c0 += bptr[0]    * tg;
                c1 += bptr[TLEN] * tg;
            }
        }
        s_c[0][idx] = c0;
        s_c[1][idx] = c1;
        if (idx >= 1 && idx <= 256 && t < TLEN){
            g_comb[(bb*2)*TLEN + t]   = c0;
            g_comb[(bb*2+1)*TLEN + t] = c1;
        }
    }
    for (int i = tid; i < 384; i += 256) s_w[i] = w[i];
    if (tid < 64)  s_b[tid] = bias[tid];
    __syncthreads();

    int wp = tid >> 5, lane = tid & 31;
    float wr[8][6], bvr[8];
    #pragma unroll
    for (int cc = 0; cc < 8; cc++){
        int co = wp*8 + cc;
        #pragma unroll
        for (int j = 0; j < 6; j++) wr[cc][j] = s_w[co*6 + j];
        bvr[cc] = s_b[co];
    }
    int tl0 = lane * 8;
    int tbase = tile0 + tl0;
    if (tbase < TLEN){
        float xa[10], xc[10];
        #pragma unroll
        for (int q = 0; q < 10; q++){ xa[q] = s_c[0][tl0 + q]; xc[q] = s_c[1][tl0 + q]; }
        #pragma unroll
        for (int cc = 0; cc < 8; cc++){
            int co = wp*8 + cc;
            unsigned short pk[8];
            #pragma unroll
            for (int tt = 0; tt < 8; tt++){
                float acc = bvr[cc] + wr[cc][0]*xa[tt] + wr[cc][1]*xa[tt+1] + wr[cc][2]*xa[tt+2]
                                    + wr[cc][3]*xc[tt] + wr[cc][4]*xc[tt+1] + wr[cc][5]*xc[tt+2];
                pk[tt] = f2bf(geluf(acc));
            }
            ull* dst = (ull*)(g_b0 + ((size_t)bb*64 + co)*TLEN + tbase);
            dst[0] = *(ull*)pk;
            dst[1] = *(ull*)(pk + 4);
        }
    }
}

// ---------------- TCN 64->64 dilated conv: persistent tcgen05, occ=2 --------
// Epilogue spread over all 4 SMSPs via two-way bf16 exchange:
//   xchA (in chain's dead B region): kh1 partials, 64 rows x 66 bf16 (33-word
//   stride, coprime 32 -> conflict-free);  xchB: kh0 partials t in [32,64),
//   64 rows x 34 bf16 (17-word stride).
#define SM_A       1024
#define C64_BBYTES 24576
#define SM_B2      (SM_A + 49152)            /* 50176 */
#define C64_TOTAL  (SM_B2 + 2*C64_BBYTES)    /* 99328 */
#define XCHA_OFF   0
#define XCHB_OFF   8448                      /* 64*66*2 */

template<int DIL>
__global__ void __launch_bounds__(256,2) conv64_mma(int src, int layer,
    const float* __restrict__ w, const float* __restrict__ bias)
{
    extern __shared__ char smem[];
    const unsigned short* in = src ? g_b1 : g_b0;
    unsigned short* out      = src ? g_b0 : g_b1;
    int tid = threadIdx.x;
    int lane = tid & 31, warp = tid >> 5;

#if HAS_TCGEN05
    uint smem_base = smem_u32(smem);
    uint mbar = smem_base + 8;

    if (warp == 0){
        asm volatile("tcgen05.alloc.cta_group::1.sync.aligned.shared::cta.b32 [%0], %1;"
                     :: "r"(smem_base), "r"(128u) : "memory");
        if (elect1()) asm volatile("mbarrier.init.shared.b64 [%0], 1;" :: "r"(mbar) : "memory");
    }
    // A tile: loaded ONCE per persistent CTA (49152 B)
    {
        const uint4* wsrc = (const uint4*)(g_wA + layer*24576);
        uint4* adst = (uint4*)(smem + SM_A);
        #pragma unroll
        for (int i = 0; i < 12; i++) adst[tid + 256*i] = wsrc[tid + 256*i];
    }
    __syncthreads();

    uint tmem_base;
    asm volatile("ld.shared.b32 %0, [%1];" : "=r"(tmem_base) : "r"(smem_base));
    ull adesc = desc_kmajor(smem_base + SM_A);
    int wg = warp >> 2;      // chain 0..1
    int j  = warp & 3;
    int co = ((j & 1) ? 32 : 0) + lane;        // pairs (0,2) co=lane, (1,3) co=32+lane
    float bv0 = bias[co];
    uint* xchA = (uint*)(smem + SM_B2 + wg*C64_BBYTES + XCHA_OFF);
    uint* xchB = (uint*)(smem + SM_B2 + wg*C64_BBYTES + XCHB_OFF);

    int it = 0;
    for (int work = blockIdx.x; work < NWORK; work += PGRID, it++){
        int bb = work / NT;
        int t0 = (work - bb*NT) * 128;
        int par = it & 1;
        const unsigned short* inb = in + (size_t)bb*64*TLEN;

        // B tiles: 2 chains x [192 rows x 64 t] MN-major, SW128. c is
        // compile-time (no division); interior tiles skip bounds checks.
        if (t0 >= DIL && t0 + 128 + DIL <= TLEN){
            #pragma unroll
            for (int c = 0; c < 2; c++){
                #pragma unroll
                for (int ii = 0; ii < 24; ii++){
                    int p = tid + 256*ii;            // < 6144
                    int r  = p >> 5;
                    int pp = p & 31;
                    int kblk = r >> 6, ci = r & 63;
                    int t = t0 + 64*c + 2*pp + (kblk - 1)*DIL;
                    uint v = *(const uint*)(inb + (size_t)ci*TLEN + t);
                    uint boff = ((uint)r << 7) + ((uint)pp << 2);
                    uint sw = boff ^ ((boff>>3)&0x70);
                    *(uint*)(smem + SM_B2 + c*C64_BBYTES + sw) = v;
                }
            }
        } else {
            #pragma unroll
            for (int c = 0; c < 2; c++){
                #pragma unroll
                for (int ii = 0; ii < 24; ii++){
                    int p = tid + 256*ii;
                    int r  = p >> 5;
                    int pp = p & 31;
                    int kblk = r >> 6, ci = r & 63;
                    int t = t0 + 64*c + 2*pp + (kblk - 1)*DIL;
                    uint v = 0u;
                    if (t >= 0 && t < TLEN) v = *(const uint*)(inb + (size_t)ci*TLEN + t);
                    uint boff = ((uint)r << 7) + ((uint)pp << 2);
                    uint sw = boff ^ ((boff>>3)&0x70);
                    *(uint*)(smem + SM_B2 + c*C64_BBYTES + sw) = v;
                }
            }
        }
        __syncthreads();
        asm volatile("fence.proxy.async.shared::cta;" ::: "memory");

        if (warp == 0 && elect1()){
            #pragma unroll
            for (int c = 0; c < 2; c++){
                ull bdesc = desc_mnmajor(smem_base + SM_B2 + c*C64_BBYTES);
                #pragma unroll
                for (int s = 0; s < 12; s++){
                    mma_f16_ss(tmem_base + 64*c,
                               adesc + (ull)((s>>2)*1024 + (s&3)*2),
                               bdesc + (ull)(s*128),
                               MMA_IDESC, (s > 0) ? 1u : 0u);
                }
            }
            asm volatile("tcgen05.commit.cta_group::1.mbarrier::arrive::one.shared::cluster.b64 [%0];"
                         :: "r"(mbar) : "memory");
        }

        mbar_wait(mbar, par);
        asm volatile("tcgen05.fence::after_thread_sync;" ::: "memory");

        uint dr[64];
        TC_LD_X32(dr,      tmem_base + 64*wg);
        TC_LD_X32(dr + 32, tmem_base + 64*wg + 32);
        asm volatile("tcgen05.wait::ld.sync.aligned;" ::: "memory");
        asm volatile("tcgen05.fence::before_thread_sync;" ::: "memory");

        if (j >= 2){          // kh1 partials: all 64 t -> xchA (bf16x2)
            #pragma unroll
            for (int i = 0; i < 32; i++)
                xchA[co*33 + i] = pack_bf16x2(__uint_as_float(dr[2*i]),
                                              __uint_as_float(dr[2*i+1]));
        } else {              // kh0 partials: t in [32,64) -> xchB
            #pragma unroll
            for (int i = 0; i < 16; i++)
                xchB[co*17 + i] = pack_bf16x2(__uint_as_float(dr[32+2*i]),
                                              __uint_as_float(dr[32+2*i+1]));
        }
        __syncthreads();

        int tbase = t0 + wg*64;
        unsigned short* orow = out + ((size_t)bb*64 + co)*TLEN;
        if (j < 2){           // gelu+store t in [0,32): kh0 regs + xchA bf16
            #pragma unroll
            for (int q = 0; q < 4; q++){   // chunks of 8 t
                int t = tbase + 8*q;
                if (t < TLEN){
                    float xv[8];
                    #pragma unroll
                    for (int i = 0; i < 4; i++){
                        uint u = xchA[co*33 + 4*q + i];
                        xv[2*i]   = __uint_as_float(u << 16);
                        xv[2*i+1] = __uint_as_float(u & 0xffff0000u);
                    }
                    unsigned short pk[8];
                    #pragma unroll
                    for (int h = 0; h < 8; h++)
                        pk[h] = f2bf(geluf(bv0 + __uint_as_float(dr[8*q+h]) + xv[h]));
                    ull* dst = (ull*)(orow + t);
                    if (t + 3 < TLEN) dst[0] = *(ull*)pk;
                    if (t + 7 < TLEN) dst[1] = *(ull*)(pk + 4);
                }
            }
        } else {              // gelu+store t in [32,64): kh1 regs + xchB bf16
            #pragma unroll
            for (int q = 0; q < 4; q++){
                int t = tbase + 32 + 8*q;
                if (t < TLEN){
                    float xv[8];
                    #pragma unroll
                    for (int i = 0; i < 4; i++){
                        uint u = xchB[co*17 + 4*q + i];
                        xv[2*i]   = __uint_as_float(u << 16);
                        xv[2*i+1] = __uint_as_float(u & 0xffff0000u);
                    }
                    unsigned short pk[8];
                    #pragma unroll
                    for (int h = 0; h < 8; h++)
                        pk[h] = f2bf(geluf(bv0 + __uint_as_float(dr[32+8*q+h]) + xv[h]));
                    ull* dst = (ull*)(orow + t);
                    if (t + 3 < TLEN) dst[0] = *(ull*)pk;
                    if (t + 7 < TLEN) dst[1] = *(ull*)(pk + 4);
                }
            }
        }
        __syncthreads();
    }
    if (warp == 0){
        asm volatile("tcgen05.relinquish_alloc_permit.cta_group::1.sync.aligned;");
        asm volatile("tcgen05.dealloc.cta_group::1.sync.aligned.b32 %0, %1;" :: "r"(tmem_base), "r"(128u));
    }
#else
    // -------- f32x2 fallback (non-'a' virtual arch), persistent loop -------
    constexpr int SSTR = 128 + 2*DIL;
    float* s_in = (float*)smem;                          // 64*SSTR floats
    float* s_w  = (float*)(smem + 64*SSTR*4);            // 12288 floats

    for (int i = tid; i < 12288; i += 256) s_w[i] = w[i];
    __syncthreads();

    for (int work = blockIdx.x; work < NWORK; work += PGRID){
        int bb = work / NT;
        int t0 = (work - bb*NT) * 128;
        const unsigned short* inb = in + (size_t)bb*64*TLEN;
        for (int idx = tid; idx < 64*SSTR; idx += 256){
            int ci = idx / SSTR, ii = idx % SSTR;
            int g = t0 - DIL + ii;
            float v = 0.0f;
            if (g >= 0 && g < TLEN) v = bf2f(inb[(size_t)ci*TLEN + g]);
            s_in[idx] = v;
        }
        __syncthreads();

        int wco = warp;
        ull acc[8][2];
        #pragma unroll
        for (int cc = 0; cc < 8; cc++){ acc[cc][0] = 0ull; acc[cc][1] = 0ull; }
        for (int ci = 0; ci < 64; ci++){
            const float* r = s_in + ci*SSTR + 2*lane;
            ull xin[3][2];
            #pragma unroll
            for (int jj = 0; jj < 3; jj++){
                xin[jj][0] = *(const ull*)(r + jj*DIL);
                xin[jj][1] = *(const ull*)(r + 64 + jj*DIL);
            }
            #pragma unroll
            for (int cc = 0; cc < 8; cc++){
                const float* wpt = s_w + (wco*8 + cc)*192 + ci*3;
                ull w0 = dup2(wpt[0]), w1 = dup2(wpt[1]), w2 = dup2(wpt[2]);
                #pragma unroll
                for (int p = 0; p < 2; p++){
                    fma2(acc[cc][p], w0, xin[0][p]);
                    fma2(acc[cc][p], w1, xin[1][p]);
                    fma2(acc[cc][p], w2, xin[2][p]);
                }
            }
        }

        unsigned short* outb = out + (size_t)bb*64*TLEN;
        #pragma unroll
        for (int cc = 0; cc < 8; cc++){
            int co = wco*8 + cc;
            float bv = bias[co];
            #pragma unroll
            for (int p = 0; p < 2; p++){
                float lo, hi; unpk(acc[cc][p], lo, hi);
                int t = t0 + 2*lane + 64*p;
                if (t < TLEN){
                    unsigned short pk[2];
                    pk[0] = f2bf(geluf(bv + lo));
                    pk[1] = f2bf(geluf(bv + hi));
                    *(uint*)(outb + (size_t)co*TLEN + t) = *(uint*)pk;
                }
            }
        }
        __syncthreads();
    }
#endif
}

// ---------------- TCN last layer 64->2 + skip + dry/wet mix -----------------
#define COUT_W 264
#define COUT_SMEM (64*COUT_W*2 + 256*17*4)   /* 33792 + 17408 = 51200 */
__global__ void __launch_bounds__(256) conv_out(
    const float* __restrict__ w, const float* __restrict__ bias,
    const float* __restrict__ audio, const float* __restrict__ params,
    float* __restrict__ outp)
{
    extern __shared__ char smemc[];
    unsigned short* s_xb = (unsigned short*)smemc;            // 64 x COUT_W bf16
    float* s_part = (float*)(smemc + 64*COUT_W*2);            // [256][17]
    __shared__ float s_w[384];
    __shared__ float s_b2[2];
    int bb = blockIdx.y;
    int tile0 = blockIdx.x * 256;
    int tid = threadIdx.x;
    const unsigned short* inb = g_b1 + (size_t)bb*64*TLEN;
    for (int idx = tid; idx < 64*66; idx += 256){
        int ci = idx / 66, j = idx % 66;
        int e = tile0 - 4 + 4*j;
        ull v = 0ull;
        if (e >= 0 && e + 3 < TLEN) v = *(const ull*)(inb + (size_t)ci*TLEN + e);
        else {
            unsigned short tmp[4];
            #pragma unroll
            for (int h = 0; h < 4; h++){
                int g = e + h;
                tmp[h] = (g >= 0 && g < TLEN) ? inb[(size_t)ci*TLEN + g] : 0;
            }
            v = *(ull*)tmp;
        }
        *(ull*)(s_xb + ci*COUT_W + 4*j) = v;
    }
    for (int i = tid; i < 384; i += 256) s_w[i] = w[i];
    if (tid < 2) s_b2[tid] = bias[tid];
    __syncthreads();

    int wp = tid >> 5, lane = tid & 31;
    float wr0[8][3], wr1[8][3];
    #pragma unroll
    for (int cc = 0; cc < 8; cc++){
        int ci = wp*8 + cc;
        #pragma unroll
        for (int j = 0; j < 3; j++){
            wr0[cc][j] = s_w[ci*3 + j];
            wr1[cc][j] = s_w[192 + ci*3 + j];
        }
    }
    int tl0 = lane * 8;
    float acc0[8], acc1[8];
    #pragma unroll
    for (int tt = 0; tt < 8; tt++){ acc0[tt] = 0.0f; acc1[tt] = 0.0f; }
    #pragma unroll
    for (int cc = 0; cc < 8; cc++){
        int ci = wp*8 + cc;
        const uint* up = (const uint*)(s_xb + ci*COUT_W + tl0 + 2);
        float ev[12];
        #pragma unroll
        for (int q = 0; q < 6; q++){
            uint u = up[q];
            ev[2*q]   = __uint_as_float(u << 16);
            ev[2*q+1] = __uint_as_float(u & 0xffff0000u);
        }
        #pragma unroll
        for (int tt = 0; tt < 8; tt++){
            float x0 = ev[tt+1], x1 = ev[tt+2], x2 = ev[tt+3];
            acc0[tt] += wr0[cc][0]*x0 + wr0[cc][1]*x1 + wr0[cc][2]*x2;
            acc1[tt] += wr1[cc][0]*x0 + wr1[cc][1]*x1 + wr1[cc][2]*x2;
        }
    }
    #pragma unroll
    for (int tt = 0; tt < 8; tt++){
        s_part[(tl0 + tt)*17 + 2*wp]     = acc0[tt];
        s_part[(tl0 + tt)*17 + 2*wp + 1] = acc1[tt];
    }
    __syncthreads();

    int t = tile0 + tid;
    if (t >= TLEN) return;
    float a0 = s_b2[0], a1 = s_b2[1];
    const float* pp = s_part + tid*17;
    #pragma unroll
    for (int k = 0; k < 8; k++){ a0 += pp[2*k]; a1 += pp[2*k+1]; }
    float amount = params[bb*7];
    int i0 = (bb*2)*TLEN + t;
    int i1 = i0 + TLEN;
    outp[i0] = (1.0f - amount)*audio[i0] + amount*(g_comb[i0] + a0);
    outp[i1] = (1.0f - amount)*audio[i1] + amount*(g_comb[i1] + a1);
}

// ---------------- launch -----------------------------------------------------
extern "C" void kernel_launch(void* const* d_in, const int* in_sizes, int n_in,
                              void* d_out, int out_size)
{
    const float* audio = (const float*)d_in[0];
    const float* params = (const float*)d_in[1];
    const float* rel   = (const float*)d_in[2];
    const float* kneep = (const float*)d_in[3];
    const float* irLL  = (const float*)d_in[4];
    const float* irLH  = (const float*)d_in[5];
    const float* irHL  = (const float*)d_in[6];
    const float* irHH  = (const float*)d_in[7];
    const float* w0 = (const float*)d_in[8];  const float* b0 = (const float*)d_in[9];
    const float* w1 = (const float*)d_in[10]; const float* b1 = (const float*)d_in[11];
    const float* w2 = (const float*)d_in[12]; const float* b2 = (const float*)d_in[13];
    const float* w3 = (const float*)d_in[14]; const float* b3 = (const float*)d_in[15];
    const float* w4 = (const float*)d_in[16]; const float* b4 = (const float*)d_in[17];
    float* out = (float*)d_out;

    cudaFuncSetAttribute(conv64_mma<2>, cudaFuncAttributeMaxDynamicSharedMemorySize, C64_TOTAL);
    cudaFuncSetAttribute(conv64_mma<4>, cudaFuncAttributeMaxDynamicSharedMemorySize, C64_TOTAL);
    cudaFuncSetAttribute(conv64_mma<8>, cudaFuncAttributeMaxDynamicSharedMemorySize, C64_TOTAL);
    cudaFuncSetAttribute(conv_out,      cudaFuncAttributeMaxDynamicSharedMemorySize, COUT_SMEM);

    prep_wtiles<<<dim3(96, 3), 256>>>(w1, w2, w3);

    dim3 gfir((TLEN + 2047)/2048, BATCH*CH);
    fir_pair<<<gfir, 256>>>(audio, 1, irLL, irLH, 2, -1, 1.81970085860998f);
    fir_pair<<<gfir, 256>>>(nullptr, 0, irHL, irHH, 1, 0, 1.0f);

    rms_kernel<<<dim3((TC + 255)/256, 24), 256>>>();
    env_kernel<<<24, 32>>>(rel);

    dim3 gT((TLEN + 255)/256, BATCH);
    gain_conv_in<<<gT, 256>>>(params, kneep, w0, b0);
    conv64_mma<2><<<PGRID, 256, C64_TOTAL>>>(0, 0, w1, b1);
    conv64_mma<4><<<PGRID, 256, C64_TOTAL>>>(1, 1, w2, b2);
    conv64_mma<8><<<PGRID, 256, C64_TOTAL>>>(0, 2, w3, b3);
    conv_out<<<gT, 256, COUT_SMEM>>>(w4, b4, audio, params, out);
}